// round 6
// baseline (speedup 1.0000x reference)
#include <cuda_runtime.h>
#include <cuda_bf16.h>
#include <cstdint>
#include <cstdio>

// ---------------- problem constants ----------------
#define NN      50000
#define EE      320000
#define ETOT    (EE + NN)
#define DIN     128
#define DD      256
#define NTOK    (NN * 3)
#define NHEAD   4
#define DH      64
#define NEGS    0.2f

// ---------------- fp32 scratch ----------------
__device__ float g_h  [(size_t)NN * DD];
__device__ float g_s  [NN];
__device__ float g_t  [NN];
__device__ float g_den[NN];
__device__ float g_agg[(size_t)NN * DD];
__device__ float g_x1 [(size_t)NN * DD];
__device__ float g_x2 [(size_t)NN * DD];
__device__ float g_seq[(size_t)NTOK * DD];
__device__ float g_qkv[(size_t)NTOK * 3 * DD];
__device__ float g_tmp[(size_t)NTOK * DD];

// ---------------- bf16 split operand buffers ----------------
__device__ __nv_bfloat16 g_xh [(size_t)NN * DIN];
__device__ __nv_bfloat16 g_xl [(size_t)NN * DIN];
__device__ __nv_bfloat16 g_x1h[(size_t)NN * DD];
__device__ __nv_bfloat16 g_x1l[(size_t)NN * DD];
__device__ __nv_bfloat16 g_seqh[(size_t)NTOK * DD];
__device__ __nv_bfloat16 g_seql[(size_t)NTOK * DD];
__device__ __nv_bfloat16 g_atth[(size_t)NTOK * DD];
__device__ __nv_bfloat16 g_attl[(size_t)NTOK * DD];
__device__ __nv_bfloat16 g_ffh[(size_t)NTOK * 4 * DD];
__device__ __nv_bfloat16 g_ffl[(size_t)NTOK * 4 * DD];
// weight pool (hi/lo)
#define WOFF_W1   0
#define WOFF_W2   32768
#define WOFF_QKV  98304
#define WOFF_WO   491520
#define WOFF_F1   622592
#define WOFF_F2   1146880
#define WTOT      1671168
__device__ __nv_bfloat16 g_wbh[WTOT];
__device__ __nv_bfloat16 g_wbl[WTOT];

// ================= warp-mma helpers =================
__device__ __forceinline__ uint32_t smem_u32(const void* p) {
    uint32_t a;
    asm("{ .reg .u64 t; cvta.to.shared.u64 t, %1; cvt.u32.u64 %0, t; }" : "=r"(a) : "l"(p));
    return a;
}

#define LDM4(r, addr) \
    asm volatile("ldmatrix.sync.aligned.m8n8.x4.shared.b16 {%0,%1,%2,%3}, [%4];" \
        : "=r"((r)[0]), "=r"((r)[1]), "=r"((r)[2]), "=r"((r)[3]) : "r"(addr))
#define LDM2(r, addr) \
    asm volatile("ldmatrix.sync.aligned.m8n8.x2.shared.b16 {%0,%1}, [%2];" \
        : "=r"((r)[0]), "=r"((r)[1]) : "r"(addr))
#define MMA16816(c, a, b) \
    asm volatile("mma.sync.aligned.m16n8k16.row.col.f32.bf16.bf16.f32 " \
        "{%0,%1,%2,%3}, {%4,%5,%6,%7}, {%8,%9}, {%0,%1,%2,%3};" \
        : "+f"((c)[0]), "+f"((c)[1]), "+f"((c)[2]), "+f"((c)[3]) \
        : "r"((a)[0]), "r"((a)[1]), "r"((a)[2]), "r"((a)[3]), "r"((b)[0]), "r"((b)[1]))
#define CP_ASYNC(dst, src, sz) \
    asm volatile("cp.async.cg.shared.global [%0], [%1], 16, %2;" :: "r"(dst), "l"(src), "r"(sz))
#define CP_COMMIT() asm volatile("cp.async.commit_group;" ::: "memory")

// ================= split-bf16 GEMM via mma.sync ==========================
// C[M,N] = (Ah+Al)[M,K] * (Bh+Bl)[N,K]^T (3-term).
// BM=128, BN=128, BK=32; 256 threads = 8 warps (2m x 4n), warp tile 64x32.
// 3-stage cp.async pipeline; term-outer MMA ordering (no acc RAW chains).
#define RSB     80                     // row stride bytes in smem
#define MAT_SZ  10240                  // 128 rows * 80B
#define STG_B   20480
#define STG_SZ  40960
#define GM_SMEM (3 * STG_SZ)           // 122880

template<bool BIAS, bool RELU, bool OUTF, bool OUTS>
__global__ __launch_bounds__(256) void gemm_mma_kernel(
    const __nv_bfloat16* __restrict__ Ah, const __nv_bfloat16* __restrict__ Al,
    const __nv_bfloat16* __restrict__ Bh, const __nv_bfloat16* __restrict__ Bl,
    const float* __restrict__ bias,
    float* __restrict__ Cf, __nv_bfloat16* __restrict__ Ch, __nv_bfloat16* __restrict__ Cl,
    int M, int Nn, int K)
{
    extern __shared__ char smraw[];
    const uint32_t sb = smem_u32(smraw);
    const int tid = threadIdx.x, wid = tid >> 5, lane = tid & 31;
    const int wm = wid & 1, wn = wid >> 1;
    const int m0 = blockIdx.y * 128, n0 = blockIdx.x * 128;

    float acc[4][4][4];
    #pragma unroll
    for (int mt = 0; mt < 4; mt++)
        #pragma unroll
        for (int nt = 0; nt < 4; nt++)
            #pragma unroll
            for (int c = 0; c < 4; c++) acc[mt][nt][c] = 0.f;

    const int a_row = (lane & 7) + ((lane >> 3) & 1) * 8;
    const int a_k   = (lane >> 4) * 8;
    const int b_row = lane & 7;
    const int b_k   = ((lane >> 3) & 1) * 8;

    const int T = K >> 5;

    auto load_stage = [&](int buf, int k0) {
        uint32_t base = sb + buf * STG_SZ;
        #pragma unroll
        for (int it = 0; it < 8; it++) {
            int i    = tid + it * 256;
            int part = i >> 10;            // 0=A, 1=B
            int idx  = i & 1023;
            int hl   = idx >> 9;           // 0=hi, 1=lo
            int rem  = idx & 511;
            int row  = rem >> 2;
            int ch   = rem & 3;
            uint32_t dst = base + part * STG_B + hl * MAT_SZ + row * RSB + ch * 16;
            const __nv_bfloat16* src;
            int sz = 16;
            if (part == 0) {
                src = hl ? Al : Ah;
                int gm = m0 + row;
                if (gm >= M) sz = 0;
                src += (size_t)gm * K + k0 + ch * 8;
            } else {
                src = (hl ? Bl : Bh) + (size_t)(n0 + row) * K + k0 + ch * 8;
            }
            CP_ASYNC(dst, src, sz);
        }
        CP_COMMIT();
    };

    auto compute = [&](int buf) {
        uint32_t base  = sb + buf * STG_SZ;
        uint32_t aB    = base + (wm * 64) * RSB;
        uint32_t bB    = base + STG_B + (wn * 32) * RSB;
        #pragma unroll
        for (int ks = 0; ks < 32; ks += 16) {
            uint32_t ah[4][4], al[4][4], bh[4][2], bl[4][2];
            #pragma unroll
            for (int mt = 0; mt < 4; mt++) {
                uint32_t ad = aB + (mt * 16 + a_row) * RSB + (ks + a_k) * 2;
                LDM4(ah[mt], ad);
                LDM4(al[mt], ad + MAT_SZ);
            }
            #pragma unroll
            for (int nt = 0; nt < 4; nt++) {
                uint32_t bd = bB + (nt * 8 + b_row) * RSB + (ks + b_k) * 2;
                LDM2(bh[nt], bd);
                LDM2(bl[nt], bd + MAT_SZ);
            }
            // term-outer ordering: 16 independent MMAs between acc reuse
            #pragma unroll
            for (int mt = 0; mt < 4; mt++)
                #pragma unroll
                for (int nt = 0; nt < 4; nt++)
                    MMA16816(acc[mt][nt], ah[mt], bh[nt]);
            #pragma unroll
            for (int mt = 0; mt < 4; mt++)
                #pragma unroll
                for (int nt = 0; nt < 4; nt++)
                    MMA16816(acc[mt][nt], ah[mt], bl[nt]);
            #pragma unroll
            for (int mt = 0; mt < 4; mt++)
                #pragma unroll
                for (int nt = 0; nt < 4; nt++)
                    MMA16816(acc[mt][nt], al[mt], bh[nt]);
        }
    };

    load_stage(0, 0);
    if (T > 1) load_stage(1, 32);
    for (int t = 0; t < T; t++) {
        if (t == T - 1) asm volatile("cp.async.wait_group 0;" ::: "memory");
        else            asm volatile("cp.async.wait_group 1;" ::: "memory");
        __syncthreads();
        compute(t % 3);
        __syncthreads();
        if (t + 2 < T) load_stage((t + 2) % 3, (t + 2) << 5);
    }

    // ---------------- epilogue (regs -> global, fused) ----------------
    const int r0    = lane >> 2;
    const int cpair = (lane & 3) * 2;
    #pragma unroll
    for (int mt = 0; mt < 4; mt++) {
        int gm1 = m0 + wm * 64 + mt * 16 + r0;
        int gm2 = gm1 + 8;
        #pragma unroll
        for (int nt = 0; nt < 4; nt++) {
            int gn = n0 + wn * 32 + nt * 8 + cpair;
            float b0 = 0.f, b1 = 0.f;
            if (BIAS) { float2 bb = *(const float2*)&bias[gn]; b0 = bb.x; b1 = bb.y; }
            float v0 = acc[mt][nt][0] + b0, v1 = acc[mt][nt][1] + b1;
            float v2 = acc[mt][nt][2] + b0, v3 = acc[mt][nt][3] + b1;
            if (RELU) {
                v0 = fmaxf(v0, 0.f); v1 = fmaxf(v1, 0.f);
                v2 = fmaxf(v2, 0.f); v3 = fmaxf(v3, 0.f);
            }
            if (gm1 < M) {
                if (OUTF) *(float2*)&Cf[(size_t)gm1 * Nn + gn] = make_float2(v0, v1);
                if (OUTS) {
                    __nv_bfloat16 h0 = __float2bfloat16(v0), h1 = __float2bfloat16(v1);
                    __nv_bfloat162 hv; hv.x = h0; hv.y = h1;
                    __nv_bfloat162 lv;
                    lv.x = __float2bfloat16(v0 - __bfloat162float(h0));
                    lv.y = __float2bfloat16(v1 - __bfloat162float(h1));
                    *(__nv_bfloat162*)&Ch[(size_t)gm1 * Nn + gn] = hv;
                    *(__nv_bfloat162*)&Cl[(size_t)gm1 * Nn + gn] = lv;
                }
            }
            if (gm2 < M) {
                if (OUTF) *(float2*)&Cf[(size_t)gm2 * Nn + gn] = make_float2(v2, v3);
                if (OUTS) {
                    __nv_bfloat16 h2 = __float2bfloat16(v2), h3 = __float2bfloat16(v3);
                    __nv_bfloat162 hv; hv.x = h2; hv.y = h3;
                    __nv_bfloat162 lv;
                    lv.x = __float2bfloat16(v2 - __bfloat162float(h2));
                    lv.y = __float2bfloat16(v3 - __bfloat162float(h3));
                    *(__nv_bfloat162*)&Ch[(size_t)gm2 * Nn + gn] = hv;
                    *(__nv_bfloat162*)&Cl[(size_t)gm2 * Nn + gn] = lv;
                }
            }
        }
    }
}

// ================= small kernels =================
__global__ void split_kernel(const float* __restrict__ s,
                             __nv_bfloat16* __restrict__ h,
                             __nv_bfloat16* __restrict__ l, int n)
{
    int i = blockIdx.x * 256 + threadIdx.x;
    if (i < n) {
        float v = s[i];
        __nv_bfloat16 a = __float2bfloat16(v);
        h[i] = a;
        l[i] = __float2bfloat16(v - __bfloat162float(a));
    }
}

__global__ void fill0_kernel(float* __restrict__ p, size_t n) {
    size_t i = (size_t)blockIdx.x * blockDim.x + threadIdx.x;
    if (i < n) p[i] = 0.f;
}

__global__ void dots_kernel(const float* __restrict__ h,
                            const float* __restrict__ asrc,
                            const float* __restrict__ adst,
                            float* __restrict__ s, float* __restrict__ t)
{
    int n = blockIdx.x * 8 + (threadIdx.x >> 5);
    if (n >= NN) return;
    int lane = threadIdx.x & 31;
    const float* row = h + (size_t)n * DD;
    float ps = 0.f, pt = 0.f;
    #pragma unroll
    for (int i = 0; i < 8; i++) {
        int d = lane + 32 * i;
        float v = row[d];
        ps += v * asrc[d];
        pt += v * adst[d];
    }
    #pragma unroll
    for (int o = 16; o; o >>= 1) {
        ps += __shfl_xor_sync(0xFFFFFFFFu, ps, o);
        pt += __shfl_xor_sync(0xFFFFFFFFu, pt, o);
    }
    if (lane == 0) { s[n] = ps; t[n] = pt; }
}

__global__ void edge_agg_kernel(const int* __restrict__ ei,
                                const float* __restrict__ s,
                                const float* __restrict__ t,
                                const float* __restrict__ h,
                                float* __restrict__ agg,
                                float* __restrict__ den)
{
    int e = blockIdx.x * 4 + (threadIdx.x >> 6);
    if (e >= ETOT) return;
    int sub = threadIdx.x & 63;
    int src, dst;
    if (e < EE) { src = ei[e]; dst = ei[EE + e]; }
    else        { src = dst = e - EE; }
    float x  = s[src] + t[dst];
    float lr = x > 0.f ? x : NEGS * x;
    float ex = expf(lr);
    if (sub == 0) atomicAdd(&den[dst], ex);
    float4 hv = *(const float4*)&h[(size_t)src * DD + sub * 4];
    float* ap = &agg[(size_t)dst * DD + sub * 4];
    atomicAdd(ap + 0, ex * hv.x);
    atomicAdd(ap + 1, ex * hv.y);
    atomicAdd(ap + 2, ex * hv.z);
    atomicAdd(ap + 3, ex * hv.w);
}

__global__ void gat_epi_kernel(const float* __restrict__ agg,
                               const float* __restrict__ den,
                               const float* __restrict__ b,
                               float* __restrict__ out,
                               __nv_bfloat16* __restrict__ oh,
                               __nv_bfloat16* __restrict__ ol)
{
    size_t i = (size_t)blockIdx.x * 256 + threadIdx.x;
    if (i >= (size_t)NN * DD) return;
    int n = (int)(i >> 8);
    int d = (int)(i & 255);
    float v = agg[i] / den[n] + b[d];
    v = fmaxf(v, 0.f);
    out[i] = v;
    if (oh) {
        __nv_bfloat16 a = __float2bfloat16(v);
        oh[i] = a;
        ol[i] = __float2bfloat16(v - __bfloat162float(a));
    }
}

__global__ void build_seq_kernel(const float* __restrict__ x1,
                                 const float* __restrict__ x2,
                                 const float* __restrict__ cls,
                                 const float* __restrict__ pos,
                                 float* __restrict__ seq,
                                 __nv_bfloat16* __restrict__ sh,
                                 __nv_bfloat16* __restrict__ sl)
{
    size_t i = (size_t)blockIdx.x * 256 + threadIdx.x;
    if (i >= (size_t)NTOK * DD) return;
    int d = (int)(i & 255);
    size_t tok = i >> 8;
    int which = (int)(tok % 3);
    size_t n = tok / 3;
    float v;
    if (which == 0)      v = cls[d];
    else if (which == 1) v = x1[n * DD + d];
    else                 v = x2[n * DD + d];
    v += pos[which * DD + d];
    seq[i] = v;
    __nv_bfloat16 a = __float2bfloat16(v);
    sh[i] = a;
    sl[i] = __float2bfloat16(v - __bfloat162float(a));
}

__global__ void attn_kernel(const float* __restrict__ qkv,
                            __nv_bfloat16* __restrict__ atth,
                            __nv_bfloat16* __restrict__ attl)
{
    int w = blockIdx.x * 8 + (threadIdx.x >> 5);
    if (w >= NN * NHEAD) return;
    int lane = threadIdx.x & 31;
    int n = w >> 2, hh = w & 3;
    const float* base = qkv + (size_t)n * 3 * (3 * DD) + hh * DH + lane * 2;
    float2 q[3], k[3], v[3];
    #pragma unroll
    for (int i = 0; i < 3; i++) {
        q[i] = *(const float2*)(base + (size_t)i * (3 * DD));
        k[i] = *(const float2*)(base + (size_t)i * (3 * DD) + DD);
        v[i] = *(const float2*)(base + (size_t)i * (3 * DD) + 2 * DD);
    }
    float lg[3][3];
    #pragma unroll
    for (int i = 0; i < 3; i++)
        #pragma unroll
        for (int j = 0; j < 3; j++) {
            float p = q[i].x * k[j].x + q[i].y * k[j].y;
            #pragma unroll
            for (int o = 16; o; o >>= 1) p += __shfl_xor_sync(0xFFFFFFFFu, p, o);
            lg[i][j] = p * 0.125f;
        }
    #pragma unroll
    for (int i = 0; i < 3; i++) {
        float m  = fmaxf(lg[i][0], fmaxf(lg[i][1], lg[i][2]));
        float e0 = expf(lg[i][0] - m), e1 = expf(lg[i][1] - m), e2 = expf(lg[i][2] - m);
        float inv = 1.f / (e0 + e1 + e2);
        float ox = (e0 * v[0].x + e1 * v[1].x + e2 * v[2].x) * inv;
        float oy = (e0 * v[0].y + e1 * v[1].y + e2 * v[2].y) * inv;
        size_t o = ((size_t)(n * 3 + i)) * DD + hh * DH + lane * 2;
        __nv_bfloat16 hx = __float2bfloat16(ox);
        __nv_bfloat16 hy = __float2bfloat16(oy);
        __nv_bfloat162 hv; hv.x = hx; hv.y = hy;
        __nv_bfloat162 lv;
        lv.x = __float2bfloat16(ox - __bfloat162float(hx));
        lv.y = __float2bfloat16(oy - __bfloat162float(hy));
        *(__nv_bfloat162*)&atth[o] = hv;
        *(__nv_bfloat162*)&attl[o] = lv;
    }
}

__global__ void add_ln_kernel(float* __restrict__ seq,
                              const float* __restrict__ res,
                              const float* __restrict__ g,
                              const float* __restrict__ b,
                              __nv_bfloat16* __restrict__ sh,
                              __nv_bfloat16* __restrict__ sl)
{
    int tok = blockIdx.x * 8 + (threadIdx.x >> 5);
    if (tok >= NTOK) return;
    int lane = threadIdx.x & 31;
    float* p = seq + (size_t)tok * DD;
    const float* q = res + (size_t)tok * DD;
    float v[8];
    float sum = 0.f, sq = 0.f;
    #pragma unroll
    for (int i = 0; i < 2; i++) {
        float4 a = *(const float4*)&p[lane * 8 + i * 4];
        float4 c = *(const float4*)&q[lane * 8 + i * 4];
        float w0 = a.x + c.x, w1 = a.y + c.y, w2 = a.z + c.z, w3 = a.w + c.w;
        v[i * 4 + 0] = w0; v[i * 4 + 1] = w1; v[i * 4 + 2] = w2; v[i * 4 + 3] = w3;
        sum += w0 + w1 + w2 + w3;
        sq  += w0 * w0 + w1 * w1 + w2 * w2 + w3 * w3;
    }
    #pragma unroll
    for (int o = 16; o; o >>= 1) {
        sum += __shfl_xor_sync(0xFFFFFFFFu, sum, o);
        sq  += __shfl_xor_sync(0xFFFFFFFFu, sq, o);
    }
    float mean = sum * (1.f / DD);
    float var  = sq * (1.f / DD) - mean * mean;
    float inv  = rsqrtf(var + 1e-5f);
    #pragma unroll
    for (int i = 0; i < 8; i++) {
        int d = lane * 8 + i;
        float y = (v[i] - mean) * inv * g[d] + b[d];
        p[d] = y;
        size_t o = (size_t)tok * DD + d;
        __nv_bfloat16 a = __float2bfloat16(y);
        sh[o] = a;
        sl[o] = __float2bfloat16(y - __bfloat162float(a));
    }
}

__global__ void final_ln_kernel(const float* __restrict__ seq,
                                const float* __restrict__ g,
                                const float* __restrict__ b,
                                float* __restrict__ out)
{
    int n = blockIdx.x * 8 + (threadIdx.x >> 5);
    if (n >= NN) return;
    int lane = threadIdx.x & 31;
    const float* p = seq + (size_t)n * 3 * DD;
    float v[8];
    float sum = 0.f, sq = 0.f;
    #pragma unroll
    for (int i = 0; i < 2; i++) {
        float4 a = *(const float4*)&p[lane * 8 + i * 4];
        v[i * 4 + 0] = a.x; v[i * 4 + 1] = a.y; v[i * 4 + 2] = a.z; v[i * 4 + 3] = a.w;
        sum += a.x + a.y + a.z + a.w;
        sq  += a.x * a.x + a.y * a.y + a.z * a.z + a.w * a.w;
    }
    #pragma unroll
    for (int o = 16; o; o >>= 1) {
        sum += __shfl_xor_sync(0xFFFFFFFFu, sum, o);
        sq  += __shfl_xor_sync(0xFFFFFFFFu, sq, o);
    }
    float mean = sum * (1.f / DD);
    float var  = sq * (1.f / DD) - mean * mean;
    float inv  = rsqrtf(var + 1e-5f);
    #pragma unroll
    for (int i = 0; i < 8; i++) {
        int d = lane * 8 + i;
        out[(size_t)n * DD + d] = (v[i] - mean) * inv * g[d] + b[d];
    }
}

// ================= host side =================
template<bool BIAS, bool RELU, bool OUTF, bool OUTS>
static void run_gemm_tc(const __nv_bfloat16* Ah, const __nv_bfloat16* Al,
                        const __nv_bfloat16* Bh, const __nv_bfloat16* Bl,
                        const float* bias, float* Cf,
                        __nv_bfloat16* Ch, __nv_bfloat16* Cl,
                        int M, int Nn, int K)
{
    cudaFuncSetAttribute(gemm_mma_kernel<BIAS, RELU, OUTF, OUTS>,
                         cudaFuncAttributeMaxDynamicSharedMemorySize, GM_SMEM);
    dim3 grid(Nn / 128, (M + 127) / 128);
    gemm_mma_kernel<BIAS, RELU, OUTF, OUTS><<<grid, 256, GM_SMEM>>>(
        Ah, Al, Bh, Bl, bias, Cf, Ch, Cl, M, Nn, K);
}

static void run_split(const float* s, __nv_bfloat16* h, __nv_bfloat16* l, int n) {
    split_kernel<<<(n + 255) / 256, 256>>>(s, h, l, n);
}

extern "C" void kernel_launch(void* const* d_in, const int* in_sizes, int n_in,
                              void* d_out, int out_size)
{
    const float* x        = (const float*)d_in[0];
    const int*   ei       = (const int*)  d_in[1];
    const float* gat1_W   = (const float*)d_in[2];
    const float* gat1_b   = (const float*)d_in[3];
    const float* gat1_as  = (const float*)d_in[4];
    const float* gat1_ad  = (const float*)d_in[5];
    const float* gat2_W   = (const float*)d_in[6];
    const float* gat2_b   = (const float*)d_in[7];
    const float* gat2_as  = (const float*)d_in[8];
    const float* gat2_ad  = (const float*)d_in[9];
    const float* cls      = (const float*)d_in[10];
    const float* pos      = (const float*)d_in[11];
    const float* Wqkv     = (const float*)d_in[12];
    const float* bqkv     = (const float*)d_in[13];
    const float* Wo       = (const float*)d_in[14];
    const float* bo       = (const float*)d_in[15];
    const float* ln1_g    = (const float*)d_in[16];
    const float* ln1_b    = (const float*)d_in[17];
    const float* ln2_g    = (const float*)d_in[18];
    const float* ln2_b    = (const float*)d_in[19];
    const float* Wff1     = (const float*)d_in[20];
    const float* bff1     = (const float*)d_in[21];
    const float* Wff2     = (const float*)d_in[22];
    const float* bff2     = (const float*)d_in[23];
    const float* norm_g   = (const float*)d_in[24];
    const float* norm_b   = (const float*)d_in[25];
    float* out = (float*)d_out;

    float *h, *s, *t, *den, *agg, *x1, *x2, *seq, *qkv, *tmp;
    cudaGetSymbolAddress((void**)&h,   g_h);
    cudaGetSymbolAddress((void**)&s,   g_s);
    cudaGetSymbolAddress((void**)&t,   g_t);
    cudaGetSymbolAddress((void**)&den, g_den);
    cudaGetSymbolAddress((void**)&agg, g_agg);
    cudaGetSymbolAddress((void**)&x1,  g_x1);
    cudaGetSymbolAddress((void**)&x2,  g_x2);
    cudaGetSymbolAddress((void**)&seq, g_seq);
    cudaGetSymbolAddress((void**)&qkv, g_qkv);
    cudaGetSymbolAddress((void**)&tmp, g_tmp);

    __nv_bfloat16 *xh, *xl, *x1h, *x1l, *seqh, *seql, *atth, *attl, *ffh, *ffl, *wbh, *wbl;
    cudaGetSymbolAddress((void**)&xh,   g_xh);
    cudaGetSymbolAddress((void**)&xl,   g_xl);
    cudaGetSymbolAddress((void**)&x1h,  g_x1h);
    cudaGetSymbolAddress((void**)&x1l,  g_x1l);
    cudaGetSymbolAddress((void**)&seqh, g_seqh);
    cudaGetSymbolAddress((void**)&seql, g_seql);
    cudaGetSymbolAddress((void**)&atth, g_atth);
    cudaGetSymbolAddress((void**)&attl, g_attl);
    cudaGetSymbolAddress((void**)&ffh,  g_ffh);
    cudaGetSymbolAddress((void**)&ffl,  g_ffl);
    cudaGetSymbolAddress((void**)&wbh,  g_wbh);
    cudaGetSymbolAddress((void**)&wbl,  g_wbl);

    const size_t nd = (size_t)NN * DD;

    // ---- weight + input conversion to split bf16 ----
    run_split(x,      xh,              xl,              NN * DIN);
    run_split(gat1_W, wbh + WOFF_W1,   wbl + WOFF_W1,   DD * DIN);
    run_split(gat2_W, wbh + WOFF_W2,   wbl + WOFF_W2,   DD * DD);
    run_split(Wqkv,   wbh + WOFF_QKV,  wbl + WOFF_QKV,  2 * 3 * DD * DD);
    run_split(Wo,     wbh + WOFF_WO,   wbl + WOFF_WO,   2 * DD * DD);
    run_split(Wff1,   wbh + WOFF_F1,   wbl + WOFF_F1,   2 * 4 * DD * DD);
    run_split(Wff2,   wbh + WOFF_F2,   wbl + WOFF_F2,   2 * DD * 4 * DD);

    // ---- GAT layer 1 ----
    run_gemm_tc<false, false, true, false>(xh, xl, wbh + WOFF_W1, wbl + WOFF_W1,
                                           nullptr, h, nullptr, nullptr, NN, DD, DIN);
    dots_kernel<<<(NN + 7) / 8, 256>>>(h, gat1_as, gat1_ad, s, t);
    fill0_kernel<<<(unsigned)((nd + 255) / 256), 256>>>(agg, nd);
    fill0_kernel<<<(NN + 255) / 256, 256>>>(den, NN);
    edge_agg_kernel<<<(ETOT + 3) / 4, 256>>>(ei, s, t, h, agg, den);
    gat_epi_kernel<<<(unsigned)((nd + 255) / 256), 256>>>(agg, den, gat1_b, x1, x1h, x1l);

    // ---- GAT layer 2 ----
    run_gemm_tc<false, false, true, false>(x1h, x1l, wbh + WOFF_W2, wbl + WOFF_W2,
                                           nullptr, h, nullptr, nullptr, NN, DD, DD);
    dots_kernel<<<(NN + 7) / 8, 256>>>(h, gat2_as, gat2_ad, s, t);
    fill0_kernel<<<(unsigned)((nd + 255) / 256), 256>>>(agg, nd);
    fill0_kernel<<<(NN + 255) / 256, 256>>>(den, NN);
    edge_agg_kernel<<<(ETOT + 3) / 4, 256>>>(ei, s, t, h, agg, den);
    gat_epi_kernel<<<(unsigned)((nd + 255) / 256), 256>>>(agg, den, gat2_b, x2, nullptr, nullptr);

    // ---- build sequence ----
    build_seq_kernel<<<(unsigned)(((size_t)NTOK * DD + 255) / 256), 256>>>(x1, x2, cls, pos, seq, seqh, seql);

    // ---- transformer layers ----
    for (int l = 0; l < 2; l++) {
        const __nv_bfloat16* wqh = wbh + WOFF_QKV + (size_t)l * 3 * DD * DD;
        const __nv_bfloat16* wql = wbl + WOFF_QKV + (size_t)l * 3 * DD * DD;
        const __nv_bfloat16* woh = wbh + WOFF_WO  + (size_t)l * DD * DD;
        const __nv_bfloat16* wol = wbl + WOFF_WO  + (size_t)l * DD * DD;
        const __nv_bfloat16* wf1h = wbh + WOFF_F1 + (size_t)l * 4 * DD * DD;
        const __nv_bfloat16* wf1l = wbl + WOFF_F1 + (size_t)l * 4 * DD * DD;
        const __nv_bfloat16* wf2h = wbh + WOFF_F2 + (size_t)l * DD * 4 * DD;
        const __nv_bfloat16* wf2l = wbl + WOFF_F2 + (size_t)l * DD * 4 * DD;

        run_gemm_tc<true, false, true, false>(seqh, seql, wqh, wql, bqkv + (size_t)l * 3 * DD,
                                              qkv, nullptr, nullptr, NTOK, 3 * DD, DD);
        attn_kernel<<<(NN * NHEAD + 7) / 8, 256>>>(qkv, atth, attl);
        run_gemm_tc<true, false, true, false>(atth, attl, woh, wol, bo + (size_t)l * DD,
                                              tmp, nullptr, nullptr, NTOK, DD, DD);
        add_ln_kernel<<<(NTOK + 7) / 8, 256>>>(seq, tmp, ln1_g + l * DD, ln1_b + l * DD, seqh, seql);
        run_gemm_tc<true, true, false, true>(seqh, seql, wf1h, wf1l, bff1 + (size_t)l * 4 * DD,
                                             nullptr, ffh, ffl, NTOK, 4 * DD, DD);
        run_gemm_tc<true, false, true, false>(ffh, ffl, wf2h, wf2l, bff2 + (size_t)l * DD,
                                              tmp, nullptr, nullptr, NTOK, DD, 4 * DD);
        add_ln_kernel<<<(NTOK + 7) / 8, 256>>>(seq, tmp, ln2_g + l * DD, ln2_b + l * DD, seqh, seql);
    }

    // ---- final LN on CLS token ----
    final_ln_kernel<<<(NN + 7) / 8, 256>>>(seq, norm_g, norm_b, out);
}

// round 7
// speedup vs baseline: 1.2623x; 1.2623x over previous
#include <cuda_runtime.h>
#include <cuda_bf16.h>
#include <cstdint>
#include <cstdio>

// ---------------- problem constants ----------------
#define NN      50000
#define EE      320000
#define ETOT    (EE + NN)
#define DIN     128
#define DD      256
#define NTOK    (NN * 3)
#define NHEAD   4
#define DH      64
#define NEGS    0.2f

// ---------------- fp32 scratch ----------------
__device__ float g_h  [(size_t)NN * DD];
__device__ float g_s  [NN];
__device__ float g_t  [NN];
__device__ float g_x1 [(size_t)NN * DD];
__device__ float g_x2 [(size_t)NN * DD];
__device__ float g_seq[(size_t)NTOK * DD];
__device__ float g_qkv[(size_t)NTOK * 3 * DD];
__device__ float g_tmp[(size_t)NTOK * DD];

// ---------------- CSR graph scratch ----------------
__device__ int g_cnt [NN];
__device__ int g_slot[ETOT];
__device__ int g_rows[NN + 1];
__device__ int g_csrc[ETOT];

// ---------------- bf16 split operand buffers ----------------
__device__ __nv_bfloat16 g_xh [(size_t)NN * DIN];
__device__ __nv_bfloat16 g_xl [(size_t)NN * DIN];
__device__ __nv_bfloat16 g_x1h[(size_t)NN * DD];
__device__ __nv_bfloat16 g_x1l[(size_t)NN * DD];
__device__ __nv_bfloat16 g_seqh[(size_t)NTOK * DD];
__device__ __nv_bfloat16 g_seql[(size_t)NTOK * DD];
__device__ __nv_bfloat16 g_atth[(size_t)NTOK * DD];
__device__ __nv_bfloat16 g_attl[(size_t)NTOK * DD];
__device__ __nv_bfloat16 g_ffh[(size_t)NTOK * 4 * DD];
__device__ __nv_bfloat16 g_ffl[(size_t)NTOK * 4 * DD];
// weight pool (hi/lo)
#define WOFF_W1   0
#define WOFF_W2   32768
#define WOFF_QKV  98304
#define WOFF_WO   491520
#define WOFF_F1   622592
#define WOFF_F2   1146880
#define WTOT      1671168
__device__ __nv_bfloat16 g_wbh[WTOT];
__device__ __nv_bfloat16 g_wbl[WTOT];

// ================= warp-mma helpers =================
__device__ __forceinline__ uint32_t smem_u32(const void* p) {
    uint32_t a;
    asm("{ .reg .u64 t; cvta.to.shared.u64 t, %1; cvt.u32.u64 %0, t; }" : "=r"(a) : "l"(p));
    return a;
}

#define LDM4(r, addr) \
    asm volatile("ldmatrix.sync.aligned.m8n8.x4.shared.b16 {%0,%1,%2,%3}, [%4];" \
        : "=r"((r)[0]), "=r"((r)[1]), "=r"((r)[2]), "=r"((r)[3]) : "r"(addr))
#define MMA16816(c, a, b) \
    asm volatile("mma.sync.aligned.m16n8k16.row.col.f32.bf16.bf16.f32 " \
        "{%0,%1,%2,%3}, {%4,%5,%6,%7}, {%8,%9}, {%0,%1,%2,%3};" \
        : "+f"((c)[0]), "+f"((c)[1]), "+f"((c)[2]), "+f"((c)[3]) \
        : "r"((a)[0]), "r"((a)[1]), "r"((a)[2]), "r"((a)[3]), "r"((b)[0]), "r"((b)[1]))
#define CP_ASYNC(dst, src, sz) \
    asm volatile("cp.async.cg.shared.global [%0], [%1], 16, %2;" :: "r"(dst), "l"(src), "r"(sz))
#define CP_COMMIT() asm volatile("cp.async.commit_group;" ::: "memory")

// ================= split-bf16 GEMM via mma.sync ==========================
// C[M,N] = (Ah+Al)[M,K] * (Bh+Bl)[N,K]^T (3-term).
// BM=128, BN=128, BK=32; 256 threads = 8 warps (2m x 4n), warp tile 64x32.
// 2-stage cp.async double buffer, 2 CTAs/SM. B via x4 ldmatrix.
#define RSB     80                     // row stride bytes in smem
#define MAT_SZ  10240                  // 128 rows * 80B
#define STG_B   20480
#define STG_SZ  40960
#define GM_SMEM (2 * STG_SZ)           // 81920

template<bool BIAS, bool RELU, bool OUTF, bool OUTS>
__global__ __launch_bounds__(256, 2) void gemm_mma_kernel(
    const __nv_bfloat16* __restrict__ Ah, const __nv_bfloat16* __restrict__ Al,
    const __nv_bfloat16* __restrict__ Bh, const __nv_bfloat16* __restrict__ Bl,
    const float* __restrict__ bias,
    float* __restrict__ Cf, __nv_bfloat16* __restrict__ Ch, __nv_bfloat16* __restrict__ Cl,
    int M, int Nn, int K)
{
    extern __shared__ char smraw[];
    const uint32_t sb = smem_u32(smraw);
    const int tid = threadIdx.x, wid = tid >> 5, lane = tid & 31;
    const int wm = wid & 1, wn = wid >> 1;
    const int m0 = blockIdx.y * 128, n0 = blockIdx.x * 128;

    float acc[4][4][4];
    #pragma unroll
    for (int mt = 0; mt < 4; mt++)
        #pragma unroll
        for (int nt = 0; nt < 4; nt++)
            #pragma unroll
            for (int c = 0; c < 4; c++) acc[mt][nt][c] = 0.f;

    const int a_row  = (lane & 7) + ((lane >> 3) & 1) * 8;
    const int a_k    = (lane >> 4) * 8;
    const int b_row4 = (lane & 7) + ((lane >> 4) & 1) * 8;   // row within 16-row pair
    const int b_k4   = ((lane >> 3) & 1) * 8;

    const int T = K >> 5;

    auto load_stage = [&](int buf, int k0) {
        uint32_t base = sb + buf * STG_SZ;
        #pragma unroll
        for (int it = 0; it < 8; it++) {
            int i    = tid + it * 256;
            int part = i >> 10;            // 0=A, 1=B
            int idx  = i & 1023;
            int hl   = idx >> 9;           // 0=hi, 1=lo
            int rem  = idx & 511;
            int row  = rem >> 2;
            int ch   = rem & 3;
            uint32_t dst = base + part * STG_B + hl * MAT_SZ + row * RSB + ch * 16;
            const __nv_bfloat16* src;
            int sz = 16;
            if (part == 0) {
                src = hl ? Al : Ah;
                int gm = m0 + row;
                if (gm >= M) sz = 0;
                src += (size_t)gm * K + k0 + ch * 8;
            } else {
                src = (hl ? Bl : Bh) + (size_t)(n0 + row) * K + k0 + ch * 8;
            }
            CP_ASYNC(dst, src, sz);
        }
        CP_COMMIT();
    };

    auto compute = [&](int buf) {
        uint32_t base  = sb + buf * STG_SZ;
        uint32_t aB    = base + (wm * 64) * RSB;
        uint32_t bB    = base + STG_B + (wn * 32) * RSB;
        #pragma unroll
        for (int ks = 0; ks < 32; ks += 16) {
            // B fragments via x4: 2 loads hi + 2 loads lo
            uint32_t bh[4][2], bl[4][2];
            #pragma unroll
            for (int ntp = 0; ntp < 2; ntp++) {
                uint32_t bd = bB + (ntp * 16 + b_row4) * RSB + (ks + b_k4) * 2;
                uint32_t r4[4];
                LDM4(r4, bd);
                bh[2 * ntp][0] = r4[0]; bh[2 * ntp][1] = r4[1];
                bh[2 * ntp + 1][0] = r4[2]; bh[2 * ntp + 1][1] = r4[3];
                LDM4(r4, bd + MAT_SZ);
                bl[2 * ntp][0] = r4[0]; bl[2 * ntp][1] = r4[1];
                bl[2 * ntp + 1][0] = r4[2]; bl[2 * ntp + 1][1] = r4[3];
            }
            // per-mt: load A hi/lo, issue 12 MMAs nt-interleaved (reuse dist 4)
            #pragma unroll
            for (int mt = 0; mt < 4; mt++) {
                uint32_t ah4[4], al4[4];
                uint32_t ad = aB + (mt * 16 + a_row) * RSB + (ks + a_k) * 2;
                LDM4(ah4, ad);
                LDM4(al4, ad + MAT_SZ);
                #pragma unroll
                for (int nt = 0; nt < 4; nt++) MMA16816(acc[mt][nt], ah4, bh[nt]);
                #pragma unroll
                for (int nt = 0; nt < 4; nt++) MMA16816(acc[mt][nt], ah4, bl[nt]);
                #pragma unroll
                for (int nt = 0; nt < 4; nt++) MMA16816(acc[mt][nt], al4, bh[nt]);
            }
        }
    };

    load_stage(0, 0);
    for (int t = 0; t < T; t++) {
        if (t + 1 < T) {
            load_stage((t + 1) & 1, (t + 1) << 5);
            asm volatile("cp.async.wait_group 1;" ::: "memory");
        } else {
            asm volatile("cp.async.wait_group 0;" ::: "memory");
        }
        __syncthreads();
        compute(t & 1);
        __syncthreads();
    }

    // ---------------- epilogue ----------------
    const int r0    = lane >> 2;
    const int cpair = (lane & 3) * 2;
    #pragma unroll
    for (int mt = 0; mt < 4; mt++) {
        int gm1 = m0 + wm * 64 + mt * 16 + r0;
        int gm2 = gm1 + 8;
        #pragma unroll
        for (int nt = 0; nt < 4; nt++) {
            int gn = n0 + wn * 32 + nt * 8 + cpair;
            float b0 = 0.f, b1 = 0.f;
            if (BIAS) { float2 bb = *(const float2*)&bias[gn]; b0 = bb.x; b1 = bb.y; }
            float v0 = acc[mt][nt][0] + b0, v1 = acc[mt][nt][1] + b1;
            float v2 = acc[mt][nt][2] + b0, v3 = acc[mt][nt][3] + b1;
            if (RELU) {
                v0 = fmaxf(v0, 0.f); v1 = fmaxf(v1, 0.f);
                v2 = fmaxf(v2, 0.f); v3 = fmaxf(v3, 0.f);
            }
            if (gm1 < M) {
                if (OUTF) *(float2*)&Cf[(size_t)gm1 * Nn + gn] = make_float2(v0, v1);
                if (OUTS) {
                    __nv_bfloat16 h0 = __float2bfloat16(v0), h1 = __float2bfloat16(v1);
                    __nv_bfloat162 hv; hv.x = h0; hv.y = h1;
                    __nv_bfloat162 lv;
                    lv.x = __float2bfloat16(v0 - __bfloat162float(h0));
                    lv.y = __float2bfloat16(v1 - __bfloat162float(h1));
                    *(__nv_bfloat162*)&Ch[(size_t)gm1 * Nn + gn] = hv;
                    *(__nv_bfloat162*)&Cl[(size_t)gm1 * Nn + gn] = lv;
                }
            }
            if (gm2 < M) {
                if (OUTF) *(float2*)&Cf[(size_t)gm2 * Nn + gn] = make_float2(v2, v3);
                if (OUTS) {
                    __nv_bfloat16 h2 = __float2bfloat16(v2), h3 = __float2bfloat16(v3);
                    __nv_bfloat162 hv; hv.x = h2; hv.y = h3;
                    __nv_bfloat162 lv;
                    lv.x = __float2bfloat16(v2 - __bfloat162float(h2));
                    lv.y = __float2bfloat16(v3 - __bfloat162float(h3));
                    *(__nv_bfloat162*)&Ch[(size_t)gm2 * Nn + gn] = hv;
                    *(__nv_bfloat162*)&Cl[(size_t)gm2 * Nn + gn] = lv;
                }
            }
        }
    }
}

// ================= CSR build kernels =================
__global__ void fill0i_kernel(int* __restrict__ p, int n) {
    int i = blockIdx.x * 256 + threadIdx.x;
    if (i < n) p[i] = 0;
}

__global__ void hist_kernel(const int* __restrict__ ei, int* __restrict__ cnt,
                            int* __restrict__ slot)
{
    int e = blockIdx.x * 256 + threadIdx.x;
    if (e >= ETOT) return;
    int dst = (e < EE) ? ei[EE + e] : e - EE;
    slot[e] = atomicAdd(&cnt[dst], 1);
}

__global__ void scan_kernel(const int* __restrict__ cnt, int* __restrict__ rows) {
    __shared__ int wsum[32];
    int tid = threadIdx.x;               // 1024 threads
    const int CH = (NN + 1023) / 1024;   // 49
    int beg = tid * CH;
    int ssum = 0;
    for (int i = 0; i < CH; i++) {
        int idx = beg + i;
        if (idx < NN) ssum += cnt[idx];
    }
    int lane = tid & 31, wid = tid >> 5;
    int v = ssum;
    #pragma unroll
    for (int o = 1; o < 32; o <<= 1) {
        int u = __shfl_up_sync(0xFFFFFFFFu, v, o);
        if (lane >= o) v += u;
    }
    if (lane == 31) wsum[wid] = v;
    __syncthreads();
    if (wid == 0) {
        int w = wsum[lane];
        #pragma unroll
        for (int o = 1; o < 32; o <<= 1) {
            int u = __shfl_up_sync(0xFFFFFFFFu, w, o);
            if (lane >= o) w += u;
        }
        wsum[lane] = w;
    }
    __syncthreads();
    int off = v - ssum + (wid ? wsum[wid - 1] : 0);
    for (int i = 0; i < CH; i++) {
        int idx = beg + i;
        if (idx < NN) { rows[idx] = off; off += cnt[idx]; }
    }
    if (tid == 0) rows[NN] = ETOT;
}

__global__ void scatter_kernel(const int* __restrict__ ei, const int* __restrict__ rows,
                               const int* __restrict__ slot, int* __restrict__ csrc)
{
    int e = blockIdx.x * 256 + threadIdx.x;
    if (e >= ETOT) return;
    int src, dst;
    if (e < EE) { src = ei[e]; dst = ei[EE + e]; }
    else        { src = dst = e - EE; }
    csrc[rows[dst] + slot[e]] = src;
}

// ================= GAT gather (CSR, no atomics) =================
// One 64-thread group per dst node; den computed redundantly (deterministic).
template<bool OUTS>
__global__ void gather_kernel(const int* __restrict__ rows, const int* __restrict__ csrc,
                              const float* __restrict__ s, const float* __restrict__ t,
                              const float* __restrict__ h, const float* __restrict__ b,
                              float* __restrict__ outf,
                              __nv_bfloat16* __restrict__ oh, __nv_bfloat16* __restrict__ ol)
{
    int n = blockIdx.x * 4 + (threadIdx.x >> 6);
    if (n >= NN) return;
    int sub = threadIdx.x & 63;
    float tn = __ldg(&t[n]);
    int beg = __ldg(&rows[n]), end = __ldg(&rows[n + 1]);
    float a0 = 0.f, a1 = 0.f, a2 = 0.f, a3 = 0.f, den = 0.f;
    for (int i = beg; i < end; i++) {
        int src = __ldg(&csrc[i]);
        float x = __ldg(&s[src]) + tn;
        float ex = expf(x > 0.f ? x : NEGS * x);
        den += ex;
        float4 hv = *(const float4*)&h[(size_t)src * DD + sub * 4];
        a0 += ex * hv.x; a1 += ex * hv.y; a2 += ex * hv.z; a3 += ex * hv.w;
    }
    float inv = 1.f / den;
    float4 bb = *(const float4*)&b[sub * 4];
    float v0 = fmaxf(a0 * inv + bb.x, 0.f);
    float v1 = fmaxf(a1 * inv + bb.y, 0.f);
    float v2 = fmaxf(a2 * inv + bb.z, 0.f);
    float v3 = fmaxf(a3 * inv + bb.w, 0.f);
    size_t o = (size_t)n * DD + sub * 4;
    *(float4*)&outf[o] = make_float4(v0, v1, v2, v3);
    if (OUTS) {
        __nv_bfloat16 h0 = __float2bfloat16(v0), h1 = __float2bfloat16(v1);
        __nv_bfloat16 h2 = __float2bfloat16(v2), h3 = __float2bfloat16(v3);
        __nv_bfloat162 p0; p0.x = h0; p0.y = h1;
        __nv_bfloat162 p1; p1.x = h2; p1.y = h3;
        *(__nv_bfloat162*)&oh[o]     = p0;
        *(__nv_bfloat162*)&oh[o + 2] = p1;
        __nv_bfloat162 q0, q1;
        q0.x = __float2bfloat16(v0 - __bfloat162float(h0));
        q0.y = __float2bfloat16(v1 - __bfloat162float(h1));
        q1.x = __float2bfloat16(v2 - __bfloat162float(h2));
        q1.y = __float2bfloat16(v3 - __bfloat162float(h3));
        *(__nv_bfloat162*)&ol[o]     = q0;
        *(__nv_bfloat162*)&ol[o + 2] = q1;
    }
}

// ================= small kernels =================
__global__ void split_kernel(const float* __restrict__ s,
                             __nv_bfloat16* __restrict__ h,
                             __nv_bfloat16* __restrict__ l, int n)
{
    int i = blockIdx.x * 256 + threadIdx.x;
    if (i < n) {
        float v = s[i];
        __nv_bfloat16 a = __float2bfloat16(v);
        h[i] = a;
        l[i] = __float2bfloat16(v - __bfloat162float(a));
    }
}

__global__ void dots_kernel(const float* __restrict__ h,
                            const float* __restrict__ asrc,
                            const float* __restrict__ adst,
                            float* __restrict__ s, float* __restrict__ t)
{
    int n = blockIdx.x * 8 + (threadIdx.x >> 5);
    if (n >= NN) return;
    int lane = threadIdx.x & 31;
    const float* row = h + (size_t)n * DD;
    float ps = 0.f, pt = 0.f;
    #pragma unroll
    for (int i = 0; i < 8; i++) {
        int d = lane + 32 * i;
        float v = row[d];
        ps += v * asrc[d];
        pt += v * adst[d];
    }
    #pragma unroll
    for (int o = 16; o; o >>= 1) {
        ps += __shfl_xor_sync(0xFFFFFFFFu, ps, o);
        pt += __shfl_xor_sync(0xFFFFFFFFu, pt, o);
    }
    if (lane == 0) { s[n] = ps; t[n] = pt; }
}

__global__ void build_seq_kernel(const float* __restrict__ x1,
                                 const float* __restrict__ x2,
                                 const float* __restrict__ cls,
                                 const float* __restrict__ pos,
                                 float* __restrict__ seq,
                                 __nv_bfloat16* __restrict__ sh,
                                 __nv_bfloat16* __restrict__ sl)
{
    size_t i = (size_t)blockIdx.x * 256 + threadIdx.x;
    if (i >= (size_t)NTOK * DD) return;
    int d = (int)(i & 255);
    size_t tok = i >> 8;
    int which = (int)(tok % 3);
    size_t n = tok / 3;
    float v;
    if (which == 0)      v = cls[d];
    else if (which == 1) v = x1[n * DD + d];
    else                 v = x2[n * DD + d];
    v += pos[which * DD + d];
    seq[i] = v;
    __nv_bfloat16 a = __float2bfloat16(v);
    sh[i] = a;
    sl[i] = __float2bfloat16(v - __bfloat162float(a));
}

__global__ void attn_kernel(const float* __restrict__ qkv,
                            __nv_bfloat16* __restrict__ atth,
                            __nv_bfloat16* __restrict__ attl)
{
    int w = blockIdx.x * 8 + (threadIdx.x >> 5);
    if (w >= NN * NHEAD) return;
    int lane = threadIdx.x & 31;
    int n = w >> 2, hh = w & 3;
    const float* base = qkv + (size_t)n * 3 * (3 * DD) + hh * DH + lane * 2;
    float2 q[3], k[3], v[3];
    #pragma unroll
    for (int i = 0; i < 3; i++) {
        q[i] = *(const float2*)(base + (size_t)i * (3 * DD));
        k[i] = *(const float2*)(base + (size_t)i * (3 * DD) + DD);
        v[i] = *(const float2*)(base + (size_t)i * (3 * DD) + 2 * DD);
    }
    float lg[3][3];
    #pragma unroll
    for (int i = 0; i < 3; i++)
        #pragma unroll
        for (int j = 0; j < 3; j++) {
            float p = q[i].x * k[j].x + q[i].y * k[j].y;
            #pragma unroll
            for (int o = 16; o; o >>= 1) p += __shfl_xor_sync(0xFFFFFFFFu, p, o);
            lg[i][j] = p * 0.125f;
        }
    #pragma unroll
    for (int i = 0; i < 3; i++) {
        float m  = fmaxf(lg[i][0], fmaxf(lg[i][1], lg[i][2]));
        float e0 = expf(lg[i][0] - m), e1 = expf(lg[i][1] - m), e2 = expf(lg[i][2] - m);
        float inv = 1.f / (e0 + e1 + e2);
        float ox = (e0 * v[0].x + e1 * v[1].x + e2 * v[2].x) * inv;
        float oy = (e0 * v[0].y + e1 * v[1].y + e2 * v[2].y) * inv;
        size_t o = ((size_t)(n * 3 + i)) * DD + hh * DH + lane * 2;
        __nv_bfloat16 hx = __float2bfloat16(ox);
        __nv_bfloat16 hy = __float2bfloat16(oy);
        __nv_bfloat162 hv; hv.x = hx; hv.y = hy;
        __nv_bfloat162 lv;
        lv.x = __float2bfloat16(ox - __bfloat162float(hx));
        lv.y = __float2bfloat16(oy - __bfloat162float(hy));
        *(__nv_bfloat162*)&atth[o] = hv;
        *(__nv_bfloat162*)&attl[o] = lv;
    }
}

__global__ void add_ln_kernel(float* __restrict__ seq,
                              const float* __restrict__ res,
                              const float* __restrict__ g,
                              const float* __restrict__ b,
                              __nv_bfloat16* __restrict__ sh,
                              __nv_bfloat16* __restrict__ sl)
{
    int tok = blockIdx.x * 8 + (threadIdx.x >> 5);
    if (tok >= NTOK) return;
    int lane = threadIdx.x & 31;
    float* p = seq + (size_t)tok * DD;
    const float* q = res + (size_t)tok * DD;
    float v[8];
    float sum = 0.f, sq = 0.f;
    #pragma unroll
    for (int i = 0; i < 2; i++) {
        float4 a = *(const float4*)&p[lane * 8 + i * 4];
        float4 c = *(const float4*)&q[lane * 8 + i * 4];
        float w0 = a.x + c.x, w1 = a.y + c.y, w2 = a.z + c.z, w3 = a.w + c.w;
        v[i * 4 + 0] = w0; v[i * 4 + 1] = w1; v[i * 4 + 2] = w2; v[i * 4 + 3] = w3;
        sum += w0 + w1 + w2 + w3;
        sq  += w0 * w0 + w1 * w1 + w2 * w2 + w3 * w3;
    }
    #pragma unroll
    for (int o = 16; o; o >>= 1) {
        sum += __shfl_xor_sync(0xFFFFFFFFu, sum, o);
        sq  += __shfl_xor_sync(0xFFFFFFFFu, sq, o);
    }
    float mean = sum * (1.f / DD);
    float var  = sq * (1.f / DD) - mean * mean;
    float inv  = rsqrtf(var + 1e-5f);
    #pragma unroll
    for (int i = 0; i < 8; i++) {
        int d = lane * 8 + i;
        float y = (v[i] - mean) * inv * g[d] + b[d];
        p[d] = y;
        size_t o = (size_t)tok * DD + d;
        __nv_bfloat16 a = __float2bfloat16(y);
        sh[o] = a;
        sl[o] = __float2bfloat16(y - __bfloat162float(a));
    }
}

__global__ void final_ln_kernel(const float* __restrict__ seq,
                                const float* __restrict__ g,
                                const float* __restrict__ b,
                                float* __restrict__ out)
{
    int n = blockIdx.x * 8 + (threadIdx.x >> 5);
    if (n >= NN) return;
    int lane = threadIdx.x & 31;
    const float* p = seq + (size_t)n * 3 * DD;
    float v[8];
    float sum = 0.f, sq = 0.f;
    #pragma unroll
    for (int i = 0; i < 2; i++) {
        float4 a = *(const float4*)&p[lane * 8 + i * 4];
        v[i * 4 + 0] = a.x; v[i * 4 + 1] = a.y; v[i * 4 + 2] = a.z; v[i * 4 + 3] = a.w;
        sum += a.x + a.y + a.z + a.w;
        sq  += a.x * a.x + a.y * a.y + a.z * a.z + a.w * a.w;
    }
    #pragma unroll
    for (int o = 16; o; o >>= 1) {
        sum += __shfl_xor_sync(0xFFFFFFFFu, sum, o);
        sq  += __shfl_xor_sync(0xFFFFFFFFu, sq, o);
    }
    float mean = sum * (1.f / DD);
    float var  = sq * (1.f / DD) - mean * mean;
    float inv  = rsqrtf(var + 1e-5f);
    #pragma unroll
    for (int i = 0; i < 8; i++) {
        int d = lane * 8 + i;
        out[(size_t)n * DD + d] = (v[i] - mean) * inv * g[d] + b[d];
    }
}

// ================= host side =================
template<bool BIAS, bool RELU, bool OUTF, bool OUTS>
static void run_gemm_tc(const __nv_bfloat16* Ah, const __nv_bfloat16* Al,
                        const __nv_bfloat16* Bh, const __nv_bfloat16* Bl,
                        const float* bias, float* Cf,
                        __nv_bfloat16* Ch, __nv_bfloat16* Cl,
                        int M, int Nn, int K)
{
    cudaFuncSetAttribute(gemm_mma_kernel<BIAS, RELU, OUTF, OUTS>,
                         cudaFuncAttributeMaxDynamicSharedMemorySize, GM_SMEM);
    dim3 grid(Nn / 128, (M + 127) / 128);
    gemm_mma_kernel<BIAS, RELU, OUTF, OUTS><<<grid, 256, GM_SMEM>>>(
        Ah, Al, Bh, Bl, bias, Cf, Ch, Cl, M, Nn, K);
}

static void run_split(const float* s, __nv_bfloat16* h, __nv_bfloat16* l, int n) {
    split_kernel<<<(n + 255) / 256, 256>>>(s, h, l, n);
}

extern "C" void kernel_launch(void* const* d_in, const int* in_sizes, int n_in,
                              void* d_out, int out_size)
{
    const float* x        = (const float*)d_in[0];
    const int*   ei       = (const int*)  d_in[1];
    const float* gat1_W   = (const float*)d_in[2];
    const float* gat1_b   = (const float*)d_in[3];
    const float* gat1_as  = (const float*)d_in[4];
    const float* gat1_ad  = (const float*)d_in[5];
    const float* gat2_W   = (const float*)d_in[6];
    const float* gat2_b   = (const float*)d_in[7];
    const float* gat2_as  = (const float*)d_in[8];
    const float* gat2_ad  = (const float*)d_in[9];
    const float* cls      = (const float*)d_in[10];
    const float* pos      = (const float*)d_in[11];
    const float* Wqkv     = (const float*)d_in[12];
    const float* bqkv     = (const float*)d_in[13];
    const float* Wo       = (const float*)d_in[14];
    const float* bo       = (const float*)d_in[15];
    const float* ln1_g    = (const float*)d_in[16];
    const float* ln1_b    = (const float*)d_in[17];
    const float* ln2_g    = (const float*)d_in[18];
    const float* ln2_b    = (const float*)d_in[19];
    const float* Wff1     = (const float*)d_in[20];
    const float* bff1     = (const float*)d_in[21];
    const float* Wff2     = (const float*)d_in[22];
    const float* bff2     = (const float*)d_in[23];
    const float* norm_g   = (const float*)d_in[24];
    const float* norm_b   = (const float*)d_in[25];
    float* out = (float*)d_out;

    float *h, *s, *t, *x1, *x2, *seq, *qkv, *tmp;
    cudaGetSymbolAddress((void**)&h,   g_h);
    cudaGetSymbolAddress((void**)&s,   g_s);
    cudaGetSymbolAddress((void**)&t,   g_t);
    cudaGetSymbolAddress((void**)&x1,  g_x1);
    cudaGetSymbolAddress((void**)&x2,  g_x2);
    cudaGetSymbolAddress((void**)&seq, g_seq);
    cudaGetSymbolAddress((void**)&qkv, g_qkv);
    cudaGetSymbolAddress((void**)&tmp, g_tmp);

    int *cnt, *slot, *rows, *csrc;
    cudaGetSymbolAddress((void**)&cnt,  g_cnt);
    cudaGetSymbolAddress((void**)&slot, g_slot);
    cudaGetSymbolAddress((void**)&rows, g_rows);
    cudaGetSymbolAddress((void**)&csrc, g_csrc);

    __nv_bfloat16 *xh, *xl, *x1h, *x1l, *seqh, *seql, *atth, *attl, *ffh, *ffl, *wbh, *wbl;
    cudaGetSymbolAddress((void**)&xh,   g_xh);
    cudaGetSymbolAddress((void**)&xl,   g_xl);
    cudaGetSymbolAddress((void**)&x1h,  g_x1h);
    cudaGetSymbolAddress((void**)&x1l,  g_x1l);
    cudaGetSymbolAddress((void**)&seqh, g_seqh);
    cudaGetSymbolAddress((void**)&seql, g_seql);
    cudaGetSymbolAddress((void**)&atth, g_atth);
    cudaGetSymbolAddress((void**)&attl, g_attl);
    cudaGetSymbolAddress((void**)&ffh,  g_ffh);
    cudaGetSymbolAddress((void**)&ffl,  g_ffl);
    cudaGetSymbolAddress((void**)&wbh,  g_wbh);
    cudaGetSymbolAddress((void**)&wbl,  g_wbl);

    // ---- CSR build (once; reused by both GAT layers) ----
    fill0i_kernel<<<(NN + 255) / 256, 256>>>(cnt, NN);
    hist_kernel<<<(ETOT + 255) / 256, 256>>>(ei, cnt, slot);
    scan_kernel<<<1, 1024>>>(cnt, rows);
    scatter_kernel<<<(ETOT + 255) / 256, 256>>>(ei, rows, slot, csrc);

    // ---- weight + input conversion to split bf16 ----
    run_split(x,      xh,              xl,              NN * DIN);
    run_split(gat1_W, wbh + WOFF_W1,   wbl + WOFF_W1,   DD * DIN);
    run_split(gat2_W, wbh + WOFF_W2,   wbl + WOFF_W2,   DD * DD);
    run_split(Wqkv,   wbh + WOFF_QKV,  wbl + WOFF_QKV,  2 * 3 * DD * DD);
    run_split(Wo,     wbh + WOFF_WO,   wbl + WOFF_WO,   2 * DD * DD);
    run_split(Wff1,   wbh + WOFF_F1,   wbl + WOFF_F1,   2 * 4 * DD * DD);
    run_split(Wff2,   wbh + WOFF_F2,   wbl + WOFF_F2,   2 * DD * 4 * DD);

    // ---- GAT layer 1 ----
    run_gemm_tc<false, false, true, false>(xh, xl, wbh + WOFF_W1, wbl + WOFF_W1,
                                           nullptr, h, nullptr, nullptr, NN, DD, DIN);
    dots_kernel<<<(NN + 7) / 8, 256>>>(h, gat1_as, gat1_ad, s, t);
    gather_kernel<true><<<(NN + 3) / 4, 256>>>(rows, csrc, s, t, h, gat1_b, x1, x1h, x1l);

    // ---- GAT layer 2 ----
    run_gemm_tc<false, false, true, false>(x1h, x1l, wbh + WOFF_W2, wbl + WOFF_W2,
                                           nullptr, h, nullptr, nullptr, NN, DD, DD);
    dots_kernel<<<(NN + 7) / 8, 256>>>(h, gat2_as, gat2_ad, s, t);
    gather_kernel<false><<<(NN + 3) / 4, 256>>>(rows, csrc, s, t, h, gat2_b, x2, nullptr, nullptr);

    // ---- build sequence ----
    build_seq_kernel<<<(unsigned)(((size_t)NTOK * DD + 255) / 256), 256>>>(x1, x2, cls, pos, seq, seqh, seql);

    // ---- transformer layers ----
    for (int l = 0; l < 2; l++) {
        const __nv_bfloat16* wqh = wbh + WOFF_QKV + (size_t)l * 3 * DD * DD;
        const __nv_bfloat16* wql = wbl + WOFF_QKV + (size_t)l * 3 * DD * DD;
        const __nv_bfloat16* woh = wbh + WOFF_WO  + (size_t)l * DD * DD;
        const __nv_bfloat16* wol = wbl + WOFF_WO  + (size_t)l * DD * DD;
        const __nv_bfloat16* wf1h = wbh + WOFF_F1 + (size_t)l * 4 * DD * DD;
        const __nv_bfloat16* wf1l = wbl + WOFF_F1 + (size_t)l * 4 * DD * DD;
        const __nv_bfloat16* wf2h = wbh + WOFF_F2 + (size_t)l * DD * 4 * DD;
        const __nv_bfloat16* wf2l = wbl + WOFF_F2 + (size_t)l * DD * 4 * DD;

        run_gemm_tc<true, false, true, false>(seqh, seql, wqh, wql, bqkv + (size_t)l * 3 * DD,
                                              qkv, nullptr, nullptr, NTOK, 3 * DD, DD);
        attn_kernel<<<(NN * NHEAD + 7) / 8, 256>>>(qkv, atth, attl);
        run_gemm_tc<true, false, true, false>(atth, attl, woh, wol, bo + (size_t)l * DD,
                                              tmp, nullptr, nullptr, NTOK, DD, DD);
        add_ln_kernel<<<(NTOK + 7) / 8, 256>>>(seq, tmp, ln1_g + l * DD, ln1_b + l * DD, seqh, seql);
        run_gemm_tc<true, true, false, true>(seqh, seql, wf1h, wf1l, bff1 + (size_t)l * 4 * DD,
                                             nullptr, ffh, ffl, NTOK, 4 * DD, DD);
        run_gemm_tc<true, false, true, false>(ffh, ffl, wf2h, wf2l, bff2 + (size_t)l * DD,
                                              tmp, nullptr, nullptr, NTOK, DD, 4 * DD);
        add_ln_kernel<<<(NTOK + 7) / 8, 256>>>(seq, tmp, ln2_g + l * DD, ln2_b + l * DD, seqh, seql);
    }

    // ---- final LN on CLS token ----
    final_ln_kernel<<<(NN + 7) / 8, 256>>>(seq, norm_g, norm_b, out);
}

// round 8
// speedup vs baseline: 1.5531x; 1.2304x over previous
#include <cuda_runtime.h>
#include <cuda_fp16.h>
#include <cstdint>
#include <cstdio>

// ---------------- problem constants ----------------
#define NN      50000
#define EE      320000
#define ETOT    (EE + NN)
#define DIN     128
#define DD      256
#define NTOK    (NN * 3)
#define NHEAD   4
#define DH      64
#define NEGS    0.2f

// ---------------- fp32 scratch ----------------
__device__ float g_h  [(size_t)NN * DD];
__device__ float g_s  [NN];
__device__ float g_t  [NN];
__device__ float g_x1 [(size_t)NN * DD];
__device__ float g_x2 [(size_t)NN * DD];
__device__ float g_seq[(size_t)NTOK * DD];
__device__ float g_qkv[(size_t)NTOK * 3 * DD];
__device__ float g_tmp[(size_t)NTOK * DD];

// ---------------- CSR graph scratch ----------------
__device__ int g_cnt [NN];
__device__ int g_slot[ETOT];
__device__ int g_rows[NN + 1];
__device__ int g_csrc[ETOT];

// ---------------- fp16 split operand buffers (A-side: hi+lo) ------------
__device__ __half g_xh [(size_t)NN * DIN];
__device__ __half g_xl [(size_t)NN * DIN];
__device__ __half g_x1h[(size_t)NN * DD];
__device__ __half g_x1l[(size_t)NN * DD];
__device__ __half g_seqh[(size_t)NTOK * DD];
__device__ __half g_seql[(size_t)NTOK * DD];
__device__ __half g_atth[(size_t)NTOK * DD];
__device__ __half g_attl[(size_t)NTOK * DD];
__device__ __half g_ffh[(size_t)NTOK * 4 * DD];
__device__ __half g_ffl[(size_t)NTOK * 4 * DD];
// weight pool (hi only — B side rounded to fp16)
#define WOFF_W1   0
#define WOFF_W2   32768
#define WOFF_QKV  98304
#define WOFF_WO   491520
#define WOFF_F1   622592
#define WOFF_F2   1146880
#define WTOT      1671168
__device__ __half g_wbh[WTOT];

// ================= warp-mma helpers =================
__device__ __forceinline__ uint32_t smem_u32(const void* p) {
    uint32_t a;
    asm("{ .reg .u64 t; cvta.to.shared.u64 t, %1; cvt.u32.u64 %0, t; }" : "=r"(a) : "l"(p));
    return a;
}

#define LDM4(r, addr) \
    asm volatile("ldmatrix.sync.aligned.m8n8.x4.shared.b16 {%0,%1,%2,%3}, [%4];" \
        : "=r"((r)[0]), "=r"((r)[1]), "=r"((r)[2]), "=r"((r)[3]) : "r"(addr))
#define MMA16816(c, a, b) \
    asm volatile("mma.sync.aligned.m16n8k16.row.col.f32.f16.f16.f32 " \
        "{%0,%1,%2,%3}, {%4,%5,%6,%7}, {%8,%9}, {%0,%1,%2,%3};" \
        : "+f"((c)[0]), "+f"((c)[1]), "+f"((c)[2]), "+f"((c)[3]) \
        : "r"((a)[0]), "r"((a)[1]), "r"((a)[2]), "r"((a)[3]), "r"((b)[0]), "r"((b)[1]))
#define CP_ASYNC(dst, src, sz) \
    asm volatile("cp.async.cg.shared.global [%0], [%1], 16, %2;" :: "r"(dst), "l"(src), "r"(sz))
#define CP_COMMIT() asm volatile("cp.async.commit_group;" ::: "memory")

// ================= 2-term fp16 GEMM via mma.sync =========================
// C[M,N] = (Ah+Al)[M,K] * Bh[N,K]^T.
// BM=128, BN=128, BK=32; 256 threads = 8 warps (2m x 4n), warp tile 64x32.
// 3-stage cp.async pipeline, 1 sync/iter, 2 CTAs/SM. Stage: Ah|Al|Bh.
#define RSB     80                     // row stride bytes in smem
#define MAT_SZ  10240                  // 128 rows * 80B
#define STG_SZ  30720                  // 3 matrices
#define GM_SMEM (3 * STG_SZ)           // 92160

template<bool BIAS, bool RELU, bool OUTF, bool OUTS>
__global__ __launch_bounds__(256, 2) void gemm_mma_kernel(
    const __half* __restrict__ Ah, const __half* __restrict__ Al,
    const __half* __restrict__ Bh,
    const float* __restrict__ bias,
    float* __restrict__ Cf, __half* __restrict__ Ch, __half* __restrict__ Cl,
    int M, int Nn, int K)
{
    extern __shared__ char smraw[];
    const uint32_t sb = smem_u32(smraw);
    const int tid = threadIdx.x, wid = tid >> 5, lane = tid & 31;
    const int wm = wid & 1, wn = wid >> 1;
    const int m0 = blockIdx.y * 128, n0 = blockIdx.x * 128;

    float acc[4][4][4];
    #pragma unroll
    for (int mt = 0; mt < 4; mt++)
        #pragma unroll
        for (int nt = 0; nt < 4; nt++)
            #pragma unroll
            for (int c = 0; c < 4; c++) acc[mt][nt][c] = 0.f;

    const int a_row  = (lane & 7) + ((lane >> 3) & 1) * 8;
    const int a_k    = (lane >> 4) * 8;
    const int b_row4 = (lane & 7) + ((lane >> 4) & 1) * 8;
    const int b_k4   = ((lane >> 3) & 1) * 8;

    const int T = K >> 5;

    auto load_stage = [&](int buf, int k0) {
        uint32_t base = sb + buf * STG_SZ;
        #pragma unroll
        for (int it = 0; it < 6; it++) {
            int i    = tid + it * 256;          // 0..1535
            int mat  = i >> 9;                  // 0=Ah, 1=Al, 2=Bh
            int rem  = i & 511;
            int row  = rem >> 2;
            int ch   = rem & 3;
            uint32_t dst = base + mat * MAT_SZ + row * RSB + ch * 16;
            const __half* src;
            int sz = 16;
            if (mat < 2) {
                src = mat ? Al : Ah;
                int gm = m0 + row;
                if (gm >= M) sz = 0;
                src += (size_t)gm * K + k0 + ch * 8;
            } else {
                src = Bh + (size_t)(n0 + row) * K + k0 + ch * 8;
            }
            CP_ASYNC(dst, src, sz);
        }
        CP_COMMIT();
    };

    auto compute = [&](int buf) {
        uint32_t base  = sb + buf * STG_SZ;
        uint32_t aB    = base + (wm * 64) * RSB;
        uint32_t bB    = base + 2 * MAT_SZ + (wn * 32) * RSB;
        #pragma unroll
        for (int ks = 0; ks < 32; ks += 16) {
            uint32_t bh[4][2];
            #pragma unroll
            for (int ntp = 0; ntp < 2; ntp++) {
                uint32_t bd = bB + (ntp * 16 + b_row4) * RSB + (ks + b_k4) * 2;
                uint32_t r4[4];
                LDM4(r4, bd);
                bh[2 * ntp][0] = r4[0]; bh[2 * ntp][1] = r4[1];
                bh[2 * ntp + 1][0] = r4[2]; bh[2 * ntp + 1][1] = r4[3];
            }
            #pragma unroll
            for (int mt = 0; mt < 4; mt++) {
                uint32_t ah4[4], al4[4];
                uint32_t ad = aB + (mt * 16 + a_row) * RSB + (ks + a_k) * 2;
                LDM4(ah4, ad);
                LDM4(al4, ad + MAT_SZ);
                #pragma unroll
                for (int nt = 0; nt < 4; nt++) MMA16816(acc[mt][nt], ah4, bh[nt]);
                #pragma unroll
                for (int nt = 0; nt < 4; nt++) MMA16816(acc[mt][nt], al4, bh[nt]);
            }
        }
    };

    load_stage(0, 0);
    if (T > 1) load_stage(1, 32);
    for (int t = 0; t < T; t++) {
        if (t + 1 < T) asm volatile("cp.async.wait_group 1;" ::: "memory");
        else           asm volatile("cp.async.wait_group 0;" ::: "memory");
        __syncthreads();
        if (t + 2 < T) load_stage((t + 2) % 3, (t + 2) << 5);
        compute(t % 3);
    }

    // ---------------- epilogue ----------------
    const int r0    = lane >> 2;
    const int cpair = (lane & 3) * 2;
    #pragma unroll
    for (int mt = 0; mt < 4; mt++) {
        int gm1 = m0 + wm * 64 + mt * 16 + r0;
        int gm2 = gm1 + 8;
        #pragma unroll
        for (int nt = 0; nt < 4; nt++) {
            int gn = n0 + wn * 32 + nt * 8 + cpair;
            float b0 = 0.f, b1 = 0.f;
            if (BIAS) { float2 bb = *(const float2*)&bias[gn]; b0 = bb.x; b1 = bb.y; }
            float v0 = acc[mt][nt][0] + b0, v1 = acc[mt][nt][1] + b1;
            float v2 = acc[mt][nt][2] + b0, v3 = acc[mt][nt][3] + b1;
            if (RELU) {
                v0 = fmaxf(v0, 0.f); v1 = fmaxf(v1, 0.f);
                v2 = fmaxf(v2, 0.f); v3 = fmaxf(v3, 0.f);
            }
            if (gm1 < M) {
                if (OUTF) *(float2*)&Cf[(size_t)gm1 * Nn + gn] = make_float2(v0, v1);
                if (OUTS) {
                    __half h0 = __float2half(v0), h1 = __float2half(v1);
                    __half2 hv; hv.x = h0; hv.y = h1;
                    __half2 lv;
                    lv.x = __float2half(v0 - __half2float(h0));
                    lv.y = __float2half(v1 - __half2float(h1));
                    *(__half2*)&Ch[(size_t)gm1 * Nn + gn] = hv;
                    *(__half2*)&Cl[(size_t)gm1 * Nn + gn] = lv;
                }
            }
            if (gm2 < M) {
                if (OUTF) *(float2*)&Cf[(size_t)gm2 * Nn + gn] = make_float2(v2, v3);
                if (OUTS) {
                    __half h2 = __float2half(v2), h3 = __float2half(v3);
                    __half2 hv; hv.x = h2; hv.y = h3;
                    __half2 lv;
                    lv.x = __float2half(v2 - __half2float(h2));
                    lv.y = __float2half(v3 - __half2float(h3));
                    *(__half2*)&Ch[(size_t)gm2 * Nn + gn] = hv;
                    *(__half2*)&Cl[(size_t)gm2 * Nn + gn] = lv;
                }
            }
        }
    }
}

// ================= CSR build kernels =================
__global__ void fill0i_kernel(int* __restrict__ p, int n) {
    int i = blockIdx.x * 256 + threadIdx.x;
    if (i < n) p[i] = 0;
}

__global__ void hist_kernel(const int* __restrict__ ei, int* __restrict__ cnt,
                            int* __restrict__ slot)
{
    int e = blockIdx.x * 256 + threadIdx.x;
    if (e >= ETOT) return;
    int dst = (e < EE) ? ei[EE + e] : e - EE;
    slot[e] = atomicAdd(&cnt[dst], 1);
}

__global__ void scan_kernel(const int* __restrict__ cnt, int* __restrict__ rows) {
    __shared__ int wsum[32];
    int tid = threadIdx.x;               // 1024 threads
    const int CH = (NN + 1023) / 1024;
    int beg = tid * CH;
    int ssum = 0;
    for (int i = 0; i < CH; i++) {
        int idx = beg + i;
        if (idx < NN) ssum += cnt[idx];
    }
    int lane = tid & 31, wid = tid >> 5;
    int v = ssum;
    #pragma unroll
    for (int o = 1; o < 32; o <<= 1) {
        int u = __shfl_up_sync(0xFFFFFFFFu, v, o);
        if (lane >= o) v += u;
    }
    if (lane == 31) wsum[wid] = v;
    __syncthreads();
    if (wid == 0) {
        int w = wsum[lane];
        #pragma unroll
        for (int o = 1; o < 32; o <<= 1) {
            int u = __shfl_up_sync(0xFFFFFFFFu, w, o);
            if (lane >= o) w += u;
        }
        wsum[lane] = w;
    }
    __syncthreads();
    int off = v - ssum + (wid ? wsum[wid - 1] : 0);
    for (int i = 0; i < CH; i++) {
        int idx = beg + i;
        if (idx < NN) { rows[idx] = off; off += cnt[idx]; }
    }
    if (tid == 0) rows[NN] = ETOT;
}

__global__ void scatter_kernel(const int* __restrict__ ei, const int* __restrict__ rows,
                               const int* __restrict__ slot, int* __restrict__ csrc)
{
    int e = blockIdx.x * 256 + threadIdx.x;
    if (e >= ETOT) return;
    int src, dst;
    if (e < EE) { src = ei[e]; dst = ei[EE + e]; }
    else        { src = dst = e - EE; }
    csrc[rows[dst] + slot[e]] = src;
}

// ================= GAT gather (CSR, no atomics) =================
template<bool OUTS>
__global__ void gather_kernel(const int* __restrict__ rows, const int* __restrict__ csrc,
                              const float* __restrict__ s, const float* __restrict__ t,
                              const float* __restrict__ h, const float* __restrict__ b,
                              float* __restrict__ outf,
                              __half* __restrict__ oh, __half* __restrict__ ol)
{
    int n = blockIdx.x * 4 + (threadIdx.x >> 6);
    if (n >= NN) return;
    int sub = threadIdx.x & 63;
    float tn = __ldg(&t[n]);
    int beg = __ldg(&rows[n]), end = __ldg(&rows[n + 1]);
    float a0 = 0.f, a1 = 0.f, a2 = 0.f, a3 = 0.f, den = 0.f;
    for (int i = beg; i < end; i++) {
        int src = __ldg(&csrc[i]);
        float x = __ldg(&s[src]) + tn;
        float ex = expf(x > 0.f ? x : NEGS * x);
        den += ex;
        float4 hv = *(const float4*)&h[(size_t)src * DD + sub * 4];
        a0 += ex * hv.x; a1 += ex * hv.y; a2 += ex * hv.z; a3 += ex * hv.w;
    }
    float inv = 1.f / den;
    float4 bb = *(const float4*)&b[sub * 4];
    float v0 = fmaxf(a0 * inv + bb.x, 0.f);
    float v1 = fmaxf(a1 * inv + bb.y, 0.f);
    float v2 = fmaxf(a2 * inv + bb.z, 0.f);
    float v3 = fmaxf(a3 * inv + bb.w, 0.f);
    size_t o = (size_t)n * DD + sub * 4;
    *(float4*)&outf[o] = make_float4(v0, v1, v2, v3);
    if (OUTS) {
        __half h0 = __float2half(v0), h1 = __float2half(v1);
        __half h2 = __float2half(v2), h3 = __float2half(v3);
        __half2 p0; p0.x = h0; p0.y = h1;
        __half2 p1; p1.x = h2; p1.y = h3;
        *(__half2*)&oh[o]     = p0;
        *(__half2*)&oh[o + 2] = p1;
        __half2 q0, q1;
        q0.x = __float2half(v0 - __half2float(h0));
        q0.y = __float2half(v1 - __half2float(h1));
        q1.x = __float2half(v2 - __half2float(h2));
        q1.y = __float2half(v3 - __half2float(h3));
        *(__half2*)&ol[o]     = q0;
        *(__half2*)&ol[o + 2] = q1;
    }
}

// ================= small kernels =================
__global__ void split_kernel(const float* __restrict__ s,
                             __half* __restrict__ h,
                             __half* __restrict__ l, int n)
{
    int i = blockIdx.x * 256 + threadIdx.x;
    if (i < n) {
        float v = s[i];
        __half a = __float2half(v);
        h[i] = a;
        l[i] = __float2half(v - __half2float(a));
    }
}

__global__ void round_kernel(const float* __restrict__ s, __half* __restrict__ h, int n)
{
    int i = blockIdx.x * 256 + threadIdx.x;
    if (i < n) h[i] = __float2half(s[i]);
}

__global__ void dots_kernel(const float* __restrict__ h,
                            const float* __restrict__ asrc,
                            const float* __restrict__ adst,
                            float* __restrict__ s, float* __restrict__ t)
{
    int n = blockIdx.x * 8 + (threadIdx.x >> 5);
    if (n >= NN) return;
    int lane = threadIdx.x & 31;
    const float* row = h + (size_t)n * DD;
    float ps = 0.f, pt = 0.f;
    #pragma unroll
    for (int i = 0; i < 8; i++) {
        int d = lane + 32 * i;
        float v = row[d];
        ps += v * asrc[d];
        pt += v * adst[d];
    }
    #pragma unroll
    for (int o = 16; o; o >>= 1) {
        ps += __shfl_xor_sync(0xFFFFFFFFu, ps, o);
        pt += __shfl_xor_sync(0xFFFFFFFFu, pt, o);
    }
    if (lane == 0) { s[n] = ps; t[n] = pt; }
}

__global__ void build_seq_kernel(const float* __restrict__ x1,
                                 const float* __restrict__ x2,
                                 const float* __restrict__ cls,
                                 const float* __restrict__ pos,
                                 float* __restrict__ seq,
                                 __half* __restrict__ sh,
                                 __half* __restrict__ sl)
{
    size_t i = (size_t)blockIdx.x * 256 + threadIdx.x;
    if (i >= (size_t)NTOK * DD) return;
    int d = (int)(i & 255);
    size_t tok = i >> 8;
    int which = (int)(tok % 3);
    size_t n = tok / 3;
    float v;
    if (which == 0)      v = cls[d];
    else if (which == 1) v = x1[n * DD + d];
    else                 v = x2[n * DD + d];
    v += pos[which * DD + d];
    seq[i] = v;
    __half a = __float2half(v);
    sh[i] = a;
    sl[i] = __float2half(v - __half2float(a));
}

__global__ void attn_kernel(const float* __restrict__ qkv,
                            __half* __restrict__ atth,
                            __half* __restrict__ attl)
{
    int w = blockIdx.x * 8 + (threadIdx.x >> 5);
    if (w >= NN * NHEAD) return;
    int lane = threadIdx.x & 31;
    int n = w >> 2, hh = w & 3;
    const float* base = qkv + (size_t)n * 3 * (3 * DD) + hh * DH + lane * 2;
    float2 q[3], k[3], v[3];
    #pragma unroll
    for (int i = 0; i < 3; i++) {
        q[i] = *(const float2*)(base + (size_t)i * (3 * DD));
        k[i] = *(const float2*)(base + (size_t)i * (3 * DD) + DD);
        v[i] = *(const float2*)(base + (size_t)i * (3 * DD) + 2 * DD);
    }
    float lg[3][3];
    #pragma unroll
    for (int i = 0; i < 3; i++)
        #pragma unroll
        for (int j = 0; j < 3; j++) {
            float p = q[i].x * k[j].x + q[i].y * k[j].y;
            #pragma unroll
            for (int o = 16; o; o >>= 1) p += __shfl_xor_sync(0xFFFFFFFFu, p, o);
            lg[i][j] = p * 0.125f;
        }
    #pragma unroll
    for (int i = 0; i < 3; i++) {
        float m  = fmaxf(lg[i][0], fmaxf(lg[i][1], lg[i][2]));
        float e0 = expf(lg[i][0] - m), e1 = expf(lg[i][1] - m), e2 = expf(lg[i][2] - m);
        float inv = 1.f / (e0 + e1 + e2);
        float ox = (e0 * v[0].x + e1 * v[1].x + e2 * v[2].x) * inv;
        float oy = (e0 * v[0].y + e1 * v[1].y + e2 * v[2].y) * inv;
        size_t o = ((size_t)(n * 3 + i)) * DD + hh * DH + lane * 2;
        __half hx = __float2half(ox);
        __half hy = __float2half(oy);
        __half2 hv; hv.x = hx; hv.y = hy;
        __half2 lv;
        lv.x = __float2half(ox - __half2float(hx));
        lv.y = __float2half(oy - __half2float(hy));
        *(__half2*)&atth[o] = hv;
        *(__half2*)&attl[o] = lv;
    }
}

__global__ void add_ln_kernel(float* __restrict__ seq,
                              const float* __restrict__ res,
                              const float* __restrict__ g,
                              const float* __restrict__ b,
                              __half* __restrict__ sh,
                              __half* __restrict__ sl)
{
    int tok = blockIdx.x * 8 + (threadIdx.x >> 5);
    if (tok >= NTOK) return;
    int lane = threadIdx.x & 31;
    float* p = seq + (size_t)tok * DD;
    const float* q = res + (size_t)tok * DD;
    float v[8];
    float sum = 0.f, sq = 0.f;
    #pragma unroll
    for (int i = 0; i < 2; i++) {
        float4 a = *(const float4*)&p[lane * 8 + i * 4];
        float4 c = *(const float4*)&q[lane * 8 + i * 4];
        float w0 = a.x + c.x, w1 = a.y + c.y, w2 = a.z + c.z, w3 = a.w + c.w;
        v[i * 4 + 0] = w0; v[i * 4 + 1] = w1; v[i * 4 + 2] = w2; v[i * 4 + 3] = w3;
        sum += w0 + w1 + w2 + w3;
        sq  += w0 * w0 + w1 * w1 + w2 * w2 + w3 * w3;
    }
    #pragma unroll
    for (int o = 16; o; o >>= 1) {
        sum += __shfl_xor_sync(0xFFFFFFFFu, sum, o);
        sq  += __shfl_xor_sync(0xFFFFFFFFu, sq, o);
    }
    float mean = sum * (1.f / DD);
    float var  = sq * (1.f / DD) - mean * mean;
    float inv  = rsqrtf(var + 1e-5f);
    #pragma unroll
    for (int i = 0; i < 8; i++) {
        int d = lane * 8 + i;
        float y = (v[i] - mean) * inv * g[d] + b[d];
        p[d] = y;
        size_t o = (size_t)tok * DD + d;
        __half a = __float2half(y);
        sh[o] = a;
        sl[o] = __float2half(y - __half2float(a));
    }
}

__global__ void final_ln_kernel(const float* __restrict__ seq,
                                const float* __restrict__ g,
                                const float* __restrict__ b,
                                float* __restrict__ out)
{
    int n = blockIdx.x * 8 + (threadIdx.x >> 5);
    if (n >= NN) return;
    int lane = threadIdx.x & 31;
    const float* p = seq + (size_t)n * 3 * DD;
    float v[8];
    float sum = 0.f, sq = 0.f;
    #pragma unroll
    for (int i = 0; i < 2; i++) {
        float4 a = *(const float4*)&p[lane * 8 + i * 4];
        v[i * 4 + 0] = a.x; v[i * 4 + 1] = a.y; v[i * 4 + 2] = a.z; v[i * 4 + 3] = a.w;
        sum += a.x + a.y + a.z + a.w;
        sq  += a.x * a.x + a.y * a.y + a.z * a.z + a.w * a.w;
    }
    #pragma unroll
    for (int o = 16; o; o >>= 1) {
        sum += __shfl_xor_sync(0xFFFFFFFFu, sum, o);
        sq  += __shfl_xor_sync(0xFFFFFFFFu, sq, o);
    }
    float mean = sum * (1.f / DD);
    float var  = sq * (1.f / DD) - mean * mean;
    float inv  = rsqrtf(var + 1e-5f);
    #pragma unroll
    for (int i = 0; i < 8; i++) {
        int d = lane * 8 + i;
        out[(size_t)n * DD + d] = (v[i] - mean) * inv * g[d] + b[d];
    }
}

// ================= host side =================
template<bool BIAS, bool RELU, bool OUTF, bool OUTS>
static void run_gemm_tc(const __half* Ah, const __half* Al, const __half* Bh,
                        const float* bias, float* Cf,
                        __half* Ch, __half* Cl,
                        int M, int Nn, int K)
{
    cudaFuncSetAttribute(gemm_mma_kernel<BIAS, RELU, OUTF, OUTS>,
                         cudaFuncAttributeMaxDynamicSharedMemorySize, GM_SMEM);
    dim3 grid(Nn / 128, (M + 127) / 128);
    gemm_mma_kernel<BIAS, RELU, OUTF, OUTS><<<grid, 256, GM_SMEM>>>(
        Ah, Al, Bh, bias, Cf, Ch, Cl, M, Nn, K);
}

extern "C" void kernel_launch(void* const* d_in, const int* in_sizes, int n_in,
                              void* d_out, int out_size)
{
    const float* x        = (const float*)d_in[0];
    const int*   ei       = (const int*)  d_in[1];
    const float* gat1_W   = (const float*)d_in[2];
    const float* gat1_b   = (const float*)d_in[3];
    const float* gat1_as  = (const float*)d_in[4];
    const float* gat1_ad  = (const float*)d_in[5];
    const float* gat2_W   = (const float*)d_in[6];
    const float* gat2_b   = (const float*)d_in[7];
    const float* gat2_as  = (const float*)d_in[8];
    const float* gat2_ad  = (const float*)d_in[9];
    const float* cls      = (const float*)d_in[10];
    const float* pos      = (const float*)d_in[11];
    const float* Wqkv     = (const float*)d_in[12];
    const float* bqkv     = (const float*)d_in[13];
    const float* Wo       = (const float*)d_in[14];
    const float* bo       = (const float*)d_in[15];
    const float* ln1_g    = (const float*)d_in[16];
    const float* ln1_b    = (const float*)d_in[17];
    const float* ln2_g    = (const float*)d_in[18];
    const float* ln2_b    = (const float*)d_in[19];
    const float* Wff1     = (const float*)d_in[20];
    const float* bff1     = (const float*)d_in[21];
    const float* Wff2     = (const float*)d_in[22];
    const float* bff2     = (const float*)d_in[23];
    const float* norm_g   = (const float*)d_in[24];
    const float* norm_b   = (const float*)d_in[25];
    float* out = (float*)d_out;

    float *h, *s, *t, *x1, *x2, *seq, *qkv, *tmp;
    cudaGetSymbolAddress((void**)&h,   g_h);
    cudaGetSymbolAddress((void**)&s,   g_s);
    cudaGetSymbolAddress((void**)&t,   g_t);
    cudaGetSymbolAddress((void**)&x1,  g_x1);
    cudaGetSymbolAddress((void**)&x2,  g_x2);
    cudaGetSymbolAddress((void**)&seq, g_seq);
    cudaGetSymbolAddress((void**)&qkv, g_qkv);
    cudaGetSymbolAddress((void**)&tmp, g_tmp);

    int *cnt, *slot, *rows, *csrc;
    cudaGetSymbolAddress((void**)&cnt,  g_cnt);
    cudaGetSymbolAddress((void**)&slot, g_slot);
    cudaGetSymbolAddress((void**)&rows, g_rows);
    cudaGetSymbolAddress((void**)&csrc, g_csrc);

    __half *xh, *xl, *x1h, *x1l, *seqh, *seql, *atth, *attl, *ffh, *ffl, *wbh;
    cudaGetSymbolAddress((void**)&xh,   g_xh);
    cudaGetSymbolAddress((void**)&xl,   g_xl);
    cudaGetSymbolAddress((void**)&x1h,  g_x1h);
    cudaGetSymbolAddress((void**)&x1l,  g_x1l);
    cudaGetSymbolAddress((void**)&seqh, g_seqh);
    cudaGetSymbolAddress((void**)&seql, g_seql);
    cudaGetSymbolAddress((void**)&atth, g_atth);
    cudaGetSymbolAddress((void**)&attl, g_attl);
    cudaGetSymbolAddress((void**)&ffh,  g_ffh);
    cudaGetSymbolAddress((void**)&ffl,  g_ffl);
    cudaGetSymbolAddress((void**)&wbh,  g_wbh);

    // ---- CSR build (once; reused by both GAT layers) ----
    fill0i_kernel<<<(NN + 255) / 256, 256>>>(cnt, NN);
    hist_kernel<<<(ETOT + 255) / 256, 256>>>(ei, cnt, slot);
    scan_kernel<<<1, 1024>>>(cnt, rows);
    scatter_kernel<<<(ETOT + 255) / 256, 256>>>(ei, rows, slot, csrc);

    // ---- conversions ----
    split_kernel<<<(NN * DIN + 255) / 256, 256>>>(x, xh, xl, NN * DIN);
    round_kernel<<<(DD * DIN + 255) / 256, 256>>>(gat1_W, wbh + WOFF_W1, DD * DIN);
    round_kernel<<<(DD * DD + 255) / 256, 256>>>(gat2_W, wbh + WOFF_W2, DD * DD);
    round_kernel<<<(2 * 3 * DD * DD + 255) / 256, 256>>>(Wqkv, wbh + WOFF_QKV, 2 * 3 * DD * DD);
    round_kernel<<<(2 * DD * DD + 255) / 256, 256>>>(Wo, wbh + WOFF_WO, 2 * DD * DD);
    round_kernel<<<(2 * 4 * DD * DD + 255) / 256, 256>>>(Wff1, wbh + WOFF_F1, 2 * 4 * DD * DD);
    round_kernel<<<(2 * DD * 4 * DD + 255) / 256, 256>>>(Wff2, wbh + WOFF_F2, 2 * DD * 4 * DD);

    // ---- GAT layer 1 ----
    run_gemm_tc<false, false, true, false>(xh, xl, wbh + WOFF_W1,
                                           nullptr, h, nullptr, nullptr, NN, DD, DIN);
    dots_kernel<<<(NN + 7) / 8, 256>>>(h, gat1_as, gat1_ad, s, t);
    gather_kernel<true><<<(NN + 3) / 4, 256>>>(rows, csrc, s, t, h, gat1_b, x1, x1h, x1l);

    // ---- GAT layer 2 ----
    run_gemm_tc<false, false, true, false>(x1h, x1l, wbh + WOFF_W2,
                                           nullptr, h, nullptr, nullptr, NN, DD, DD);
    dots_kernel<<<(NN + 7) / 8, 256>>>(h, gat2_as, gat2_ad, s, t);
    gather_kernel<false><<<(NN + 3) / 4, 256>>>(rows, csrc, s, t, h, gat2_b, x2, nullptr, nullptr);

    // ---- build sequence ----
    build_seq_kernel<<<(unsigned)(((size_t)NTOK * DD + 255) / 256), 256>>>(x1, x2, cls, pos, seq, seqh, seql);

    // ---- transformer layers ----
    for (int l = 0; l < 2; l++) {
        const __half* wqh  = wbh + WOFF_QKV + (size_t)l * 3 * DD * DD;
        const __half* woh  = wbh + WOFF_WO  + (size_t)l * DD * DD;
        const __half* wf1h = wbh + WOFF_F1  + (size_t)l * 4 * DD * DD;
        const __half* wf2h = wbh + WOFF_F2  + (size_t)l * DD * 4 * DD;

        run_gemm_tc<true, false, true, false>(seqh, seql, wqh, bqkv + (size_t)l * 3 * DD,
                                              qkv, nullptr, nullptr, NTOK, 3 * DD, DD);
        attn_kernel<<<(NN * NHEAD + 7) / 8, 256>>>(qkv, atth, attl);
        run_gemm_tc<true, false, true, false>(atth, attl, woh, bo + (size_t)l * DD,
                                              tmp, nullptr, nullptr, NTOK, DD, DD);
        add_ln_kernel<<<(NTOK + 7) / 8, 256>>>(seq, tmp, ln1_g + l * DD, ln1_b + l * DD, seqh, seql);
        run_gemm_tc<true, true, false, true>(seqh, seql, wf1h, bff1 + (size_t)l * 4 * DD,
                                             nullptr, ffh, ffl, NTOK, 4 * DD, DD);
        run_gemm_tc<true, false, true, false>(ffh, ffl, wf2h, bff2 + (size_t)l * DD,
                                              tmp, nullptr, nullptr, NTOK, DD, 4 * DD);
        add_ln_kernel<<<(NTOK + 7) / 8, 256>>>(seq, tmp, ln2_g + l * DD, ln2_b + l * DD, seqh, seql);
    }

    // ---- final LN on CLS token ----
    final_ln_kernel<<<(NN + 7) / 8, 256>>>(seq, norm_g, norm_b, out);
}

// round 9
// speedup vs baseline: 1.8376x; 1.1832x over previous
#include <cuda_runtime.h>
#include <cuda_fp16.h>
#include <cstdint>
#include <cstdio>

// ---------------- problem constants ----------------
#define NN      50000
#define EE      320000
#define ETOT    (EE + NN)
#define DIN     128
#define DD      256
#define NTOK    (NN * 3)
#define NHEAD   4
#define DH      64
#define NEGS    0.2f

// ---------------- fp32 scratch ----------------
__device__ float g_h  [(size_t)NN * DD];
__device__ float g_s  [NN];
__device__ float g_t  [NN];
__device__ float g_tmp[(size_t)NTOK * DD];

// ---------------- CSR graph scratch ----------------
__device__ int g_cnt [NN];
__device__ int g_slot[ETOT];
__device__ int g_rows[NN + 1];
__device__ int g_csrc[ETOT];

// ---------------- fp16 hi/lo activation buffers ----------------
__device__ __half g_xh [(size_t)NN * DIN];
__device__ __half g_xl [(size_t)NN * DIN];
__device__ __half g_x1h[(size_t)NN * DD];
__device__ __half g_x1l[(size_t)NN * DD];
__device__ __half g_x2h[(size_t)NN * DD];
__device__ __half g_x2l[(size_t)NN * DD];
__device__ __half g_seqh[(size_t)NTOK * DD];
__device__ __half g_seql[(size_t)NTOK * DD];
__device__ __half g_qkvh[(size_t)NTOK * 3 * DD];
__device__ __half g_qkvl[(size_t)NTOK * 3 * DD];
__device__ __half g_atth[(size_t)NTOK * DD];
__device__ __half g_attl[(size_t)NTOK * DD];
__device__ __half g_ffh[(size_t)NTOK * 4 * DD];
__device__ __half g_ffl[(size_t)NTOK * 4 * DD];
// weight pool (hi only — B side rounded to fp16)
#define WOFF_W1   0
#define WOFF_W2   32768
#define WOFF_QKV  98304
#define WOFF_WO   491520
#define WOFF_F1   622592
#define WOFF_F2   1146880
#define WTOT      1671168
__device__ __half g_wbh[WTOT];

// ================= warp-mma helpers =================
__device__ __forceinline__ uint32_t smem_u32(const void* p) {
    uint32_t a;
    asm("{ .reg .u64 t; cvta.to.shared.u64 t, %1; cvt.u32.u64 %0, t; }" : "=r"(a) : "l"(p));
    return a;
}

#define LDM4(r, addr) \
    asm volatile("ldmatrix.sync.aligned.m8n8.x4.shared.b16 {%0,%1,%2,%3}, [%4];" \
        : "=r"((r)[0]), "=r"((r)[1]), "=r"((r)[2]), "=r"((r)[3]) : "r"(addr))
#define MMA16816(c, a, b) \
    asm volatile("mma.sync.aligned.m16n8k16.row.col.f32.f16.f16.f32 " \
        "{%0,%1,%2,%3}, {%4,%5,%6,%7}, {%8,%9}, {%0,%1,%2,%3};" \
        : "+f"((c)[0]), "+f"((c)[1]), "+f"((c)[2]), "+f"((c)[3]) \
        : "r"((a)[0]), "r"((a)[1]), "r"((a)[2]), "r"((a)[3]), "r"((b)[0]), "r"((b)[1]))
#define CP_ASYNC(dst, src, sz) \
    asm volatile("cp.async.cg.shared.global [%0], [%1], 16, %2;" :: "r"(dst), "l"(src), "r"(sz))
#define CP_COMMIT() asm volatile("cp.async.commit_group;" ::: "memory")

__device__ __forceinline__ void split_store(__half* hp, __half* lp, float a, float b) {
    __half h0 = __float2half(a), h1 = __float2half(b);
    __half2 hv; hv.x = h0; hv.y = h1;
    __half2 lv;
    lv.x = __float2half(a - __half2float(h0));
    lv.y = __float2half(b - __half2float(h1));
    *(__half2*)hp = hv;
    *(__half2*)lp = lv;
}

// ================= 2-term fp16 GEMM via mma.sync =========================
// C[M,N] = (Ah+Al)[M,K] * Bh[N,K]^T.
// BM=128, BN=128, BK=32; 256 threads = 8 warps (2m x 4n), warp tile 64x32.
// 3-stage cp.async pipeline, 1 sync/iter, 2 CTAs/SM.
#define RSB     80
#define MAT_SZ  10240
#define STG_SZ  30720
#define GM_SMEM (3 * STG_SZ)

template<bool BIAS, bool RELU, bool OUTF, bool OUTS>
__global__ __launch_bounds__(256, 2) void gemm_mma_kernel(
    const __half* __restrict__ Ah, const __half* __restrict__ Al,
    const __half* __restrict__ Bh,
    const float* __restrict__ bias,
    float* __restrict__ Cf, __half* __restrict__ Ch, __half* __restrict__ Cl,
    int M, int Nn, int K)
{
    extern __shared__ char smraw[];
    const uint32_t sb = smem_u32(smraw);
    const int tid = threadIdx.x, wid = tid >> 5, lane = tid & 31;
    const int wm = wid & 1, wn = wid >> 1;
    const int m0 = blockIdx.y * 128, n0 = blockIdx.x * 128;

    float acc[4][4][4];
    #pragma unroll
    for (int mt = 0; mt < 4; mt++)
        #pragma unroll
        for (int nt = 0; nt < 4; nt++)
            #pragma unroll
            for (int c = 0; c < 4; c++) acc[mt][nt][c] = 0.f;

    const int a_row  = (lane & 7) + ((lane >> 3) & 1) * 8;
    const int a_k    = (lane >> 4) * 8;
    const int b_row4 = (lane & 7) + ((lane >> 4) & 1) * 8;
    const int b_k4   = ((lane >> 3) & 1) * 8;

    const int T = K >> 5;

    auto load_stage = [&](int buf, int k0) {
        uint32_t base = sb + buf * STG_SZ;
        #pragma unroll
        for (int it = 0; it < 6; it++) {
            int i    = tid + it * 256;
            int mat  = i >> 9;
            int rem  = i & 511;
            int row  = rem >> 2;
            int ch   = rem & 3;
            uint32_t dst = base + mat * MAT_SZ + row * RSB + ch * 16;
            const __half* src;
            int sz = 16;
            if (mat < 2) {
                src = mat ? Al : Ah;
                int gm = m0 + row;
                if (gm >= M) sz = 0;
                src += (size_t)gm * K + k0 + ch * 8;
            } else {
                src = Bh + (size_t)(n0 + row) * K + k0 + ch * 8;
            }
            CP_ASYNC(dst, src, sz);
        }
        CP_COMMIT();
    };

    auto compute = [&](int buf) {
        uint32_t base  = sb + buf * STG_SZ;
        uint32_t aB    = base + (wm * 64) * RSB;
        uint32_t bB    = base + 2 * MAT_SZ + (wn * 32) * RSB;
        #pragma unroll
        for (int ks = 0; ks < 32; ks += 16) {
            uint32_t bh[4][2];
            #pragma unroll
            for (int ntp = 0; ntp < 2; ntp++) {
                uint32_t bd = bB + (ntp * 16 + b_row4) * RSB + (ks + b_k4) * 2;
                uint32_t r4[4];
                LDM4(r4, bd);
                bh[2 * ntp][0] = r4[0]; bh[2 * ntp][1] = r4[1];
                bh[2 * ntp + 1][0] = r4[2]; bh[2 * ntp + 1][1] = r4[3];
            }
            #pragma unroll
            for (int mt = 0; mt < 4; mt++) {
                uint32_t ah4[4], al4[4];
                uint32_t ad = aB + (mt * 16 + a_row) * RSB + (ks + a_k) * 2;
                LDM4(ah4, ad);
                LDM4(al4, ad + MAT_SZ);
                #pragma unroll
                for (int nt = 0; nt < 4; nt++) MMA16816(acc[mt][nt], ah4, bh[nt]);
                #pragma unroll
                for (int nt = 0; nt < 4; nt++) MMA16816(acc[mt][nt], al4, bh[nt]);
            }
        }
    };

    load_stage(0, 0);
    if (T > 1) load_stage(1, 32);
    for (int t = 0; t < T; t++) {
        if (t + 1 < T) asm volatile("cp.async.wait_group 1;" ::: "memory");
        else           asm volatile("cp.async.wait_group 0;" ::: "memory");
        __syncthreads();
        if (t + 2 < T) load_stage((t + 2) % 3, (t + 2) << 5);
        compute(t % 3);
    }

    // ---------------- epilogue ----------------
    const int r0    = lane >> 2;
    const int cpair = (lane & 3) * 2;
    #pragma unroll
    for (int mt = 0; mt < 4; mt++) {
        int gm1 = m0 + wm * 64 + mt * 16 + r0;
        int gm2 = gm1 + 8;
        #pragma unroll
        for (int nt = 0; nt < 4; nt++) {
            int gn = n0 + wn * 32 + nt * 8 + cpair;
            float b0 = 0.f, b1 = 0.f;
            if (BIAS) { float2 bb = *(const float2*)&bias[gn]; b0 = bb.x; b1 = bb.y; }
            float v0 = acc[mt][nt][0] + b0, v1 = acc[mt][nt][1] + b1;
            float v2 = acc[mt][nt][2] + b0, v3 = acc[mt][nt][3] + b1;
            if (RELU) {
                v0 = fmaxf(v0, 0.f); v1 = fmaxf(v1, 0.f);
                v2 = fmaxf(v2, 0.f); v3 = fmaxf(v3, 0.f);
            }
            if (gm1 < M) {
                if (OUTF) *(float2*)&Cf[(size_t)gm1 * Nn + gn] = make_float2(v0, v1);
                if (OUTS) split_store(&Ch[(size_t)gm1 * Nn + gn], &Cl[(size_t)gm1 * Nn + gn], v0, v1);
            }
            if (gm2 < M) {
                if (OUTF) *(float2*)&Cf[(size_t)gm2 * Nn + gn] = make_float2(v2, v3);
                if (OUTS) split_store(&Ch[(size_t)gm2 * Nn + gn], &Cl[(size_t)gm2 * Nn + gn], v2, v3);
            }
        }
    }
}

// ================= CSR build kernels =================
__global__ void fill0i_kernel(int* __restrict__ p, int n) {
    int i = blockIdx.x * 256 + threadIdx.x;
    if (i < n) p[i] = 0;
}

__global__ void hist_kernel(const int* __restrict__ ei, int* __restrict__ cnt,
                            int* __restrict__ slot)
{
    int e = blockIdx.x * 256 + threadIdx.x;
    if (e >= ETOT) return;
    int dst = (e < EE) ? ei[EE + e] : e - EE;
    slot[e] = atomicAdd(&cnt[dst], 1);
}

__global__ void scan_kernel(const int* __restrict__ cnt, int* __restrict__ rows) {
    __shared__ int wsum[32];
    int tid = threadIdx.x;
    const int CH = (NN + 1023) / 1024;
    int beg = tid * CH;
    int ssum = 0;
    for (int i = 0; i < CH; i++) {
        int idx = beg + i;
        if (idx < NN) ssum += cnt[idx];
    }
    int lane = tid & 31, wid = tid >> 5;
    int v = ssum;
    #pragma unroll
    for (int o = 1; o < 32; o <<= 1) {
        int u = __shfl_up_sync(0xFFFFFFFFu, v, o);
        if (lane >= o) v += u;
    }
    if (lane == 31) wsum[wid] = v;
    __syncthreads();
    if (wid == 0) {
        int w = wsum[lane];
        #pragma unroll
        for (int o = 1; o < 32; o <<= 1) {
            int u = __shfl_up_sync(0xFFFFFFFFu, w, o);
            if (lane >= o) w += u;
        }
        wsum[lane] = w;
    }
    __syncthreads();
    int off = v - ssum + (wid ? wsum[wid - 1] : 0);
    for (int i = 0; i < CH; i++) {
        int idx = beg + i;
        if (idx < NN) { rows[idx] = off; off += cnt[idx]; }
    }
    if (tid == 0) rows[NN] = ETOT;
}

__global__ void scatter_kernel(const int* __restrict__ ei, const int* __restrict__ rows,
                               const int* __restrict__ slot, int* __restrict__ csrc)
{
    int e = blockIdx.x * 256 + threadIdx.x;
    if (e >= ETOT) return;
    int src, dst;
    if (e < EE) { src = ei[e]; dst = ei[EE + e]; }
    else        { src = dst = e - EE; }
    csrc[rows[dst] + slot[e]] = src;
}

// ================= GAT gather (CSR, no atomics) =================
// Writes only hi/lo fp16 pair (fp32 value = hi + lo).
__global__ void gather_kernel(const int* __restrict__ rows, const int* __restrict__ csrc,
                              const float* __restrict__ s, const float* __restrict__ t,
                              const float* __restrict__ h, const float* __restrict__ b,
                              __half* __restrict__ oh, __half* __restrict__ ol)
{
    int n = blockIdx.x * 4 + (threadIdx.x >> 6);
    if (n >= NN) return;
    int sub = threadIdx.x & 63;
    float tn = __ldg(&t[n]);
    int beg = __ldg(&rows[n]), end = __ldg(&rows[n + 1]);
    float a0 = 0.f, a1 = 0.f, a2 = 0.f, a3 = 0.f, den = 0.f;
    for (int i = beg; i < end; i++) {
        int src = __ldg(&csrc[i]);
        float x = __ldg(&s[src]) + tn;
        float ex = expf(x > 0.f ? x : NEGS * x);
        den += ex;
        float4 hv = *(const float4*)&h[(size_t)src * DD + sub * 4];
        a0 += ex * hv.x; a1 += ex * hv.y; a2 += ex * hv.z; a3 += ex * hv.w;
    }
    float inv = 1.f / den;
    float4 bb = *(const float4*)&b[sub * 4];
    float v0 = fmaxf(a0 * inv + bb.x, 0.f);
    float v1 = fmaxf(a1 * inv + bb.y, 0.f);
    float v2 = fmaxf(a2 * inv + bb.z, 0.f);
    float v3 = fmaxf(a3 * inv + bb.w, 0.f);
    size_t o = (size_t)n * DD + sub * 4;
    split_store(&oh[o],     &ol[o],     v0, v1);
    split_store(&oh[o + 2], &ol[o + 2], v2, v3);
}

// ================= small kernels =================
__global__ void split_kernel(const float* __restrict__ s,
                             __half* __restrict__ h,
                             __half* __restrict__ l, int n)
{
    int i = blockIdx.x * 256 + threadIdx.x;
    if (i < n) {
        float v = s[i];
        __half a = __float2half(v);
        h[i] = a;
        l[i] = __float2half(v - __half2float(a));
    }
}

__global__ void round_kernel(const float* __restrict__ s, __half* __restrict__ h, int n)
{
    int i = blockIdx.x * 256 + threadIdx.x;
    if (i < n) h[i] = __float2half(s[i]);
}

__global__ void dots_kernel(const float* __restrict__ h,
                            const float* __restrict__ asrc,
                            const float* __restrict__ adst,
                            float* __restrict__ s, float* __restrict__ t)
{
    int n = blockIdx.x * 8 + (threadIdx.x >> 5);
    if (n >= NN) return;
    int lane = threadIdx.x & 31;
    const float* row = h + (size_t)n * DD;
    float ps = 0.f, pt = 0.f;
    #pragma unroll
    for (int i = 0; i < 8; i++) {
        int d = lane + 32 * i;
        float v = row[d];
        ps += v * asrc[d];
        pt += v * adst[d];
    }
    #pragma unroll
    for (int o = 16; o; o >>= 1) {
        ps += __shfl_xor_sync(0xFFFFFFFFu, ps, o);
        pt += __shfl_xor_sync(0xFFFFFFFFu, pt, o);
    }
    if (lane == 0) { s[n] = ps; t[n] = pt; }
}

// build seq (hi/lo only) from x1,x2 hi/lo pairs + cls + pos
__global__ void build_seq_kernel(const __half* __restrict__ x1h, const __half* __restrict__ x1l,
                                 const __half* __restrict__ x2h, const __half* __restrict__ x2l,
                                 const float* __restrict__ cls,
                                 const float* __restrict__ pos,
                                 __half* __restrict__ sh,
                                 __half* __restrict__ sl)
{
    size_t i = (size_t)blockIdx.x * 256 + threadIdx.x;
    if (i >= (size_t)NTOK * DD) return;
    int d = (int)(i & 255);
    size_t tok = i >> 8;
    int which = (int)(tok % 3);
    size_t n = tok / 3;
    float v;
    if (which == 0)      v = cls[d];
    else if (which == 1) v = __half2float(x1h[n * DD + d]) + __half2float(x1l[n * DD + d]);
    else                 v = __half2float(x2h[n * DD + d]) + __half2float(x2l[n * DD + d]);
    v += pos[which * DD + d];
    __half a = __float2half(v);
    sh[i] = a;
    sl[i] = __float2half(v - __half2float(a));
}

// attention from hi/lo fp16 qkv
__global__ void attn_kernel(const __half* __restrict__ qh, const __half* __restrict__ ql,
                            __half* __restrict__ atth, __half* __restrict__ attl)
{
    int w = blockIdx.x * 8 + (threadIdx.x >> 5);
    if (w >= NN * NHEAD) return;
    int lane = threadIdx.x & 31;
    int n = w >> 2, hh = w & 3;
    size_t base = (size_t)n * 3 * (3 * DD) + hh * DH + lane * 2;
    float2 q[3], k[3], v[3];
    #pragma unroll
    for (int i = 0; i < 3; i++) {
        size_t o = base + (size_t)i * (3 * DD);
        __half2 ah, al;
        ah = *(const __half2*)(qh + o);           al = *(const __half2*)(ql + o);
        q[i].x = __half2float(ah.x) + __half2float(al.x);
        q[i].y = __half2float(ah.y) + __half2float(al.y);
        ah = *(const __half2*)(qh + o + DD);      al = *(const __half2*)(ql + o + DD);
        k[i].x = __half2float(ah.x) + __half2float(al.x);
        k[i].y = __half2float(ah.y) + __half2float(al.y);
        ah = *(const __half2*)(qh + o + 2 * DD);  al = *(const __half2*)(ql + o + 2 * DD);
        v[i].x = __half2float(ah.x) + __half2float(al.x);
        v[i].y = __half2float(ah.y) + __half2float(al.y);
    }
    float lg[3][3];
    #pragma unroll
    for (int i = 0; i < 3; i++)
        #pragma unroll
        for (int j = 0; j < 3; j++) {
            float p = q[i].x * k[j].x + q[i].y * k[j].y;
            #pragma unroll
            for (int o = 16; o; o >>= 1) p += __shfl_xor_sync(0xFFFFFFFFu, p, o);
            lg[i][j] = p * 0.125f;
        }
    #pragma unroll
    for (int i = 0; i < 3; i++) {
        float m  = fmaxf(lg[i][0], fmaxf(lg[i][1], lg[i][2]));
        float e0 = expf(lg[i][0] - m), e1 = expf(lg[i][1] - m), e2 = expf(lg[i][2] - m);
        float inv = 1.f / (e0 + e1 + e2);
        float ox = (e0 * v[0].x + e1 * v[1].x + e2 * v[2].x) * inv;
        float oy = (e0 * v[0].y + e1 * v[1].y + e2 * v[2].y) * inv;
        size_t o = ((size_t)(n * 3 + i)) * DD + hh * DH + lane * 2;
        split_store(&atth[o], &attl[o], ox, oy);
    }
}

// residual + LN, in-place on (sh, sl)
__global__ void add_ln_kernel(__half* __restrict__ sh, __half* __restrict__ sl,
                              const float* __restrict__ res,
                              const float* __restrict__ g,
                              const float* __restrict__ b)
{
    int tok = blockIdx.x * 8 + (threadIdx.x >> 5);
    if (tok >= NTOK) return;
    int lane = threadIdx.x & 31;
    __half* ph = sh + (size_t)tok * DD;
    __half* pl = sl + (size_t)tok * DD;
    const float* q = res + (size_t)tok * DD;
    float v[8];
    float sum = 0.f, sq = 0.f;
    #pragma unroll
    for (int i = 0; i < 4; i++) {
        __half2 ah = *(const __half2*)&ph[lane * 8 + i * 2];
        __half2 al = *(const __half2*)&pl[lane * 8 + i * 2];
        float2 c = *(const float2*)&q[lane * 8 + i * 2];
        float w0 = __half2float(ah.x) + __half2float(al.x) + c.x;
        float w1 = __half2float(ah.y) + __half2float(al.y) + c.y;
        v[i * 2 + 0] = w0; v[i * 2 + 1] = w1;
        sum += w0 + w1;
        sq  += w0 * w0 + w1 * w1;
    }
    #pragma unroll
    for (int o = 16; o; o >>= 1) {
        sum += __shfl_xor_sync(0xFFFFFFFFu, sum, o);
        sq  += __shfl_xor_sync(0xFFFFFFFFu, sq, o);
    }
    float mean = sum * (1.f / DD);
    float var  = sq * (1.f / DD) - mean * mean;
    float inv  = rsqrtf(var + 1e-5f);
    #pragma unroll
    for (int i = 0; i < 4; i++) {
        int d = lane * 8 + i * 2;
        float y0 = (v[i * 2 + 0] - mean) * inv * g[d + 0] + b[d + 0];
        float y1 = (v[i * 2 + 1] - mean) * inv * g[d + 1] + b[d + 1];
        split_store(&ph[d], &pl[d], y0, y1);
    }
}

__global__ void final_ln_kernel(const __half* __restrict__ sh, const __half* __restrict__ sl,
                                const float* __restrict__ g,
                                const float* __restrict__ b,
                                float* __restrict__ out)
{
    int n = blockIdx.x * 8 + (threadIdx.x >> 5);
    if (n >= NN) return;
    int lane = threadIdx.x & 31;
    const __half* ph = sh + (size_t)n * 3 * DD;
    const __half* pl = sl + (size_t)n * 3 * DD;
    float v[8];
    float sum = 0.f, sq = 0.f;
    #pragma unroll
    for (int i = 0; i < 4; i++) {
        __half2 ah = *(const __half2*)&ph[lane * 8 + i * 2];
        __half2 al = *(const __half2*)&pl[lane * 8 + i * 2];
        float w0 = __half2float(ah.x) + __half2float(al.x);
        float w1 = __half2float(ah.y) + __half2float(al.y);
        v[i * 2 + 0] = w0; v[i * 2 + 1] = w1;
        sum += w0 + w1;
        sq  += w0 * w0 + w1 * w1;
    }
    #pragma unroll
    for (int o = 16; o; o >>= 1) {
        sum += __shfl_xor_sync(0xFFFFFFFFu, sum, o);
        sq  += __shfl_xor_sync(0xFFFFFFFFu, sq, o);
    }
    float mean = sum * (1.f / DD);
    float var  = sq * (1.f / DD) - mean * mean;
    float inv  = rsqrtf(var + 1e-5f);
    #pragma unroll
    for (int i = 0; i < 8; i++) {
        int d = lane * 8 + i;
        out[(size_t)n * DD + d] = (v[i] - mean) * inv * g[d] + b[d];
    }
}

// ================= host side =================
template<bool BIAS, bool RELU, bool OUTF, bool OUTS>
static void run_gemm_tc(const __half* Ah, const __half* Al, const __half* Bh,
                        const float* bias, float* Cf,
                        __half* Ch, __half* Cl,
                        int M, int Nn, int K)
{
    cudaFuncSetAttribute(gemm_mma_kernel<BIAS, RELU, OUTF, OUTS>,
                         cudaFuncAttributeMaxDynamicSharedMemorySize, GM_SMEM);
    dim3 grid(Nn / 128, (M + 127) / 128);
    gemm_mma_kernel<BIAS, RELU, OUTF, OUTS><<<grid, 256, GM_SMEM>>>(
        Ah, Al, Bh, bias, Cf, Ch, Cl, M, Nn, K);
}

extern "C" void kernel_launch(void* const* d_in, const int* in_sizes, int n_in,
                              void* d_out, int out_size)
{
    const float* x        = (const float*)d_in[0];
    const int*   ei       = (const int*)  d_in[1];
    const float* gat1_W   = (const float*)d_in[2];
    const float* gat1_b   = (const float*)d_in[3];
    const float* gat1_as  = (const float*)d_in[4];
    const float* gat1_ad  = (const float*)d_in[5];
    const float* gat2_W   = (const float*)d_in[6];
    const float* gat2_b   = (const float*)d_in[7];
    const float* gat2_as  = (const float*)d_in[8];
    const float* gat2_ad  = (const float*)d_in[9];
    const float* cls      = (const float*)d_in[10];
    const float* pos      = (const float*)d_in[11];
    const float* Wqkv     = (const float*)d_in[12];
    const float* bqkv     = (const float*)d_in[13];
    const float* Wo       = (const float*)d_in[14];
    const float* bo       = (const float*)d_in[15];
    const float* ln1_g    = (const float*)d_in[16];
    const float* ln1_b    = (const float*)d_in[17];
    const float* ln2_g    = (const float*)d_in[18];
    const float* ln2_b    = (const float*)d_in[19];
    const float* Wff1     = (const float*)d_in[20];
    const float* bff1     = (const float*)d_in[21];
    const float* Wff2     = (const float*)d_in[22];
    const float* bff2     = (const float*)d_in[23];
    const float* norm_g   = (const float*)d_in[24];
    const float* norm_b   = (const float*)d_in[25];
    float* out = (float*)d_out;

    float *h, *s, *t, *tmp;
    cudaGetSymbolAddress((void**)&h,   g_h);
    cudaGetSymbolAddress((void**)&s,   g_s);
    cudaGetSymbolAddress((void**)&t,   g_t);
    cudaGetSymbolAddress((void**)&tmp, g_tmp);

    int *cnt, *slot, *rows, *csrc;
    cudaGetSymbolAddress((void**)&cnt,  g_cnt);
    cudaGetSymbolAddress((void**)&slot, g_slot);
    cudaGetSymbolAddress((void**)&rows, g_rows);
    cudaGetSymbolAddress((void**)&csrc, g_csrc);

    __half *xh, *xl, *x1h, *x1l, *x2h, *x2l, *seqh, *seql, *qkvh, *qkvl,
           *atth, *attl, *ffh, *ffl, *wbh;
    cudaGetSymbolAddress((void**)&xh,   g_xh);
    cudaGetSymbolAddress((void**)&xl,   g_xl);
    cudaGetSymbolAddress((void**)&x1h,  g_x1h);
    cudaGetSymbolAddress((void**)&x1l,  g_x1l);
    cudaGetSymbolAddress((void**)&x2h,  g_x2h);
    cudaGetSymbolAddress((void**)&x2l,  g_x2l);
    cudaGetSymbolAddress((void**)&seqh, g_seqh);
    cudaGetSymbolAddress((void**)&seql, g_seql);
    cudaGetSymbolAddress((void**)&qkvh, g_qkvh);
    cudaGetSymbolAddress((void**)&qkvl, g_qkvl);
    cudaGetSymbolAddress((void**)&atth, g_atth);
    cudaGetSymbolAddress((void**)&attl, g_attl);
    cudaGetSymbolAddress((void**)&ffh,  g_ffh);
    cudaGetSymbolAddress((void**)&ffl,  g_ffl);
    cudaGetSymbolAddress((void**)&wbh,  g_wbh);

    // ---- CSR build ----
    fill0i_kernel<<<(NN + 255) / 256, 256>>>(cnt, NN);
    hist_kernel<<<(ETOT + 255) / 256, 256>>>(ei, cnt, slot);
    scan_kernel<<<1, 1024>>>(cnt, rows);
    scatter_kernel<<<(ETOT + 255) / 256, 256>>>(ei, rows, slot, csrc);

    // ---- conversions ----
    split_kernel<<<(NN * DIN + 255) / 256, 256>>>(x, xh, xl, NN * DIN);
    round_kernel<<<(DD * DIN + 255) / 256, 256>>>(gat1_W, wbh + WOFF_W1, DD * DIN);
    round_kernel<<<(DD * DD + 255) / 256, 256>>>(gat2_W, wbh + WOFF_W2, DD * DD);
    round_kernel<<<(2 * 3 * DD * DD + 255) / 256, 256>>>(Wqkv, wbh + WOFF_QKV, 2 * 3 * DD * DD);
    round_kernel<<<(2 * DD * DD + 255) / 256, 256>>>(Wo, wbh + WOFF_WO, 2 * DD * DD);
    round_kernel<<<(2 * 4 * DD * DD + 255) / 256, 256>>>(Wff1, wbh + WOFF_F1, 2 * 4 * DD * DD);
    round_kernel<<<(2 * DD * 4 * DD + 255) / 256, 256>>>(Wff2, wbh + WOFF_F2, 2 * DD * 4 * DD);

    // ---- GAT layer 1 ----
    run_gemm_tc<false, false, true, false>(xh, xl, wbh + WOFF_W1,
                                           nullptr, h, nullptr, nullptr, NN, DD, DIN);
    dots_kernel<<<(NN + 7) / 8, 256>>>(h, gat1_as, gat1_ad, s, t);
    gather_kernel<<<(NN + 3) / 4, 256>>>(rows, csrc, s, t, h, gat1_b, x1h, x1l);

    // ---- GAT layer 2 ----
    run_gemm_tc<false, false, true, false>(x1h, x1l, wbh + WOFF_W2,
                                           nullptr, h, nullptr, nullptr, NN, DD, DD);
    dots_kernel<<<(NN + 7) / 8, 256>>>(h, gat2_as, gat2_ad, s, t);
    gather_kernel<<<(NN + 3) / 4, 256>>>(rows, csrc, s, t, h, gat2_b, x2h, x2l);

    // ---- build sequence (hi/lo only) ----
    build_seq_kernel<<<(unsigned)(((size_t)NTOK * DD + 255) / 256), 256>>>(
        x1h, x1l, x2h, x2l, cls, pos, seqh, seql);

    // ---- transformer layers ----
    for (int l = 0; l < 2; l++) {
        const __half* wqh  = wbh + WOFF_QKV + (size_t)l * 3 * DD * DD;
        const __half* woh  = wbh + WOFF_WO  + (size_t)l * DD * DD;
        const __half* wf1h = wbh + WOFF_F1  + (size_t)l * 4 * DD * DD;
        const __half* wf2h = wbh + WOFF_F2  + (size_t)l * DD * 4 * DD;

        run_gemm_tc<true, false, false, true>(seqh, seql, wqh, bqkv + (size_t)l * 3 * DD,
                                              nullptr, qkvh, qkvl, NTOK, 3 * DD, DD);
        attn_kernel<<<(NN * NHEAD + 7) / 8, 256>>>(qkvh, qkvl, atth, attl);
        run_gemm_tc<true, false, true, false>(atth, attl, woh, bo + (size_t)l * DD,
                                              tmp, nullptr, nullptr, NTOK, DD, DD);
        add_ln_kernel<<<(NTOK + 7) / 8, 256>>>(seqh, seql, tmp, ln1_g + l * DD, ln1_b + l * DD);
        run_gemm_tc<true, true, false, true>(seqh, seql, wf1h, bff1 + (size_t)l * 4 * DD,
                                             nullptr, ffh, ffl, NTOK, 4 * DD, DD);
        run_gemm_tc<true, false, true, false>(ffh, ffl, wf2h, bff2 + (size_t)l * DD,
                                              tmp, nullptr, nullptr, NTOK, DD, 4 * DD);
        add_ln_kernel<<<(NTOK + 7) / 8, 256>>>(seqh, seql, tmp, ln2_g + l * DD, ln2_b + l * DD);
    }

    // ---- final LN on CLS token ----
    final_ln_kernel<<<(NN + 7) / 8, 256>>>(seqh, seql, norm_g, norm_b, out);
}

// round 10
// speedup vs baseline: 2.6640x; 1.4497x over previous
#include <cuda_runtime.h>
#include <cuda_fp16.h>
#include <cstdint>
#include <cstdio>

// ---------------- problem constants ----------------
#define NN      50000
#define EE      320000
#define ETOT    (EE + NN)
#define DIN     128
#define DD      256
#define NTOK    (NN * 3)
#define NHEAD   4
#define DH      64
#define NEGS    0.2f

// ---------------- fp32 scratch ----------------
__device__ float g_h  [(size_t)NN * DD];
__device__ float g_s  [NN];
__device__ float g_t  [NN];
__device__ float g_tmp[(size_t)NTOK * DD];

// ---------------- CSR graph scratch ----------------
__device__ int g_cnt [NN];
__device__ int g_slot[ETOT];
__device__ int g_rows[NN + 1];
__device__ int g_csrc[ETOT];

// ---------------- fp16 activation buffers ----------------
__device__ __half g_xh  [(size_t)NN * DIN];
__device__ __half g_x1h [(size_t)NN * DD];
__device__ __half g_x2h [(size_t)NN * DD];
__device__ __half g_seqh[(size_t)NTOK * DD];    // residual stream hi
__device__ __half g_seql[(size_t)NTOK * DD];    // residual stream lo (fp32-exact carrier)
__device__ __half g_qkvh[(size_t)NTOK * 3 * DD];
__device__ __half g_atth[(size_t)NTOK * DD];
__device__ __half g_ffh [(size_t)NTOK * 4 * DD];
// weight pool (fp16-rounded)
#define WOFF_W1   0
#define WOFF_W2   32768
#define WOFF_QKV  98304
#define WOFF_WO   491520
#define WOFF_F1   622592
#define WOFF_F2   1146880
#define WTOT      1671168
__device__ __half g_wbh[WTOT];

// ================= warp-mma helpers =================
__device__ __forceinline__ uint32_t smem_u32(const void* p) {
    uint32_t a;
    asm("{ .reg .u64 t; cvta.to.shared.u64 t, %1; cvt.u32.u64 %0, t; }" : "=r"(a) : "l"(p));
    return a;
}

#define LDM4(r, addr) \
    asm volatile("ldmatrix.sync.aligned.m8n8.x4.shared.b16 {%0,%1,%2,%3}, [%4];" \
        : "=r"((r)[0]), "=r"((r)[1]), "=r"((r)[2]), "=r"((r)[3]) : "r"(addr))
#define MMA16816(c, a, b) \
    asm volatile("mma.sync.aligned.m16n8k16.row.col.f32.f16.f16.f32 " \
        "{%0,%1,%2,%3}, {%4,%5,%6,%7}, {%8,%9}, {%0,%1,%2,%3};" \
        : "+f"((c)[0]), "+f"((c)[1]), "+f"((c)[2]), "+f"((c)[3]) \
        : "r"((a)[0]), "r"((a)[1]), "r"((a)[2]), "r"((a)[3]), "r"((b)[0]), "r"((b)[1]))
#define CP_ASYNC(dst, src, sz) \
    asm volatile("cp.async.cg.shared.global [%0], [%1], 16, %2;" :: "r"(dst), "l"(src), "r"(sz))
#define CP_COMMIT() asm volatile("cp.async.commit_group;" ::: "memory")

__device__ __forceinline__ void split_store(__half* hp, __half* lp, float a, float b) {
    __half h0 = __float2half(a), h1 = __float2half(b);
    __half2 hv; hv.x = h0; hv.y = h1;
    __half2 lv;
    lv.x = __float2half(a - __half2float(h0));
    lv.y = __float2half(b - __half2float(h1));
    *(__half2*)hp = hv;
    *(__half2*)lp = lv;
}

// ================= fp16 GEMM via mma.sync ================================
// C[M,N] = Ah[M,K] * Bh[N,K]^T.
// BM=128, BN=128, BK=32; 256 threads = 8 warps (2m x 4n), warp tile 64x32.
// 3-stage cp.async pipeline, 1 sync/iter, 2 CTAs/SM. Stage: Ah|Bh (20KB).
#define RSB     80
#define MAT_SZ  10240
#define STG_SZ  20480
#define GM_SMEM (3 * STG_SZ)   // 61440

template<bool BIAS, bool RELU, bool OUTF, bool OUTH>
__global__ __launch_bounds__(256, 2) void gemm_mma_kernel(
    const __half* __restrict__ Ah, const __half* __restrict__ Bh,
    const float* __restrict__ bias,
    float* __restrict__ Cf, __half* __restrict__ Ch,
    int M, int Nn, int K)
{
    extern __shared__ char smraw[];
    const uint32_t sb = smem_u32(smraw);
    const int tid = threadIdx.x, wid = tid >> 5, lane = tid & 31;
    const int wm = wid & 1, wn = wid >> 1;
    const int m0 = blockIdx.y * 128, n0 = blockIdx.x * 128;

    float acc[4][4][4];
    #pragma unroll
    for (int mt = 0; mt < 4; mt++)
        #pragma unroll
        for (int nt = 0; nt < 4; nt++)
            #pragma unroll
            for (int c = 0; c < 4; c++) acc[mt][nt][c] = 0.f;

    const int a_row  = (lane & 7) + ((lane >> 3) & 1) * 8;
    const int a_k    = (lane >> 4) * 8;
    const int b_row4 = (lane & 7) + ((lane >> 4) & 1) * 8;
    const int b_k4   = ((lane >> 3) & 1) * 8;

    const int T = K >> 5;

    auto load_stage = [&](int buf, int k0) {
        uint32_t base = sb + buf * STG_SZ;
        #pragma unroll
        for (int it = 0; it < 4; it++) {
            int i    = tid + it * 256;          // 0..1023
            int mat  = i >> 9;                  // 0=Ah, 1=Bh
            int rem  = i & 511;
            int row  = rem >> 2;
            int ch   = rem & 3;
            uint32_t dst = base + mat * MAT_SZ + row * RSB + ch * 16;
            const __half* src;
            int sz = 16;
            if (mat == 0) {
                src = Ah;
                int gm = m0 + row;
                if (gm >= M) sz = 0;
                src += (size_t)gm * K + k0 + ch * 8;
            } else {
                src = Bh + (size_t)(n0 + row) * K + k0 + ch * 8;
            }
            CP_ASYNC(dst, src, sz);
        }
        CP_COMMIT();
    };

    auto compute = [&](int buf) {
        uint32_t base  = sb + buf * STG_SZ;
        uint32_t aB    = base + (wm * 64) * RSB;
        uint32_t bB    = base + MAT_SZ + (wn * 32) * RSB;
        #pragma unroll
        for (int ks = 0; ks < 32; ks += 16) {
            uint32_t bh[4][2];
            #pragma unroll
            for (int ntp = 0; ntp < 2; ntp++) {
                uint32_t bd = bB + (ntp * 16 + b_row4) * RSB + (ks + b_k4) * 2;
                uint32_t r4[4];
                LDM4(r4, bd);
                bh[2 * ntp][0] = r4[0]; bh[2 * ntp][1] = r4[1];
                bh[2 * ntp + 1][0] = r4[2]; bh[2 * ntp + 1][1] = r4[3];
            }
            #pragma unroll
            for (int mt = 0; mt < 4; mt++) {
                uint32_t ah4[4];
                uint32_t ad = aB + (mt * 16 + a_row) * RSB + (ks + a_k) * 2;
                LDM4(ah4, ad);
                #pragma unroll
                for (int nt = 0; nt < 4; nt++) MMA16816(acc[mt][nt], ah4, bh[nt]);
            }
        }
    };

    load_stage(0, 0);
    if (T > 1) load_stage(1, 32);
    for (int t = 0; t < T; t++) {
        if (t + 1 < T) asm volatile("cp.async.wait_group 1;" ::: "memory");
        else           asm volatile("cp.async.wait_group 0;" ::: "memory");
        __syncthreads();
        if (t + 2 < T) load_stage((t + 2) % 3, (t + 2) << 5);
        compute(t % 3);
    }

    // ---------------- epilogue ----------------
    const int r0    = lane >> 2;
    const int cpair = (lane & 3) * 2;
    #pragma unroll
    for (int mt = 0; mt < 4; mt++) {
        int gm1 = m0 + wm * 64 + mt * 16 + r0;
        int gm2 = gm1 + 8;
        #pragma unroll
        for (int nt = 0; nt < 4; nt++) {
            int gn = n0 + wn * 32 + nt * 8 + cpair;
            float b0 = 0.f, b1 = 0.f;
            if (BIAS) { float2 bb = *(const float2*)&bias[gn]; b0 = bb.x; b1 = bb.y; }
            float v0 = acc[mt][nt][0] + b0, v1 = acc[mt][nt][1] + b1;
            float v2 = acc[mt][nt][2] + b0, v3 = acc[mt][nt][3] + b1;
            if (RELU) {
                v0 = fmaxf(v0, 0.f); v1 = fmaxf(v1, 0.f);
                v2 = fmaxf(v2, 0.f); v3 = fmaxf(v3, 0.f);
            }
            if (gm1 < M) {
                if (OUTF) *(float2*)&Cf[(size_t)gm1 * Nn + gn] = make_float2(v0, v1);
                if (OUTH) {
                    __half2 hv; hv.x = __float2half(v0); hv.y = __float2half(v1);
                    *(__half2*)&Ch[(size_t)gm1 * Nn + gn] = hv;
                }
            }
            if (gm2 < M) {
                if (OUTF) *(float2*)&Cf[(size_t)gm2 * Nn + gn] = make_float2(v2, v3);
                if (OUTH) {
                    __half2 hv; hv.x = __float2half(v2); hv.y = __float2half(v3);
                    *(__half2*)&Ch[(size_t)gm2 * Nn + gn] = hv;
                }
            }
        }
    }
}

// ================= CSR build kernels =================
__global__ void fill0i_kernel(int* __restrict__ p, int n) {
    int i = blockIdx.x * 256 + threadIdx.x;
    if (i < n) p[i] = 0;
}

__global__ void hist_kernel(const int* __restrict__ ei, int* __restrict__ cnt,
                            int* __restrict__ slot)
{
    int e = blockIdx.x * 256 + threadIdx.x;
    if (e >= ETOT) return;
    int dst = (e < EE) ? ei[EE + e] : e - EE;
    slot[e] = atomicAdd(&cnt[dst], 1);
}

__global__ void scan_kernel(const int* __restrict__ cnt, int* __restrict__ rows) {
    __shared__ int wsum[32];
    int tid = threadIdx.x;
    const int CH = (NN + 1023) / 1024;
    int beg = tid * CH;
    int ssum = 0;
    for (int i = 0; i < CH; i++) {
        int idx = beg + i;
        if (idx < NN) ssum += cnt[idx];
    }
    int lane = tid & 31, wid = tid >> 5;
    int v = ssum;
    #pragma unroll
    for (int o = 1; o < 32; o <<= 1) {
        int u = __shfl_up_sync(0xFFFFFFFFu, v, o);
        if (lane >= o) v += u;
    }
    if (lane == 31) wsum[wid] = v;
    __syncthreads();
    if (wid == 0) {
        int w = wsum[lane];
        #pragma unroll
        for (int o = 1; o < 32; o <<= 1) {
            int u = __shfl_up_sync(0xFFFFFFFFu, w, o);
            if (lane >= o) w += u;
        }
        wsum[lane] = w;
    }
    __syncthreads();
    int off = v - ssum + (wid ? wsum[wid - 1] : 0);
    for (int i = 0; i < CH; i++) {
        int idx = beg + i;
        if (idx < NN) { rows[idx] = off; off += cnt[idx]; }
    }
    if (tid == 0) rows[NN] = ETOT;
}

__global__ void scatter_kernel(const int* __restrict__ ei, const int* __restrict__ rows,
                               const int* __restrict__ slot, int* __restrict__ csrc)
{
    int e = blockIdx.x * 256 + threadIdx.x;
    if (e >= ETOT) return;
    int src, dst;
    if (e < EE) { src = ei[e]; dst = ei[EE + e]; }
    else        { src = dst = e - EE; }
    csrc[rows[dst] + slot[e]] = src;
}

// ================= GAT gather (CSR, no atomics) — fp16 hi output =========
__global__ void gather_kernel(const int* __restrict__ rows, const int* __restrict__ csrc,
                              const float* __restrict__ s, const float* __restrict__ t,
                              const float* __restrict__ h, const float* __restrict__ b,
                              __half* __restrict__ oh)
{
    int n = blockIdx.x * 4 + (threadIdx.x >> 6);
    if (n >= NN) return;
    int sub = threadIdx.x & 63;
    float tn = __ldg(&t[n]);
    int beg = __ldg(&rows[n]), end = __ldg(&rows[n + 1]);
    float a0 = 0.f, a1 = 0.f, a2 = 0.f, a3 = 0.f, den = 0.f;
    for (int i = beg; i < end; i++) {
        int src = __ldg(&csrc[i]);
        float x = __ldg(&s[src]) + tn;
        float ex = expf(x > 0.f ? x : NEGS * x);
        den += ex;
        float4 hv = *(const float4*)&h[(size_t)src * DD + sub * 4];
        a0 += ex * hv.x; a1 += ex * hv.y; a2 += ex * hv.z; a3 += ex * hv.w;
    }
    float inv = 1.f / den;
    float4 bb = *(const float4*)&b[sub * 4];
    float v0 = fmaxf(a0 * inv + bb.x, 0.f);
    float v1 = fmaxf(a1 * inv + bb.y, 0.f);
    float v2 = fmaxf(a2 * inv + bb.z, 0.f);
    float v3 = fmaxf(a3 * inv + bb.w, 0.f);
    size_t o = (size_t)n * DD + sub * 4;
    __half2 p0; p0.x = __float2half(v0); p0.y = __float2half(v1);
    __half2 p1; p1.x = __float2half(v2); p1.y = __float2half(v3);
    *(__half2*)&oh[o]     = p0;
    *(__half2*)&oh[o + 2] = p1;
}

// ================= small kernels =================
__global__ void round_kernel(const float* __restrict__ s, __half* __restrict__ h, int n)
{
    int i = blockIdx.x * 256 + threadIdx.x;
    if (i < n) h[i] = __float2half(s[i]);
}

__global__ void dots_kernel(const float* __restrict__ h,
                            const float* __restrict__ asrc,
                            const float* __restrict__ adst,
                            float* __restrict__ s, float* __restrict__ t)
{
    int n = blockIdx.x * 8 + (threadIdx.x >> 5);
    if (n >= NN) return;
    int lane = threadIdx.x & 31;
    const float* row = h + (size_t)n * DD;
    float ps = 0.f, pt = 0.f;
    #pragma unroll
    for (int i = 0; i < 8; i++) {
        int d = lane + 32 * i;
        float v = row[d];
        ps += v * asrc[d];
        pt += v * adst[d];
    }
    #pragma unroll
    for (int o = 16; o; o >>= 1) {
        ps += __shfl_xor_sync(0xFFFFFFFFu, ps, o);
        pt += __shfl_xor_sync(0xFFFFFFFFu, pt, o);
    }
    if (lane == 0) { s[n] = ps; t[n] = pt; }
}

// build seq (hi/lo residual stream) from x1,x2 fp16 + cls + pos
__global__ void build_seq_kernel(const __half* __restrict__ x1h,
                                 const __half* __restrict__ x2h,
                                 const float* __restrict__ cls,
                                 const float* __restrict__ pos,
                                 __half* __restrict__ sh,
                                 __half* __restrict__ sl)
{
    size_t i = (size_t)blockIdx.x * 256 + threadIdx.x;
    if (i >= (size_t)NTOK * DD) return;
    int d = (int)(i & 255);
    size_t tok = i >> 8;
    int which = (int)(tok % 3);
    size_t n = tok / 3;
    float v;
    if (which == 0)      v = cls[d];
    else if (which == 1) v = __half2float(x1h[n * DD + d]);
    else                 v = __half2float(x2h[n * DD + d]);
    v += pos[which * DD + d];
    __half a = __float2half(v);
    sh[i] = a;
    sl[i] = __float2half(v - __half2float(a));
}

// attention from fp16 qkv, fp16 output
__global__ void attn_kernel(const __half* __restrict__ qh, __half* __restrict__ atth)
{
    int w = blockIdx.x * 8 + (threadIdx.x >> 5);
    if (w >= NN * NHEAD) return;
    int lane = threadIdx.x & 31;
    int n = w >> 2, hh = w & 3;
    size_t base = (size_t)n * 3 * (3 * DD) + hh * DH + lane * 2;
    float2 q[3], k[3], v[3];
    #pragma unroll
    for (int i = 0; i < 3; i++) {
        size_t o = base + (size_t)i * (3 * DD);
        __half2 a;
        a = *(const __half2*)(qh + o);
        q[i].x = __half2float(a.x); q[i].y = __half2float(a.y);
        a = *(const __half2*)(qh + o + DD);
        k[i].x = __half2float(a.x); k[i].y = __half2float(a.y);
        a = *(const __half2*)(qh + o + 2 * DD);
        v[i].x = __half2float(a.x); v[i].y = __half2float(a.y);
    }
    float lg[3][3];
    #pragma unroll
    for (int i = 0; i < 3; i++)
        #pragma unroll
        for (int j = 0; j < 3; j++) {
            float p = q[i].x * k[j].x + q[i].y * k[j].y;
            #pragma unroll
            for (int o = 16; o; o >>= 1) p += __shfl_xor_sync(0xFFFFFFFFu, p, o);
            lg[i][j] = p * 0.125f;
        }
    #pragma unroll
    for (int i = 0; i < 3; i++) {
        float m  = fmaxf(lg[i][0], fmaxf(lg[i][1], lg[i][2]));
        float e0 = expf(lg[i][0] - m), e1 = expf(lg[i][1] - m), e2 = expf(lg[i][2] - m);
        float inv = 1.f / (e0 + e1 + e2);
        float ox = (e0 * v[0].x + e1 * v[1].x + e2 * v[2].x) * inv;
        float oy = (e0 * v[0].y + e1 * v[1].y + e2 * v[2].y) * inv;
        size_t o = ((size_t)(n * 3 + i)) * DD + hh * DH + lane * 2;
        __half2 hv; hv.x = __float2half(ox); hv.y = __float2half(oy);
        *(__half2*)&atth[o] = hv;
    }
}

// residual + LN, in-place on (sh, sl); res is fp32
__global__ void add_ln_kernel(__half* __restrict__ sh, __half* __restrict__ sl,
                              const float* __restrict__ res,
                              const float* __restrict__ g,
                              const float* __restrict__ b)
{
    int tok = blockIdx.x * 8 + (threadIdx.x >> 5);
    if (tok >= NTOK) return;
    int lane = threadIdx.x & 31;
    __half* ph = sh + (size_t)tok * DD;
    __half* pl = sl + (size_t)tok * DD;
    const float* q = res + (size_t)tok * DD;
    float v[8];
    float sum = 0.f, sq = 0.f;
    #pragma unroll
    for (int i = 0; i < 4; i++) {
        __half2 ah = *(const __half2*)&ph[lane * 8 + i * 2];
        __half2 al = *(const __half2*)&pl[lane * 8 + i * 2];
        float2 c = *(const float2*)&q[lane * 8 + i * 2];
        float w0 = __half2float(ah.x) + __half2float(al.x) + c.x;
        float w1 = __half2float(ah.y) + __half2float(al.y) + c.y;
        v[i * 2 + 0] = w0; v[i * 2 + 1] = w1;
        sum += w0 + w1;
        sq  += w0 * w0 + w1 * w1;
    }
    #pragma unroll
    for (int o = 16; o; o >>= 1) {
        sum += __shfl_xor_sync(0xFFFFFFFFu, sum, o);
        sq  += __shfl_xor_sync(0xFFFFFFFFu, sq, o);
    }
    float mean = sum * (1.f / DD);
    float var  = sq * (1.f / DD) - mean * mean;
    float inv  = rsqrtf(var + 1e-5f);
    #pragma unroll
    for (int i = 0; i < 4; i++) {
        int d = lane * 8 + i * 2;
        float y0 = (v[i * 2 + 0] - mean) * inv * g[d + 0] + b[d + 0];
        float y1 = (v[i * 2 + 1] - mean) * inv * g[d + 1] + b[d + 1];
        split_store(&ph[d], &pl[d], y0, y1);
    }
}

__global__ void final_ln_kernel(const __half* __restrict__ sh, const __half* __restrict__ sl,
                                const float* __restrict__ g,
                                const float* __restrict__ b,
                                float* __restrict__ out)
{
    int n = blockIdx.x * 8 + (threadIdx.x >> 5);
    if (n >= NN) return;
    int lane = threadIdx.x & 31;
    const __half* ph = sh + (size_t)n * 3 * DD;
    const __half* pl = sl + (size_t)n * 3 * DD;
    float v[8];
    float sum = 0.f, sq = 0.f;
    #pragma unroll
    for (int i = 0; i < 4; i++) {
        __half2 ah = *(const __half2*)&ph[lane * 8 + i * 2];
        __half2 al = *(const __half2*)&pl[lane * 8 + i * 2];
        float w0 = __half2float(ah.x) + __half2float(al.x);
        float w1 = __half2float(ah.y) + __half2float(al.y);
        v[i * 2 + 0] = w0; v[i * 2 + 1] = w1;
        sum += w0 + w1;
        sq  += w0 * w0 + w1 * w1;
    }
    #pragma unroll
    for (int o = 16; o; o >>= 1) {
        sum += __shfl_xor_sync(0xFFFFFFFFu, sum, o);
        sq  += __shfl_xor_sync(0xFFFFFFFFu, sq, o);
    }
    float mean = sum * (1.f / DD);
    float var  = sq * (1.f / DD) - mean * mean;
    float inv  = rsqrtf(var + 1e-5f);
    #pragma unroll
    for (int i = 0; i < 8; i++) {
        int d = lane * 8 + i;
        out[(size_t)n * DD + d] = (v[i] - mean) * inv * g[d] + b[d];
    }
}

// ================= host side =================
template<bool BIAS, bool RELU, bool OUTF, bool OUTH>
static void run_gemm_tc(const __half* Ah, const __half* Bh,
                        const float* bias, float* Cf, __half* Ch,
                        int M, int Nn, int K)
{
    cudaFuncSetAttribute(gemm_mma_kernel<BIAS, RELU, OUTF, OUTH>,
                         cudaFuncAttributeMaxDynamicSharedMemorySize, GM_SMEM);
    dim3 grid(Nn / 128, (M + 127) / 128);
    gemm_mma_kernel<BIAS, RELU, OUTF, OUTH><<<grid, 256, GM_SMEM>>>(
        Ah, Bh, bias, Cf, Ch, M, Nn, K);
}

extern "C" void kernel_launch(void* const* d_in, const int* in_sizes, int n_in,
                              void* d_out, int out_size)
{
    const float* x        = (const float*)d_in[0];
    const int*   ei       = (const int*)  d_in[1];
    const float* gat1_W   = (const float*)d_in[2];
    const float* gat1_b   = (const float*)d_in[3];
    const float* gat1_as  = (const float*)d_in[4];
    const float* gat1_ad  = (const float*)d_in[5];
    const float* gat2_W   = (const float*)d_in[6];
    const float* gat2_b   = (const float*)d_in[7];
    const float* gat2_as  = (const float*)d_in[8];
    const float* gat2_ad  = (const float*)d_in[9];
    const float* cls      = (const float*)d_in[10];
    const float* pos      = (const float*)d_in[11];
    const float* Wqkv     = (const float*)d_in[12];
    const float* bqkv     = (const float*)d_in[13];
    const float* Wo       = (const float*)d_in[14];
    const float* bo       = (const float*)d_in[15];
    const float* ln1_g    = (const float*)d_in[16];
    const float* ln1_b    = (const float*)d_in[17];
    const float* ln2_g    = (const float*)d_in[18];
    const float* ln2_b    = (const float*)d_in[19];
    const float* Wff1     = (const float*)d_in[20];
    const float* bff1     = (const float*)d_in[21];
    const float* Wff2     = (const float*)d_in[22];
    const float* bff2     = (const float*)d_in[23];
    const float* norm_g   = (const float*)d_in[24];
    const float* norm_b   = (const float*)d_in[25];
    float* out = (float*)d_out;

    float *h, *s, *t, *tmp;
    cudaGetSymbolAddress((void**)&h,   g_h);
    cudaGetSymbolAddress((void**)&s,   g_s);
    cudaGetSymbolAddress((void**)&t,   g_t);
    cudaGetSymbolAddress((void**)&tmp, g_tmp);

    int *cnt, *slot, *rows, *csrc;
    cudaGetSymbolAddress((void**)&cnt,  g_cnt);
    cudaGetSymbolAddress((void**)&slot, g_slot);
    cudaGetSymbolAddress((void**)&rows, g_rows);
    cudaGetSymbolAddress((void**)&csrc, g_csrc);

    __half *xh, *x1h, *x2h, *seqh, *seql, *qkvh, *atth, *ffh, *wbh;
    cudaGetSymbolAddress((void**)&xh,   g_xh);
    cudaGetSymbolAddress((void**)&x1h,  g_x1h);
    cudaGetSymbolAddress((void**)&x2h,  g_x2h);
    cudaGetSymbolAddress((void**)&seqh, g_seqh);
    cudaGetSymbolAddress((void**)&seql, g_seql);
    cudaGetSymbolAddress((void**)&qkvh, g_qkvh);
    cudaGetSymbolAddress((void**)&atth, g_atth);
    cudaGetSymbolAddress((void**)&ffh,  g_ffh);
    cudaGetSymbolAddress((void**)&wbh,  g_wbh);

    // ---- CSR build ----
    fill0i_kernel<<<(NN + 255) / 256, 256>>>(cnt, NN);
    hist_kernel<<<(ETOT + 255) / 256, 256>>>(ei, cnt, slot);
    scan_kernel<<<1, 1024>>>(cnt, rows);
    scatter_kernel<<<(ETOT + 255) / 256, 256>>>(ei, rows, slot, csrc);

    // ---- conversions ----
    round_kernel<<<(NN * DIN + 255) / 256, 256>>>(x, xh, NN * DIN);
    round_kernel<<<(DD * DIN + 255) / 256, 256>>>(gat1_W, wbh + WOFF_W1, DD * DIN);
    round_kernel<<<(DD * DD + 255) / 256, 256>>>(gat2_W, wbh + WOFF_W2, DD * DD);
    round_kernel<<<(2 * 3 * DD * DD + 255) / 256, 256>>>(Wqkv, wbh + WOFF_QKV, 2 * 3 * DD * DD);
    round_kernel<<<(2 * DD * DD + 255) / 256, 256>>>(Wo, wbh + WOFF_WO, 2 * DD * DD);
    round_kernel<<<(2 * 4 * DD * DD + 255) / 256, 256>>>(Wff1, wbh + WOFF_F1, 2 * 4 * DD * DD);
    round_kernel<<<(2 * DD * 4 * DD + 255) / 256, 256>>>(Wff2, wbh + WOFF_F2, 2 * DD * 4 * DD);

    // ---- GAT layer 1 ----
    run_gemm_tc<false, false, true, false>(xh, wbh + WOFF_W1, nullptr, h, nullptr, NN, DD, DIN);
    dots_kernel<<<(NN + 7) / 8, 256>>>(h, gat1_as, gat1_ad, s, t);
    gather_kernel<<<(NN + 3) / 4, 256>>>(rows, csrc, s, t, h, gat1_b, x1h);

    // ---- GAT layer 2 ----
    run_gemm_tc<false, false, true, false>(x1h, wbh + WOFF_W2, nullptr, h, nullptr, NN, DD, DD);
    dots_kernel<<<(NN + 7) / 8, 256>>>(h, gat2_as, gat2_ad, s, t);
    gather_kernel<<<(NN + 3) / 4, 256>>>(rows, csrc, s, t, h, gat2_b, x2h);

    // ---- build sequence (hi/lo residual stream) ----
    build_seq_kernel<<<(unsigned)(((size_t)NTOK * DD + 255) / 256), 256>>>(
        x1h, x2h, cls, pos, seqh, seql);

    // ---- transformer layers ----
    for (int l = 0; l < 2; l++) {
        const __half* wqh  = wbh + WOFF_QKV + (size_t)l * 3 * DD * DD;
        const __half* woh  = wbh + WOFF_WO  + (size_t)l * DD * DD;
        const __half* wf1h = wbh + WOFF_F1  + (size_t)l * 4 * DD * DD;
        const __half* wf2h = wbh + WOFF_F2  + (size_t)l * DD * 4 * DD;

        run_gemm_tc<true, false, false, true>(seqh, wqh, bqkv + (size_t)l * 3 * DD,
                                              nullptr, qkvh, NTOK, 3 * DD, DD);
        attn_kernel<<<(NN * NHEAD + 7) / 8, 256>>>(qkvh, atth);
        run_gemm_tc<true, false, true, false>(atth, woh, bo + (size_t)l * DD,
                                              tmp, nullptr, NTOK, DD, DD);
        add_ln_kernel<<<(NTOK + 7) / 8, 256>>>(seqh, seql, tmp, ln1_g + l * DD, ln1_b + l * DD);
        run_gemm_tc<true, true, false, true>(seqh, wf1h, bff1 + (size_t)l * 4 * DD,
                                             nullptr, ffh, NTOK, 4 * DD, DD);
        run_gemm_tc<true, false, true, false>(ffh, wf2h, bff2 + (size_t)l * DD,
                                              tmp, nullptr, NTOK, DD, 4 * DD);
        add_ln_kernel<<<(NTOK + 7) / 8, 256>>>(seqh, seql, tmp, ln2_g + l * DD, ln2_b + l * DD);
    }

    // ---- final LN on CLS token ----
    final_ln_kernel<<<(NN + 7) / 8, 256>>>(seqh, seql, norm_g, norm_b, out);
}

// round 12
// speedup vs baseline: 2.6954x; 1.0118x over previous
#include <cuda_runtime.h>
#include <cuda_fp16.h>
#include <cstdint>
#include <cstdio>

// ---------------- problem constants ----------------
#define NN      50000
#define EE      320000
#define ETOT    (EE + NN)
#define DIN     128
#define DD      256
#define NTOK    (NN * 3)
#define NHEAD   4
#define DH      64
#define NEGS    0.2f

// ---------------- fp32 scratch ----------------
__device__ float g_h  [(size_t)NN * DD];
__device__ float g_s  [NN];
__device__ float g_t  [NN];

// ---------------- CSR graph scratch ----------------
__device__ int g_cnt [NN];
__device__ int g_slot[ETOT];
__device__ int g_rows[NN + 1];
__device__ int g_csrc[ETOT];

// ---------------- fp16 activation buffers ----------------
__device__ __half g_xh  [(size_t)NN * DIN];
__device__ __half g_x1h [(size_t)NN * DD];
__device__ __half g_x2h [(size_t)NN * DD];
__device__ __half g_seqh[(size_t)NTOK * DD];    // residual stream hi
__device__ __half g_seql[(size_t)NTOK * DD];    // residual stream lo (fp32-exact carrier)
__device__ __half g_qkvh[(size_t)NTOK * 3 * DD];
__device__ __half g_atth[(size_t)NTOK * DD];
__device__ __half g_tmph[(size_t)NTOK * DD];    // residual branch (fp16)
__device__ __half g_ffh [(size_t)NTOK * 4 * DD];
// weight pool (fp16-rounded)
#define WOFF_W1   0
#define WOFF_W2   32768
#define WOFF_QKV  98304
#define WOFF_WO   491520
#define WOFF_F1   622592
#define WOFF_F2   1146880
#define WTOT      1671168
__device__ __half g_wbh[WTOT];

// ================= warp-mma helpers =================
__device__ __forceinline__ uint32_t smem_u32(const void* p) {
    uint32_t a;
    asm("{ .reg .u64 t; cvta.to.shared.u64 t, %1; cvt.u32.u64 %0, t; }" : "=r"(a) : "l"(p));
    return a;
}

#define LDM4(r, addr) \
    asm volatile("ldmatrix.sync.aligned.m8n8.x4.shared.b16 {%0,%1,%2,%3}, [%4];" \
        : "=r"((r)[0]), "=r"((r)[1]), "=r"((r)[2]), "=r"((r)[3]) : "r"(addr))
#define MMA16816(c, a, b) \
    asm volatile("mma.sync.aligned.m16n8k16.row.col.f32.f16.f16.f32 " \
        "{%0,%1,%2,%3}, {%4,%5,%6,%7}, {%8,%9}, {%0,%1,%2,%3};" \
        : "+f"((c)[0]), "+f"((c)[1]), "+f"((c)[2]), "+f"((c)[3]) \
        : "r"((a)[0]), "r"((a)[1]), "r"((a)[2]), "r"((a)[3]), "r"((b)[0]), "r"((b)[1]))
#define CP_ASYNC(dst, src, sz) \
    asm volatile("cp.async.cg.shared.global [%0], [%1], 16, %2;" :: "r"(dst), "l"(src), "r"(sz))
#define CP_COMMIT() asm volatile("cp.async.commit_group;" ::: "memory")

__device__ __forceinline__ void split_store(__half* hp, __half* lp, float a, float b) {
    __half h0 = __float2half(a), h1 = __float2half(b);
    __half2 hv; hv.x = h0; hv.y = h1;
    __half2 lv;
    lv.x = __float2half(a - __half2float(h0));
    lv.y = __float2half(b - __half2float(h1));
    *(__half2*)hp = hv;
    *(__half2*)lp = lv;
}

// ================= fp16 GEMM via mma.sync ================================
// C[M,N] = Ah[M,K] * Bh[N,K]^T.
// BM=128, BN=128, BK=32; 256 threads = 8 warps (2m x 4n), warp tile 64x32.
// 3-stage cp.async pipeline, 1 sync/iter, 2 CTAs/SM. Stage: Ah|Bh (20KB).
#define RSB     80
#define MAT_SZ  10240
#define STG_SZ  20480
#define GM_SMEM (3 * STG_SZ)   // 61440

template<bool BIAS, bool RELU, bool OUTF, bool OUTH>
__global__ __launch_bounds__(256, 2) void gemm_mma_kernel(
    const __half* __restrict__ Ah, const __half* __restrict__ Bh,
    const float* __restrict__ bias,
    float* __restrict__ Cf, __half* __restrict__ Ch,
    int M, int Nn, int K)
{
    extern __shared__ char smraw[];
    const uint32_t sb = smem_u32(smraw);
    const int tid = threadIdx.x, wid = tid >> 5, lane = tid & 31;
    const int wm = wid & 1, wn = wid >> 1;
    const int m0 = blockIdx.y * 128, n0 = blockIdx.x * 128;

    float acc[4][4][4];
    #pragma unroll
    for (int mt = 0; mt < 4; mt++)
        #pragma unroll
        for (int nt = 0; nt < 4; nt++)
            #pragma unroll
            for (int c = 0; c < 4; c++) acc[mt][nt][c] = 0.f;

    const int a_row  = (lane & 7) + ((lane >> 3) & 1) * 8;
    const int a_k    = (lane >> 4) * 8;
    const int b_row4 = (lane & 7) + ((lane >> 4) & 1) * 8;
    const int b_k4   = ((lane >> 3) & 1) * 8;

    const int T = K >> 5;

    auto load_stage = [&](int buf, int k0) {
        uint32_t base = sb + buf * STG_SZ;
        #pragma unroll
        for (int it = 0; it < 4; it++) {
            int i    = tid + it * 256;
            int mat  = i >> 9;
            int rem  = i & 511;
            int row  = rem >> 2;
            int ch   = rem & 3;
            uint32_t dst = base + mat * MAT_SZ + row * RSB + ch * 16;
            const __half* src;
            int sz = 16;
            if (mat == 0) {
                src = Ah;
                int gm = m0 + row;
                if (gm >= M) sz = 0;
                src += (size_t)gm * K + k0 + ch * 8;
            } else {
                src = Bh + (size_t)(n0 + row) * K + k0 + ch * 8;
            }
            CP_ASYNC(dst, src, sz);
        }
        CP_COMMIT();
    };

    auto compute = [&](int buf) {
        uint32_t base  = sb + buf * STG_SZ;
        uint32_t aB    = base + (wm * 64) * RSB;
        uint32_t bB    = base + MAT_SZ + (wn * 32) * RSB;
        #pragma unroll
        for (int ks = 0; ks < 32; ks += 16) {
            uint32_t bh[4][2];
            #pragma unroll
            for (int ntp = 0; ntp < 2; ntp++) {
                uint32_t bd = bB + (ntp * 16 + b_row4) * RSB + (ks + b_k4) * 2;
                uint32_t r4[4];
                LDM4(r4, bd);
                bh[2 * ntp][0] = r4[0]; bh[2 * ntp][1] = r4[1];
                bh[2 * ntp + 1][0] = r4[2]; bh[2 * ntp + 1][1] = r4[3];
            }
            #pragma unroll
            for (int mt = 0; mt < 4; mt++) {
                uint32_t ah4[4];
                uint32_t ad = aB + (mt * 16 + a_row) * RSB + (ks + a_k) * 2;
                LDM4(ah4, ad);
                #pragma unroll
                for (int nt = 0; nt < 4; nt++) MMA16816(acc[mt][nt], ah4, bh[nt]);
            }
        }
    };

    load_stage(0, 0);
    if (T > 1) load_stage(1, 32);
    for (int t = 0; t < T; t++) {
        if (t + 1 < T) asm volatile("cp.async.wait_group 1;" ::: "memory");
        else           asm volatile("cp.async.wait_group 0;" ::: "memory");
        __syncthreads();
        if (t + 2 < T) load_stage((t + 2) % 3, (t + 2) << 5);
        compute(t % 3);
    }

    // ---------------- epilogue ----------------
    const int r0    = lane >> 2;
    const int cpair = (lane & 3) * 2;
    #pragma unroll
    for (int mt = 0; mt < 4; mt++) {
        int gm1 = m0 + wm * 64 + mt * 16 + r0;
        int gm2 = gm1 + 8;
        #pragma unroll
        for (int nt = 0; nt < 4; nt++) {
            int gn = n0 + wn * 32 + nt * 8 + cpair;
            float b0 = 0.f, b1 = 0.f;
            if (BIAS) { float2 bb = *(const float2*)&bias[gn]; b0 = bb.x; b1 = bb.y; }
            float v0 = acc[mt][nt][0] + b0, v1 = acc[mt][nt][1] + b1;
            float v2 = acc[mt][nt][2] + b0, v3 = acc[mt][nt][3] + b1;
            if (RELU) {
                v0 = fmaxf(v0, 0.f); v1 = fmaxf(v1, 0.f);
                v2 = fmaxf(v2, 0.f); v3 = fmaxf(v3, 0.f);
            }
            if (gm1 < M) {
                if (OUTF) *(float2*)&Cf[(size_t)gm1 * Nn + gn] = make_float2(v0, v1);
                if (OUTH) {
                    __half2 hv; hv.x = __float2half(v0); hv.y = __float2half(v1);
                    *(__half2*)&Ch[(size_t)gm1 * Nn + gn] = hv;
                }
            }
            if (gm2 < M) {
                if (OUTF) *(float2*)&Cf[(size_t)gm2 * Nn + gn] = make_float2(v2, v3);
                if (OUTH) {
                    __half2 hv; hv.x = __float2half(v2); hv.y = __float2half(v3);
                    *(__half2*)&Ch[(size_t)gm2 * Nn + gn] = hv;
                }
            }
        }
    }
}

// ================= CSR build kernels =================
__global__ void fill0i_kernel(int* __restrict__ p, int n) {
    int i = blockIdx.x * 256 + threadIdx.x;
    if (i < n) p[i] = 0;
}

__global__ void hist_kernel(const int* __restrict__ ei, int* __restrict__ cnt,
                            int* __restrict__ slot)
{
    int e = blockIdx.x * 256 + threadIdx.x;
    if (e >= ETOT) return;
    int dst = (e < EE) ? ei[EE + e] : e - EE;
    slot[e] = atomicAdd(&cnt[dst], 1);
}

__global__ void scan_kernel(const int* __restrict__ cnt, int* __restrict__ rows) {
    __shared__ int wsum[32];
    int tid = threadIdx.x;
    const int CH = (NN + 1023) / 1024;
    int beg = tid * CH;
    int ssum = 0;
    for (int i = 0; i < CH; i++) {
        int idx = beg + i;
        if (idx < NN) ssum += cnt[idx];
    }
    int lane = tid & 31, wid = tid >> 5;
    int v = ssum;
    #pragma unroll
    for (int o = 1; o < 32; o <<= 1) {
        int u = __shfl_up_sync(0xFFFFFFFFu, v, o);
        if (lane >= o) v += u;
    }
    if (lane == 31) wsum[wid] = v;
    __syncthreads();
    if (wid == 0) {
        int w = wsum[lane];
        #pragma unroll
        for (int o = 1; o < 32; o <<= 1) {
            int u = __shfl_up_sync(0xFFFFFFFFu, w, o);
            if (lane >= o) w += u;
        }
        wsum[lane] = w;
    }
    __syncthreads();
    int off = v - ssum + (wid ? wsum[wid - 1] : 0);
    for (int i = 0; i < CH; i++) {
        int idx = beg + i;
        if (idx < NN) { rows[idx] = off; off += cnt[idx]; }
    }
    if (tid == 0) rows[NN] = ETOT;
}

__global__ void scatter_kernel(const int* __restrict__ ei, const int* __restrict__ rows,
                               const int* __restrict__ slot, int* __restrict__ csrc)
{
    int e = blockIdx.x * 256 + threadIdx.x;
    if (e >= ETOT) return;
    int src, dst;
    if (e < EE) { src = ei[e]; dst = ei[EE + e]; }
    else        { src = dst = e - EE; }
    csrc[rows[dst] + slot[e]] = src;
}

// ================= GAT gather (CSR, no atomics) — fp16 hi output =========
__global__ void gather_kernel(const int* __restrict__ rows, const int* __restrict__ csrc,
                              const float* __restrict__ s, const float* __restrict__ t,
                              const float* __restrict__ h, const float* __restrict__ b,
                              __half* __restrict__ oh)
{
    int n = blockIdx.x * 4 + (threadIdx.x >> 6);
    if (n >= NN) return;
    int sub = threadIdx.x & 63;
    float tn = __ldg(&t[n]);
    int beg = __ldg(&rows[n]), end = __ldg(&rows[n + 1]);
    float a0 = 0.f, a1 = 0.f, a2 = 0.f, a3 = 0.f, den = 0.f;
    for (int i = beg; i < end; i++) {
        int src = __ldg(&csrc[i]);
        float x = __ldg(&s[src]) + tn;
        float ex = expf(x > 0.f ? x : NEGS * x);
        den += ex;
        float4 hv = *(const float4*)&h[(size_t)src * DD + sub * 4];
        a0 += ex * hv.x; a1 += ex * hv.y; a2 += ex * hv.z; a3 += ex * hv.w;
    }
    float inv = 1.f / den;
    float4 bb = *(const float4*)&b[sub * 4];
    float v0 = fmaxf(a0 * inv + bb.x, 0.f);
    float v1 = fmaxf(a1 * inv + bb.y, 0.f);
    float v2 = fmaxf(a2 * inv + bb.z, 0.f);
    float v3 = fmaxf(a3 * inv + bb.w, 0.f);
    size_t o = (size_t)n * DD + sub * 4;
    __half2 p0; p0.x = __float2half(v0); p0.y = __float2half(v1);
    __half2 p1; p1.x = __float2half(v2); p1.y = __float2half(v3);
    *(__half2*)&oh[o]     = p0;
    *(__half2*)&oh[o + 2] = p1;
}

// ================= small kernels =================
__global__ void round_kernel(const float* __restrict__ s, __half* __restrict__ h, int n)
{
    int i = blockIdx.x * 256 + threadIdx.x;
    if (i < n) h[i] = __float2half(s[i]);
}

__global__ void dots_kernel(const float* __restrict__ h,
                            const float* __restrict__ asrc,
                            const float* __restrict__ adst,
                            float* __restrict__ s, float* __restrict__ t)
{
    int n = blockIdx.x * 8 + (threadIdx.x >> 5);
    if (n >= NN) return;
    int lane = threadIdx.x & 31;
    const float* row = h + (size_t)n * DD;
    float ps = 0.f, pt = 0.f;
    #pragma unroll
    for (int i = 0; i < 8; i++) {
        int d = lane + 32 * i;
        float v = row[d];
        ps += v * asrc[d];
        pt += v * adst[d];
    }
    #pragma unroll
    for (int o = 16; o; o >>= 1) {
        ps += __shfl_xor_sync(0xFFFFFFFFu, ps, o);
        pt += __shfl_xor_sync(0xFFFFFFFFu, pt, o);
    }
    if (lane == 0) { s[n] = ps; t[n] = pt; }
}

// build seq (hi/lo residual stream) from x1,x2 fp16 + cls + pos
__global__ void build_seq_kernel(const __half* __restrict__ x1h,
                                 const __half* __restrict__ x2h,
                                 const float* __restrict__ cls,
                                 const float* __restrict__ pos,
                                 __half* __restrict__ sh,
                                 __half* __restrict__ sl)
{
    size_t i = (size_t)blockIdx.x * 256 + threadIdx.x;
    if (i >= (size_t)NTOK * DD) return;
    int d = (int)(i & 255);
    size_t tok = i >> 8;
    int which = (int)(tok % 3);
    size_t n = tok / 3;
    float v;
    if (which == 0)      v = cls[d];
    else if (which == 1) v = __half2float(x1h[n * DD + d]);
    else                 v = __half2float(x2h[n * DD + d]);
    v += pos[which * DD + d];
    __half a = __float2half(v);
    sh[i] = a;
    sl[i] = __float2half(v - __half2float(a));
}

// attention from fp16 qkv, fp16 output
__global__ void attn_kernel(const __half* __restrict__ qh, __half* __restrict__ atth)
{
    int w = blockIdx.x * 8 + (threadIdx.x >> 5);
    if (w >= NN * NHEAD) return;
    int lane = threadIdx.x & 31;
    int n = w >> 2, hh = w & 3;
    size_t base = (size_t)n * 3 * (3 * DD) + hh * DH + lane * 2;
    float2 q[3], k[3], v[3];
    #pragma unroll
    for (int i = 0; i < 3; i++) {
        size_t o = base + (size_t)i * (3 * DD);
        __half2 a;
        a = *(const __half2*)(qh + o);
        q[i].x = __half2float(a.x); q[i].y = __half2float(a.y);
        a = *(const __half2*)(qh + o + DD);
        k[i].x = __half2float(a.x); k[i].y = __half2float(a.y);
        a = *(const __half2*)(qh + o + 2 * DD);
        v[i].x = __half2float(a.x); v[i].y = __half2float(a.y);
    }
    float lg[3][3];
    #pragma unroll
    for (int i = 0; i < 3; i++)
        #pragma unroll
        for (int j = 0; j < 3; j++) {
            float p = q[i].x * k[j].x + q[i].y * k[j].y;
            #pragma unroll
            for (int o = 16; o; o >>= 1) p += __shfl_xor_sync(0xFFFFFFFFu, p, o);
            lg[i][j] = p * 0.125f;
        }
    #pragma unroll
    for (int i = 0; i < 3; i++) {
        float m  = fmaxf(lg[i][0], fmaxf(lg[i][1], lg[i][2]));
        float e0 = expf(lg[i][0] - m), e1 = expf(lg[i][1] - m), e2 = expf(lg[i][2] - m);
        float inv = 1.f / (e0 + e1 + e2);
        float ox = (e0 * v[0].x + e1 * v[1].x + e2 * v[2].x) * inv;
        float oy = (e0 * v[0].y + e1 * v[1].y + e2 * v[2].y) * inv;
        size_t o = ((size_t)(n * 3 + i)) * DD + hh * DH + lane * 2;
        __half2 hv; hv.x = __float2half(ox); hv.y = __float2half(oy);
        *(__half2*)&atth[o] = hv;
    }
}

// residual + LN, in-place on (sh, sl); res is fp16
__global__ void add_ln_kernel(__half* __restrict__ sh, __half* __restrict__ sl,
                              const __half* __restrict__ res,
                              const float* __restrict__ g,
                              const float* __restrict__ b)
{
    int tok = blockIdx.x * 8 + (threadIdx.x >> 5);
    if (tok >= NTOK) return;
    int lane = threadIdx.x & 31;
    __half* ph = sh + (size_t)tok * DD;
    __half* pl = sl + (size_t)tok * DD;
    const __half* q = res + (size_t)tok * DD;
    float v[8];
    float sum = 0.f, sq = 0.f;
    #pragma unroll
    for (int i = 0; i < 4; i++) {
        __half2 ah = *(const __half2*)&ph[lane * 8 + i * 2];
        __half2 al = *(const __half2*)&pl[lane * 8 + i * 2];
        __half2 c  = *(const __half2*)&q[lane * 8 + i * 2];
        float w0 = __half2float(ah.x) + __half2float(al.x) + __half2float(c.x);
        float w1 = __half2float(ah.y) + __half2float(al.y) + __half2float(c.y);
        v[i * 2 + 0] = w0; v[i * 2 + 1] = w1;
        sum += w0 + w1;
        sq  += w0 * w0 + w1 * w1;
    }
    #pragma unroll
    for (int o = 16; o; o >>= 1) {
        sum += __shfl_xor_sync(0xFFFFFFFFu, sum, o);
        sq  += __shfl_xor_sync(0xFFFFFFFFu, sq, o);
    }
    float mean = sum * (1.f / DD);
    float var  = sq * (1.f / DD) - mean * mean;
    float inv  = rsqrtf(var + 1e-5f);
    #pragma unroll
    for (int i = 0; i < 4; i++) {
        int d = lane * 8 + i * 2;
        float y0 = (v[i * 2 + 0] - mean) * inv * g[d + 0] + b[d + 0];
        float y1 = (v[i * 2 + 1] - mean) * inv * g[d + 1] + b[d + 1];
        split_store(&ph[d], &pl[d], y0, y1);
    }
}

__global__ void final_ln_kernel(const __half* __restrict__ sh, const __half* __restrict__ sl,
                                const float* __restrict__ g,
                                const float* __restrict__ b,
                                float* __restrict__ out)
{
    int n = blockIdx.x * 8 + (threadIdx.x >> 5);
    if (n >= NN) return;
    int lane = threadIdx.x & 31;
    const __half* ph = sh + (size_t)n * 3 * DD;
    const __half* pl = sl + (size_t)n * 3 * DD;
    float v[8];
    float sum = 0.f, sq = 0.f;
    #pragma unroll
    for (int i = 0; i < 4; i++) {
        __half2 ah = *(const __half2*)&ph[lane * 8 + i * 2];
        __half2 al = *(const __half2*)&pl[lane * 8 + i * 2];
        float w0 = __half2float(ah.x) + __half2float(al.x);
        float w1 = __half2float(ah.y) + __half2float(al.y);
        v[i * 2 + 0] = w0; v[i * 2 + 1] = w1;
        sum += w0 + w1;
        sq  += w0 * w0 + w1 * w1;
    }
    #pragma unroll
    for (int o = 16; o; o >>= 1) {
        sum += __shfl_xor_sync(0xFFFFFFFFu, sum, o);
        sq  += __shfl_xor_sync(0xFFFFFFFFu, sq, o);
    }
    float mean = sum * (1.f / DD);
    float var  = sq * (1.f / DD) - mean * mean;
    float inv  = rsqrtf(var + 1e-5f);
    #pragma unroll
    for (int i = 0; i < 8; i++) {
        int d = lane * 8 + i;
        out[(size_t)n * DD + d] = (v[i] - mean) * inv * g[d] + b[d];
    }
}

// ================= host side =================
template<bool BIAS, bool RELU, bool OUTF, bool OUTH>
static void run_gemm_tc(const __half* Ah, const __half* Bh,
                        const float* bias, float* Cf, __half* Ch,
                        int M, int Nn, int K)
{
    cudaFuncSetAttribute(gemm_mma_kernel<BIAS, RELU, OUTF, OUTH>,
                         cudaFuncAttributeMaxDynamicSharedMemorySize, GM_SMEM);
    dim3 grid(Nn / 128, (M + 127) / 128);
    gemm_mma_kernel<BIAS, RELU, OUTF, OUTH><<<grid, 256, GM_SMEM>>>(
        Ah, Bh, bias, Cf, Ch, M, Nn, K);
}

extern "C" void kernel_launch(void* const* d_in, const int* in_sizes, int n_in,
                              void* d_out, int out_size)
{
    const float* x        = (const float*)d_in[0];
    const int*   ei       = (const int*)  d_in[1];
    const float* gat1_W   = (const float*)d_in[2];
    const float* gat1_b   = (const float*)d_in[3];
    const float* gat1_as  = (const float*)d_in[4];
    const float* gat1_ad  = (const float*)d_in[5];
    const float* gat2_W   = (const float*)d_in[6];
    const float* gat2_b   = (const float*)d_in[7];
    const float* gat2_as  = (const float*)d_in[8];
    const float* gat2_ad  = (const float*)d_in[9];
    const float* cls      = (const float*)d_in[10];
    const float* pos      = (const float*)d_in[11];
    const float* Wqkv     = (const float*)d_in[12];
    const float* bqkv     = (const float*)d_in[13];
    const float* Wo       = (const float*)d_in[14];
    const float* bo       = (const float*)d_in[15];
    const float* ln1_g    = (const float*)d_in[16];
    const float* ln1_b    = (const float*)d_in[17];
    const float* ln2_g    = (const float*)d_in[18];
    const float* ln2_b    = (const float*)d_in[19];
    const float* Wff1     = (const float*)d_in[20];
    const float* bff1     = (const float*)d_in[21];
    const float* Wff2     = (const float*)d_in[22];
    const float* bff2     = (const float*)d_in[23];
    const float* norm_g   = (const float*)d_in[24];
    const float* norm_b   = (const float*)d_in[25];
    float* out = (float*)d_out;

    float *h, *s, *t;
    cudaGetSymbolAddress((void**)&h, g_h);
    cudaGetSymbolAddress((void**)&s, g_s);
    cudaGetSymbolAddress((void**)&t, g_t);

    int *cnt, *slot, *rows, *csrc;
    cudaGetSymbolAddress((void**)&cnt,  g_cnt);
    cudaGetSymbolAddress((void**)&slot, g_slot);
    cudaGetSymbolAddress((void**)&rows, g_rows);
    cudaGetSymbolAddress((void**)&csrc, g_csrc);

    __half *xh, *x1h, *x2h, *seqh, *seql, *qkvh, *atth, *tmph, *ffh, *wbh;
    cudaGetSymbolAddress((void**)&xh,   g_xh);
    cudaGetSymbolAddress((void**)&x1h,  g_x1h);
    cudaGetSymbolAddress((void**)&x2h,  g_x2h);
    cudaGetSymbolAddress((void**)&seqh, g_seqh);
    cudaGetSymbolAddress((void**)&seql, g_seql);
    cudaGetSymbolAddress((void**)&qkvh, g_qkvh);
    cudaGetSymbolAddress((void**)&atth, g_atth);
    cudaGetSymbolAddress((void**)&tmph, g_tmph);
    cudaGetSymbolAddress((void**)&ffh,  g_ffh);
    cudaGetSymbolAddress((void**)&wbh,  g_wbh);

    // ---- CSR build ----
    fill0i_kernel<<<(NN + 255) / 256, 256>>>(cnt, NN);
    hist_kernel<<<(ETOT + 255) / 256, 256>>>(ei, cnt, slot);
    scan_kernel<<<1, 1024>>>(cnt, rows);
    scatter_kernel<<<(ETOT + 255) / 256, 256>>>(ei, rows, slot, csrc);

    // ---- conversions ----
    round_kernel<<<(NN * DIN + 255) / 256, 256>>>(x, xh, NN * DIN);
    round_kernel<<<(DD * DIN + 255) / 256, 256>>>(gat1_W, wbh + WOFF_W1, DD * DIN);
    round_kernel<<<(DD * DD + 255) / 256, 256>>>(gat2_W, wbh + WOFF_W2, DD * DD);
    round_kernel<<<(2 * 3 * DD * DD + 255) / 256, 256>>>(Wqkv, wbh + WOFF_QKV, 2 * 3 * DD * DD);
    round_kernel<<<(2 * DD * DD + 255) / 256, 256>>>(Wo, wbh + WOFF_WO, 2 * DD * DD);
    round_kernel<<<(2 * 4 * DD * DD + 255) / 256, 256>>>(Wff1, wbh + WOFF_F1, 2 * 4 * DD * DD);
    round_kernel<<<(2 * DD * 4 * DD + 255) / 256, 256>>>(Wff2, wbh + WOFF_F2, 2 * DD * 4 * DD);

    // ---- GAT layer 1 ----
    run_gemm_tc<false, false, true, false>(xh, wbh + WOFF_W1, nullptr, h, nullptr, NN, DD, DIN);
    dots_kernel<<<(NN + 7) / 8, 256>>>(h, gat1_as, gat1_ad, s, t);
    gather_kernel<<<(NN + 3) / 4, 256>>>(rows, csrc, s, t, h, gat1_b, x1h);

    // ---- GAT layer 2 ----
    run_gemm_tc<false, false, true, false>(x1h, wbh + WOFF_W2, nullptr, h, nullptr, NN, DD, DD);
    dots_kernel<<<(NN + 7) / 8, 256>>>(h, gat2_as, gat2_ad, s, t);
    gather_kernel<<<(NN + 3) / 4, 256>>>(rows, csrc, s, t, h, gat2_b, x2h);

    // ---- build sequence (hi/lo residual stream) ----
    build_seq_kernel<<<(unsigned)(((size_t)NTOK * DD + 255) / 256), 256>>>(
        x1h, x2h, cls, pos, seqh, seql);

    // ---- transformer layers ----
    for (int l = 0; l < 2; l++) {
        const __half* wqh  = wbh + WOFF_QKV + (size_t)l * 3 * DD * DD;
        const __half* woh  = wbh + WOFF_WO  + (size_t)l * DD * DD;
        const __half* wf1h = wbh + WOFF_F1  + (size_t)l * 4 * DD * DD;
        const __half* wf2h = wbh + WOFF_F2  + (size_t)l * DD * 4 * DD;

        run_gemm_tc<true, false, false, true>(seqh, wqh, bqkv + (size_t)l * 3 * DD,
                                              nullptr, qkvh, NTOK, 3 * DD, DD);
        attn_kernel<<<(NN * NHEAD + 7) / 8, 256>>>(qkvh, atth);
        run_gemm_tc<true, false, false, true>(atth, woh, bo + (size_t)l * DD,
                                              nullptr, tmph, NTOK, DD, DD);
        add_ln_kernel<<<(NTOK + 7) / 8, 256>>>(seqh, seql, tmph, ln1_g + l * DD, ln1_b + l * DD);
        run_gemm_tc<true, true, false, true>(seqh, wf1h, bff1 + (size_t)l * 4 * DD,
                                             nullptr, ffh, NTOK, 4 * DD, DD);
        run_gemm_tc<true, false, false, true>(ffh, wf2h, bff2 + (size_t)l * DD,
                                              nullptr, tmph, NTOK, DD, 4 * DD);
        add_ln_kernel<<<(NTOK + 7) / 8, 256>>>(seqh, seql, tmph, ln2_g + l * DD, ln2_b + l * DD);
    }

    // ---- final LN on CLS token ----
    final_ln_kernel<<<(NN + 7) / 8, 256>>>(seqh, seql, norm_g, norm_b, out);
}

// round 14
// speedup vs baseline: 2.7275x; 1.0119x over previous
#include <cuda_runtime.h>
#include <cuda_fp16.h>
#include <cstdint>
#include <cstdio>

// ---------------- problem constants ----------------
#define NN      50000
#define EE      320000
#define ETOT    (EE + NN)
#define DIN     128
#define DD      256
#define NTOK    (NN * 3)
#define NHEAD   4
#define DH      64
#define NEGS    0.2f

// ---------------- fp32 scratch ----------------
__device__ float g_s  [NN];
__device__ float g_t  [NN];

// ---------------- CSR graph scratch ----------------
__device__ int g_cnt [NN];
__device__ int g_slot[ETOT];
__device__ int g_rows[NN + 1];
__device__ int g_csrc[ETOT];

// ---------------- fp16 activation buffers ----------------
__device__ __half g_hh  [(size_t)NN * DD];      // GAT projection (fp16)
__device__ __half g_xh  [(size_t)NN * DIN];
__device__ __half g_x1h [(size_t)NN * DD];
__device__ __half g_x2h [(size_t)NN * DD];
__device__ __half g_seqh[(size_t)NTOK * DD];    // residual stream hi
__device__ __half g_seql[(size_t)NTOK * DD];    // residual stream lo (fp32-exact carrier)
__device__ __half g_qkvh[(size_t)NTOK * 3 * DD];
__device__ __half g_atth[(size_t)NTOK * DD];
__device__ __half g_ffh [(size_t)NTOK * 4 * DD];
// weight pool (fp16-rounded)
#define WOFF_W1   0
#define WOFF_W2   32768
#define WOFF_QKV  98304
#define WOFF_WO   491520
#define WOFF_F1   622592
#define WOFF_F2   1146880
#define WTOT      1671168
__device__ __half g_wbh[WTOT];

// ================= warp-mma helpers =================
__device__ __forceinline__ uint32_t smem_u32(const void* p) {
    uint32_t a;
    asm("{ .reg .u64 t; cvta.to.shared.u64 t, %1; cvt.u32.u64 %0, t; }" : "=r"(a) : "l"(p));
    return a;
}

#define LDM4(r, addr) \
    asm volatile("ldmatrix.sync.aligned.m8n8.x4.shared.b16 {%0,%1,%2,%3}, [%4];" \
        : "=r"((r)[0]), "=r"((r)[1]), "=r"((r)[2]), "=r"((r)[3]) : "r"(addr))
#define MMA16816(c, a, b) \
    asm volatile("mma.sync.aligned.m16n8k16.row.col.f32.f16.f16.f32 " \
        "{%0,%1,%2,%3}, {%4,%5,%6,%7}, {%8,%9}, {%0,%1,%2,%3};" \
        : "+f"((c)[0]), "+f"((c)[1]), "+f"((c)[2]), "+f"((c)[3]) \
        : "r"((a)[0]), "r"((a)[1]), "r"((a)[2]), "r"((a)[3]), "r"((b)[0]), "r"((b)[1]))
#define CP_ASYNC(dst, src, sz) \
    asm volatile("cp.async.cg.shared.global [%0], [%1], 16, %2;" :: "r"(dst), "l"(src), "r"(sz))
#define CP_COMMIT() asm volatile("cp.async.commit_group;" ::: "memory")

__device__ __forceinline__ void split_store(__half* hp, __half* lp, float a, float b) {
    __half h0 = __float2half(a), h1 = __float2half(b);
    __half2 hv; hv.x = h0; hv.y = h1;
    __half2 lv;
    lv.x = __float2half(a - __half2float(h0));
    lv.y = __float2half(b - __half2float(h1));
    *(__half2*)hp = hv;
    *(__half2*)lp = lv;
}

// ================= fp16 GEMM via mma.sync (generic N) ====================
// C[M,N] = Ah[M,K] * Bh[N,K]^T. BM=128, BN=128, BK=32; 256 threads.
#define RSB     80
#define MAT_SZ  10240
#define STG_SZ  20480
#define GM_SMEM (3 * STG_SZ)   // 61440

template<bool BIAS, bool RELU>
__global__ __launch_bounds__(256, 2) void gemm_mma_kernel(
    const __half* __restrict__ Ah, const __half* __restrict__ Bh,
    const float* __restrict__ bias, __half* __restrict__ Ch,
    int M, int Nn, int K)
{
    extern __shared__ char smraw[];
    const uint32_t sb = smem_u32(smraw);
    const int tid = threadIdx.x, wid = tid >> 5, lane = tid & 31;
    const int wm = wid & 1, wn = wid >> 1;
    const int m0 = blockIdx.y * 128, n0 = blockIdx.x * 128;

    float acc[4][4][4];
    #pragma unroll
    for (int mt = 0; mt < 4; mt++)
        #pragma unroll
        for (int nt = 0; nt < 4; nt++)
            #pragma unroll
            for (int c = 0; c < 4; c++) acc[mt][nt][c] = 0.f;

    const int a_row  = (lane & 7) + ((lane >> 3) & 1) * 8;
    const int a_k    = (lane >> 4) * 8;
    const int b_row4 = (lane & 7) + ((lane >> 4) & 1) * 8;
    const int b_k4   = ((lane >> 3) & 1) * 8;

    const int T = K >> 5;

    auto load_stage = [&](int buf, int k0) {
        uint32_t base = sb + buf * STG_SZ;
        #pragma unroll
        for (int it = 0; it < 4; it++) {
            int i    = tid + it * 256;
            int mat  = i >> 9;
            int rem  = i & 511;
            int row  = rem >> 2;
            int ch   = rem & 3;
            uint32_t dst = base + mat * MAT_SZ + row * RSB + ch * 16;
            const __half* src;
            int sz = 16;
            if (mat == 0) {
                src = Ah;
                int gm = m0 + row;
                if (gm >= M) sz = 0;
                src += (size_t)gm * K + k0 + ch * 8;
            } else {
                src = Bh + (size_t)(n0 + row) * K + k0 + ch * 8;
            }
            CP_ASYNC(dst, src, sz);
        }
        CP_COMMIT();
    };

    auto compute = [&](int buf) {
        uint32_t base  = sb + buf * STG_SZ;
        uint32_t aB    = base + (wm * 64) * RSB;
        uint32_t bB    = base + MAT_SZ + (wn * 32) * RSB;
        #pragma unroll
        for (int ks = 0; ks < 32; ks += 16) {
            uint32_t bh[4][2];
            #pragma unroll
            for (int ntp = 0; ntp < 2; ntp++) {
                uint32_t bd = bB + (ntp * 16 + b_row4) * RSB + (ks + b_k4) * 2;
                uint32_t r4[4];
                LDM4(r4, bd);
                bh[2 * ntp][0] = r4[0]; bh[2 * ntp][1] = r4[1];
                bh[2 * ntp + 1][0] = r4[2]; bh[2 * ntp + 1][1] = r4[3];
            }
            #pragma unroll
            for (int mt = 0; mt < 4; mt++) {
                uint32_t ah4[4];
                uint32_t ad = aB + (mt * 16 + a_row) * RSB + (ks + a_k) * 2;
                LDM4(ah4, ad);
                #pragma unroll
                for (int nt = 0; nt < 4; nt++) MMA16816(acc[mt][nt], ah4, bh[nt]);
            }
        }
    };

    load_stage(0, 0);
    if (T > 1) load_stage(1, 32);
    for (int t = 0; t < T; t++) {
        if (t + 1 < T) asm volatile("cp.async.wait_group 1;" ::: "memory");
        else           asm volatile("cp.async.wait_group 0;" ::: "memory");
        __syncthreads();
        if (t + 2 < T) load_stage((t + 2) % 3, (t + 2) << 5);
        compute(t % 3);
    }

    const int r0    = lane >> 2;
    const int cpair = (lane & 3) * 2;
    #pragma unroll
    for (int mt = 0; mt < 4; mt++) {
        int gm1 = m0 + wm * 64 + mt * 16 + r0;
        int gm2 = gm1 + 8;
        #pragma unroll
        for (int nt = 0; nt < 4; nt++) {
            int gn = n0 + wn * 32 + nt * 8 + cpair;
            float b0 = 0.f, b1 = 0.f;
            if (BIAS) { float2 bb = *(const float2*)&bias[gn]; b0 = bb.x; b1 = bb.y; }
            float v0 = acc[mt][nt][0] + b0, v1 = acc[mt][nt][1] + b1;
            float v2 = acc[mt][nt][2] + b0, v3 = acc[mt][nt][3] + b1;
            if (RELU) {
                v0 = fmaxf(v0, 0.f); v1 = fmaxf(v1, 0.f);
                v2 = fmaxf(v2, 0.f); v3 = fmaxf(v3, 0.f);
            }
            if (gm1 < M) {
                __half2 hv; hv.x = __float2half(v0); hv.y = __float2half(v1);
                *(__half2*)&Ch[(size_t)gm1 * Nn + gn] = hv;
            }
            if (gm2 < M) {
                __half2 hv; hv.x = __float2half(v2); hv.y = __float2half(v3);
                *(__half2*)&Ch[(size_t)gm2 * Nn + gn] = hv;
            }
        }
    }
}

// ================= fused GEMM + residual + LayerNorm (N=256) =============
// seq = LN(seq + bias + A*B^T). BM=128, BN=256, 512 threads = 16 warps (2m x 8n).
#define FL_A_SZ  10240                 // 128 rows * 80B
#define FL_B_SZ  20480                 // 256 rows * 80B
#define FL_STG   (FL_A_SZ + FL_B_SZ)   // 30720
#define FL_RED   (3 * FL_STG)          // 92160
#define FL_SMEM  (FL_RED + 8192)       // 100352

__global__ __launch_bounds__(512, 1) void gemm_ln_kernel(
    const __half* __restrict__ Ah, const __half* __restrict__ Bh,
    const float* __restrict__ bias,
    __half* __restrict__ sh, __half* __restrict__ sl,
    const float* __restrict__ lng, const float* __restrict__ lnb,
    int M, int K)
{
    extern __shared__ char smraw[];
    const uint32_t sb = smem_u32(smraw);
    const int tid = threadIdx.x, wid = tid >> 5, lane = tid & 31;
    const int wm = wid & 1, wn = wid >> 1;          // wn 0..7
    const int m0 = blockIdx.x * 128;

    float acc[4][4][4];
    #pragma unroll
    for (int mt = 0; mt < 4; mt++)
        #pragma unroll
        for (int nt = 0; nt < 4; nt++)
            #pragma unroll
            for (int c = 0; c < 4; c++) acc[mt][nt][c] = 0.f;

    const int a_row  = (lane & 7) + ((lane >> 3) & 1) * 8;
    const int a_k    = (lane >> 4) * 8;
    const int b_row4 = (lane & 7) + ((lane >> 4) & 1) * 8;
    const int b_k4   = ((lane >> 3) & 1) * 8;

    const int T = K >> 5;

    auto load_stage = [&](int buf, int k0) {
        uint32_t base = sb + buf * FL_STG;
        #pragma unroll
        for (int it = 0; it < 3; it++) {
            int i = tid + it * 512;                 // 0..1535
            uint32_t dst;
            const __half* src;
            int sz = 16;
            if (i < 512) {
                int row = i >> 2, ch = i & 3;
                dst = base + row * RSB + ch * 16;
                int gm = m0 + row;
                if (gm >= M) sz = 0;
                src = Ah + (size_t)gm * K + k0 + ch * 8;
            } else {
                int r = i - 512;                    // 0..1023
                int row = r >> 2, ch = r & 3;       // row 0..255
                dst = base + FL_A_SZ + row * RSB + ch * 16;
                src = Bh + (size_t)row * K + k0 + ch * 8;
            }
            CP_ASYNC(dst, src, sz);
        }
        CP_COMMIT();
    };

    auto compute = [&](int buf) {
        uint32_t base  = sb + buf * FL_STG;
        uint32_t aB    = base + (wm * 64) * RSB;
        uint32_t bB    = base + FL_A_SZ + (wn * 32) * RSB;
        #pragma unroll
        for (int ks = 0; ks < 32; ks += 16) {
            uint32_t bh[4][2];
            #pragma unroll
            for (int ntp = 0; ntp < 2; ntp++) {
                uint32_t bd = bB + (ntp * 16 + b_row4) * RSB + (ks + b_k4) * 2;
                uint32_t r4[4];
                LDM4(r4, bd);
                bh[2 * ntp][0] = r4[0]; bh[2 * ntp][1] = r4[1];
                bh[2 * ntp + 1][0] = r4[2]; bh[2 * ntp + 1][1] = r4[3];
            }
            #pragma unroll
            for (int mt = 0; mt < 4; mt++) {
                uint32_t ah4[4];
                uint32_t ad = aB + (mt * 16 + a_row) * RSB + (ks + a_k) * 2;
                LDM4(ah4, ad);
                #pragma unroll
                for (int nt = 0; nt < 4; nt++) MMA16816(acc[mt][nt], ah4, bh[nt]);
            }
        }
    };

    load_stage(0, 0);
    if (T > 1) load_stage(1, 32);
    for (int t = 0; t < T; t++) {
        if (t + 1 < T) asm volatile("cp.async.wait_group 1;" ::: "memory");
        else           asm volatile("cp.async.wait_group 0;" ::: "memory");
        __syncthreads();
        if (t + 2 < T) load_stage((t + 2) % 3, (t + 2) << 5);
        compute(t % 3);
    }

    // ------- fused epilogue: w = acc + bias + (sh+sl); LN(w) -> sh, sl -------
    const int r0    = lane >> 2;
    const int cpair = (lane & 3) * 2;
    float* red_sum = (float*)(smraw + FL_RED);          // [128][8]
    float* red_sq  = (float*)(smraw + FL_RED + 4096);   // [128][8]

    #pragma unroll
    for (int mt = 0; mt < 4; mt++) {
        int row1 = wm * 64 + mt * 16 + r0;
        int gm1 = m0 + row1, gm2 = gm1 + 8;
        float s0 = 0.f, q0 = 0.f, s1 = 0.f, q1 = 0.f;
        #pragma unroll
        for (int nt = 0; nt < 4; nt++) {
            int gn = wn * 32 + nt * 8 + cpair;
            float2 bb = *(const float2*)&bias[gn];
            float ra = 0.f, rb = 0.f, rc = 0.f, rd = 0.f;
            if (gm1 < M) {
                __half2 hh1 = *(const __half2*)&sh[(size_t)gm1 * DD + gn];
                __half2 ll1 = *(const __half2*)&sl[(size_t)gm1 * DD + gn];
                ra = __half2float(hh1.x) + __half2float(ll1.x);
                rb = __half2float(hh1.y) + __half2float(ll1.y);
            }
            if (gm2 < M) {
                __half2 hh2 = *(const __half2*)&sh[(size_t)gm2 * DD + gn];
                __half2 ll2 = *(const __half2*)&sl[(size_t)gm2 * DD + gn];
                rc = __half2float(hh2.x) + __half2float(ll2.x);
                rd = __half2float(hh2.y) + __half2float(ll2.y);
            }
            float w0 = acc[mt][nt][0] + bb.x + ra;
            float w1 = acc[mt][nt][1] + bb.y + rb;
            float w2 = acc[mt][nt][2] + bb.x + rc;
            float w3 = acc[mt][nt][3] + bb.y + rd;
            acc[mt][nt][0] = w0; acc[mt][nt][1] = w1;
            acc[mt][nt][2] = w2; acc[mt][nt][3] = w3;
            s0 += w0 + w1; q0 += w0 * w0 + w1 * w1;
            s1 += w2 + w3; q1 += w2 * w2 + w3 * w3;
        }
        s0 += __shfl_xor_sync(0xFFFFFFFFu, s0, 1); s0 += __shfl_xor_sync(0xFFFFFFFFu, s0, 2);
        q0 += __shfl_xor_sync(0xFFFFFFFFu, q0, 1); q0 += __shfl_xor_sync(0xFFFFFFFFu, q0, 2);
        s1 += __shfl_xor_sync(0xFFFFFFFFu, s1, 1); s1 += __shfl_xor_sync(0xFFFFFFFFu, s1, 2);
        q1 += __shfl_xor_sync(0xFFFFFFFFu, q1, 1); q1 += __shfl_xor_sync(0xFFFFFFFFu, q1, 2);
        if ((lane & 3) == 0) {
            red_sum[row1 * 8 + wn] = s0;       red_sq[row1 * 8 + wn] = q0;
            red_sum[(row1 + 8) * 8 + wn] = s1; red_sq[(row1 + 8) * 8 + wn] = q1;
        }
    }
    __syncthreads();

    #pragma unroll
    for (int mt = 0; mt < 4; mt++) {
        int row1 = wm * 64 + mt * 16 + r0;
        int gm1 = m0 + row1, gm2 = gm1 + 8;
        float su0 = 0.f, sq0 = 0.f, su1 = 0.f, sq1 = 0.f;
        #pragma unroll
        for (int wj = 0; wj < 8; wj++) {
            su0 += red_sum[row1 * 8 + wj];       sq0 += red_sq[row1 * 8 + wj];
            su1 += red_sum[(row1 + 8) * 8 + wj]; sq1 += red_sq[(row1 + 8) * 8 + wj];
        }
        float mean0 = su0 * (1.f / DD);
        float inv0  = rsqrtf(sq0 * (1.f / DD) - mean0 * mean0 + 1e-5f);
        float mean1 = su1 * (1.f / DD);
        float inv1  = rsqrtf(sq1 * (1.f / DD) - mean1 * mean1 + 1e-5f);
        #pragma unroll
        for (int nt = 0; nt < 4; nt++) {
            int gn = wn * 32 + nt * 8 + cpair;
            float2 gg = *(const float2*)&lng[gn];
            float2 bb = *(const float2*)&lnb[gn];
            if (gm1 < M) {
                float y0 = (acc[mt][nt][0] - mean0) * inv0 * gg.x + bb.x;
                float y1 = (acc[mt][nt][1] - mean0) * inv0 * gg.y + bb.y;
                split_store(&sh[(size_t)gm1 * DD + gn], &sl[(size_t)gm1 * DD + gn], y0, y1);
            }
            if (gm2 < M) {
                float y2 = (acc[mt][nt][2] - mean1) * inv1 * gg.x + bb.x;
                float y3 = (acc[mt][nt][3] - mean1) * inv1 * gg.y + bb.y;
                split_store(&sh[(size_t)gm2 * DD + gn], &sl[(size_t)gm2 * DD + gn], y2, y3);
            }
        }
    }
}

// ================= CSR build kernels =================
__global__ void fill0i_kernel(int* __restrict__ p, int n) {
    int i = blockIdx.x * 256 + threadIdx.x;
    if (i < n) p[i] = 0;
}

__global__ void hist_kernel(const int* __restrict__ ei, int* __restrict__ cnt,
                            int* __restrict__ slot)
{
    int e = blockIdx.x * 256 + threadIdx.x;
    if (e >= ETOT) return;
    int dst = (e < EE) ? ei[EE + e] : e - EE;
    slot[e] = atomicAdd(&cnt[dst], 1);
}

__global__ void scan_kernel(const int* __restrict__ cnt, int* __restrict__ rows) {
    __shared__ int wsum[32];
    int tid = threadIdx.x;
    const int CH = (NN + 1023) / 1024;
    int beg = tid * CH;
    int ssum = 0;
    for (int i = 0; i < CH; i++) {
        int idx = beg + i;
        if (idx < NN) ssum += cnt[idx];
    }
    int lane = tid & 31, wid = tid >> 5;
    int v = ssum;
    #pragma unroll
    for (int o = 1; o < 32; o <<= 1) {
        int u = __shfl_up_sync(0xFFFFFFFFu, v, o);
        if (lane >= o) v += u;
    }
    if (lane == 31) wsum[wid] = v;
    __syncthreads();
    if (wid == 0) {
        int w = wsum[lane];
        #pragma unroll
        for (int o = 1; o < 32; o <<= 1) {
            int u = __shfl_up_sync(0xFFFFFFFFu, w, o);
            if (lane >= o) w += u;
        }
        wsum[lane] = w;
    }
    __syncthreads();
    int off = v - ssum + (wid ? wsum[wid - 1] : 0);
    for (int i = 0; i < CH; i++) {
        int idx = beg + i;
        if (idx < NN) { rows[idx] = off; off += cnt[idx]; }
    }
    if (tid == 0) rows[NN] = ETOT;
}

__global__ void scatter_kernel(const int* __restrict__ ei, const int* __restrict__ rows,
                               const int* __restrict__ slot, int* __restrict__ csrc)
{
    int e = blockIdx.x * 256 + threadIdx.x;
    if (e >= ETOT) return;
    int src, dst;
    if (e < EE) { src = ei[e]; dst = ei[EE + e]; }
    else        { src = dst = e - EE; }
    csrc[rows[dst] + slot[e]] = src;
}

// ================= GAT gather (CSR, no atomics; fp16 h) ==================
__global__ void gather_kernel(const int* __restrict__ rows, const int* __restrict__ csrc,
                              const float* __restrict__ s, const float* __restrict__ t,
                              const __half* __restrict__ hh, const float* __restrict__ b,
                              __half* __restrict__ oh)
{
    int n = blockIdx.x * 4 + (threadIdx.x >> 6);
    if (n >= NN) return;
    int sub = threadIdx.x & 63;
    float tn = __ldg(&t[n]);
    int beg = __ldg(&rows[n]), end = __ldg(&rows[n + 1]);
    float a0 = 0.f, a1 = 0.f, a2 = 0.f, a3 = 0.f, den = 0.f;
    for (int i = beg; i < end; i++) {
        int src = __ldg(&csrc[i]);
        float x = __ldg(&s[src]) + tn;
        float ex = expf(x > 0.f ? x : NEGS * x);
        den += ex;
        size_t o = (size_t)src * DD + sub * 4;
        __half2 h01 = *(const __half2*)&hh[o];
        __half2 h23 = *(const __half2*)&hh[o + 2];
        a0 += ex * __half2float(h01.x); a1 += ex * __half2float(h01.y);
        a2 += ex * __half2float(h23.x); a3 += ex * __half2float(h23.y);
    }
    float inv = 1.f / den;
    float4 bb = *(const float4*)&b[sub * 4];
    float v0 = fmaxf(a0 * inv + bb.x, 0.f);
    float v1 = fmaxf(a1 * inv + bb.y, 0.f);
    float v2 = fmaxf(a2 * inv + bb.z, 0.f);
    float v3 = fmaxf(a3 * inv + bb.w, 0.f);
    size_t o = (size_t)n * DD + sub * 4;
    __half2 p0; p0.x = __float2half(v0); p0.y = __float2half(v1);
    __half2 p1; p1.x = __float2half(v2); p1.y = __float2half(v3);
    *(__half2*)&oh[o]     = p0;
    *(__half2*)&oh[o + 2] = p1;
}

// ================= small kernels =================
__global__ void round_kernel(const float* __restrict__ s, __half* __restrict__ h, int n)
{
    int i = blockIdx.x * 256 + threadIdx.x;
    if (i < n) h[i] = __float2half(s[i]);
}

__global__ void dots_kernel(const __half* __restrict__ hh,
                            const float* __restrict__ asrc,
                            const float* __restrict__ adst,
                            float* __restrict__ s, float* __restrict__ t)
{
    int n = blockIdx.x * 8 + (threadIdx.x >> 5);
    if (n >= NN) return;
    int lane = threadIdx.x & 31;
    const __half* row = hh + (size_t)n * DD;
    float ps = 0.f, pt = 0.f;
    #pragma unroll
    for (int i = 0; i < 4; i++) {
        int d = lane * 8 + i * 2;
        __half2 hv = *(const __half2*)&row[d];
        float v0 = __half2float(hv.x), v1 = __half2float(hv.y);
        ps += v0 * asrc[d] + v1 * asrc[d + 1];
        pt += v0 * adst[d] + v1 * adst[d + 1];
    }
    #pragma unroll
    for (int o = 16; o; o >>= 1) {
        ps += __shfl_xor_sync(0xFFFFFFFFu, ps, o);
        pt += __shfl_xor_sync(0xFFFFFFFFu, pt, o);
    }
    if (lane == 0) { s[n] = ps; t[n] = pt; }
}

// build seq (hi/lo residual stream) from x1,x2 fp16 + cls + pos
__global__ void build_seq_kernel(const __half* __restrict__ x1h,
                                 const __half* __restrict__ x2h,
                                 const float* __restrict__ cls,
                                 const float* __restrict__ pos,
                                 __half* __restrict__ sh,
                                 __half* __restrict__ sl)
{
    size_t i = (size_t)blockIdx.x * 256 + threadIdx.x;
    if (i >= (size_t)NTOK * DD) return;
    int d = (int)(i & 255);
    size_t tok = i >> 8;
    int which = (int)(tok % 3);
    size_t n = tok / 3;
    float v;
    if (which == 0)      v = cls[d];
    else if (which == 1) v = __half2float(x1h[n * DD + d]);
    else                 v = __half2float(x2h[n * DD + d]);
    v += pos[which * DD + d];
    __half a = __float2half(v);
    sh[i] = a;
    sl[i] = __float2half(v - __half2float(a));
}

// attention from fp16 qkv, fp16 output
__global__ void attn_kernel(const __half* __restrict__ qh, __half* __restrict__ atth)
{
    int w = blockIdx.x * 8 + (threadIdx.x >> 5);
    if (w >= NN * NHEAD) return;
    int lane = threadIdx.x & 31;
    int n = w >> 2, hh = w & 3;
    size_t base = (size_t)n * 3 * (3 * DD) + hh * DH + lane * 2;
    float2 q[3], k[3], v[3];
    #pragma unroll
    for (int i = 0; i < 3; i++) {
        size_t o = base + (size_t)i * (3 * DD);
        __half2 a;
        a = *(const __half2*)(qh + o);
        q[i].x = __half2float(a.x); q[i].y = __half2float(a.y);
        a = *(const __half2*)(qh + o + DD);
        k[i].x = __half2float(a.x); k[i].y = __half2float(a.y);
        a = *(const __half2*)(qh + o + 2 * DD);
        v[i].x = __half2float(a.x); v[i].y = __half2float(a.y);
    }
    float lg[3][3];
    #pragma unroll
    for (int i = 0; i < 3; i++)
        #pragma unroll
        for (int j = 0; j < 3; j++) {
            float p = q[i].x * k[j].x + q[i].y * k[j].y;
            #pragma unroll
            for (int o = 16; o; o >>= 1) p += __shfl_xor_sync(0xFFFFFFFFu, p, o);
            lg[i][j] = p * 0.125f;
        }
    #pragma unroll
    for (int i = 0; i < 3; i++) {
        float m  = fmaxf(lg[i][0], fmaxf(lg[i][1], lg[i][2]));
        float e0 = expf(lg[i][0] - m), e1 = expf(lg[i][1] - m), e2 = expf(lg[i][2] - m);
        float inv = 1.f / (e0 + e1 + e2);
        float ox = (e0 * v[0].x + e1 * v[1].x + e2 * v[2].x) * inv;
        float oy = (e0 * v[0].y + e1 * v[1].y + e2 * v[2].y) * inv;
        size_t o = ((size_t)(n * 3 + i)) * DD + hh * DH + lane * 2;
        __half2 hv; hv.x = __float2half(ox); hv.y = __float2half(oy);
        *(__half2*)&atth[o] = hv;
    }
}

__global__ void final_ln_kernel(const __half* __restrict__ sh, const __half* __restrict__ sl,
                                const float* __restrict__ g,
                                const float* __restrict__ b,
                                float* __restrict__ out)
{
    int n = blockIdx.x * 8 + (threadIdx.x >> 5);
    if (n >= NN) return;
    int lane = threadIdx.x & 31;
    const __half* ph = sh + (size_t)n * 3 * DD;
    const __half* pl = sl + (size_t)n * 3 * DD;
    float v[8];
    float sum = 0.f, sq = 0.f;
    #pragma unroll
    for (int i = 0; i < 4; i++) {
        __half2 ah = *(const __half2*)&ph[lane * 8 + i * 2];
        __half2 al = *(const __half2*)&pl[lane * 8 + i * 2];
        float w0 = __half2float(ah.x) + __half2float(al.x);
        float w1 = __half2float(ah.y) + __half2float(al.y);
        v[i * 2 + 0] = w0; v[i * 2 + 1] = w1;
        sum += w0 + w1;
        sq  += w0 * w0 + w1 * w1;
    }
    #pragma unroll
    for (int o = 16; o; o >>= 1) {
        sum += __shfl_xor_sync(0xFFFFFFFFu, sum, o);
        sq  += __shfl_xor_sync(0xFFFFFFFFu, sq, o);
    }
    float mean = sum * (1.f / DD);
    float var  = sq * (1.f / DD) - mean * mean;
    float inv  = rsqrtf(var + 1e-5f);
    #pragma unroll
    for (int i = 0; i < 8; i++) {
        int d = lane * 8 + i;
        out[(size_t)n * DD + d] = (v[i] - mean) * inv * g[d] + b[d];
    }
}

// ================= host side =================
template<bool BIAS, bool RELU>
static void run_gemm_tc(const __half* Ah, const __half* Bh,
                        const float* bias, __half* Ch,
                        int M, int Nn, int K)
{
    cudaFuncSetAttribute(gemm_mma_kernel<BIAS, RELU>,
                         cudaFuncAttributeMaxDynamicSharedMemorySize, GM_SMEM);
    dim3 grid(Nn / 128, (M + 127) / 128);
    gemm_mma_kernel<BIAS, RELU><<<grid, 256, GM_SMEM>>>(Ah, Bh, bias, Ch, M, Nn, K);
}

static void run_gemm_ln(const __half* Ah, const __half* Bh, const float* bias,
                        __half* sh, __half* sl, const float* lng, const float* lnb,
                        int M, int K)
{
    cudaFuncSetAttribute(gemm_ln_kernel,
                         cudaFuncAttributeMaxDynamicSharedMemorySize, FL_SMEM);
    gemm_ln_kernel<<<(M + 127) / 128, 512, FL_SMEM>>>(Ah, Bh, bias, sh, sl, lng, lnb, M, K);
}

extern "C" void kernel_launch(void* const* d_in, const int* in_sizes, int n_in,
                              void* d_out, int out_size)
{
    const float* x        = (const float*)d_in[0];
    const int*   ei       = (const int*)  d_in[1];
    const float* gat1_W   = (const float*)d_in[2];
    const float* gat1_b   = (const float*)d_in[3];
    const float* gat1_as  = (const float*)d_in[4];
    const float* gat1_ad  = (const float*)d_in[5];
    const float* gat2_W   = (const float*)d_in[6];
    const float* gat2_b   = (const float*)d_in[7];
    const float* gat2_as  = (const float*)d_in[8];
    const float* gat2_ad  = (const float*)d_in[9];
    const float* cls      = (const float*)d_in[10];
    const float* pos      = (const float*)d_in[11];
    const float* Wqkv     = (const float*)d_in[12];
    const float* bqkv     = (const float*)d_in[13];
    const float* Wo       = (const float*)d_in[14];
    const float* bo       = (const float*)d_in[15];
    const float* ln1_g    = (const float*)d_in[16];
    const float* ln1_b    = (const float*)d_in[17];
    const float* ln2_g    = (const float*)d_in[18];
    const float* ln2_b    = (const float*)d_in[19];
    const float* Wff1     = (const float*)d_in[20];
    const float* bff1     = (const float*)d_in[21];
    const float* Wff2     = (const float*)d_in[22];
    const float* bff2     = (const float*)d_in[23];
    const float* norm_g   = (const float*)d_in[24];
    const float* norm_b   = (const float*)d_in[25];
    float* out = (float*)d_out;

    float *s, *t;
    cudaGetSymbolAddress((void**)&s, g_s);
    cudaGetSymbolAddress((void**)&t, g_t);

    int *cnt, *slot, *rows, *csrc;
    cudaGetSymbolAddress((void**)&cnt,  g_cnt);
    cudaGetSymbolAddress((void**)&slot, g_slot);
    cudaGetSymbolAddress((void**)&rows, g_rows);
    cudaGetSymbolAddress((void**)&csrc, g_csrc);

    __half *hh, *xh, *x1h, *x2h, *seqh, *seql, *qkvh, *atth, *ffh, *wbh;
    cudaGetSymbolAddress((void**)&hh,   g_hh);
    cudaGetSymbolAddress((void**)&xh,   g_xh);
    cudaGetSymbolAddress((void**)&x1h,  g_x1h);
    cudaGetSymbolAddress((void**)&x2h,  g_x2h);
    cudaGetSymbolAddress((void**)&seqh, g_seqh);
    cudaGetSymbolAddress((void**)&seql, g_seql);
    cudaGetSymbolAddress((void**)&qkvh, g_qkvh);
    cudaGetSymbolAddress((void**)&atth, g_atth);
    cudaGetSymbolAddress((void**)&ffh,  g_ffh);
    cudaGetSymbolAddress((void**)&wbh,  g_wbh);

    // ---- CSR build ----
    fill0i_kernel<<<(NN + 255) / 256, 256>>>(cnt, NN);
    hist_kernel<<<(ETOT + 255) / 256, 256>>>(ei, cnt, slot);
    scan_kernel<<<1, 1024>>>(cnt, rows);
    scatter_kernel<<<(ETOT + 255) / 256, 256>>>(ei, rows, slot, csrc);

    // ---- conversions ----
    round_kernel<<<(NN * DIN + 255) / 256, 256>>>(x, xh, NN * DIN);
    round_kernel<<<(DD * DIN + 255) / 256, 256>>>(gat1_W, wbh + WOFF_W1, DD * DIN);
    round_kernel<<<(DD * DD + 255) / 256, 256>>>(gat2_W, wbh + WOFF_W2, DD * DD);
    round_kernel<<<(2 * 3 * DD * DD + 255) / 256, 256>>>(Wqkv, wbh + WOFF_QKV, 2 * 3 * DD * DD);
    round_kernel<<<(2 * DD * DD + 255) / 256, 256>>>(Wo, wbh + WOFF_WO, 2 * DD * DD);
    round_kernel<<<(2 * 4 * DD * DD + 255) / 256, 256>>>(Wff1, wbh + WOFF_F1, 2 * 4 * DD * DD);
    round_kernel<<<(2 * DD * 4 * DD + 255) / 256, 256>>>(Wff2, wbh + WOFF_F2, 2 * DD * 4 * DD);

    // ---- GAT layer 1 ----
    run_gemm_tc<false, false>(xh, wbh + WOFF_W1, nullptr, hh, NN, DD, DIN);
    dots_kernel<<<(NN + 7) / 8, 256>>>(hh, gat1_as, gat1_ad, s, t);
    gather_kernel<<<(NN + 3) / 4, 256>>>(rows, csrc, s, t, hh, gat1_b, x1h);

    // ---- GAT layer 2 ----
    run_gemm_tc<false, false>(x1h, wbh + WOFF_W2, nullptr, hh, NN, DD, DD);
    dots_kernel<<<(NN + 7) / 8, 256>>>(hh, gat2_as, gat2_ad, s, t);
    gather_kernel<<<(NN + 3) / 4, 256>>>(rows, csrc, s, t, hh, gat2_b, x2h);

    // ---- build sequence (hi/lo residual stream) ----
    build_seq_kernel<<<(unsigned)(((size_t)NTOK * DD + 255) / 256), 256>>>(
        x1h, x2h, cls, pos, seqh, seql);

    // ---- transformer layers ----
    for (int l = 0; l < 2; l++) {
        const __half* wqh  = wbh + WOFF_QKV + (size_t)l * 3 * DD * DD;
        const __half* woh  = wbh + WOFF_WO  + (size_t)l * DD * DD;
        const __half* wf1h = wbh + WOFF_F1  + (size_t)l * 4 * DD * DD;
        const __half* wf2h = wbh + WOFF_F2  + (size_t)l * DD * 4 * DD;

        run_gemm_tc<true, false>(seqh, wqh, bqkv + (size_t)l * 3 * DD, qkvh, NTOK, 3 * DD, DD);
        attn_kernel<<<(NN * NHEAD + 7) / 8, 256>>>(qkvh, atth);
        run_gemm_ln(atth, woh, bo + (size_t)l * DD, seqh, seql,
                    ln1_g + l * DD, ln1_b + l * DD, NTOK, DD);
        run_gemm_tc<true, true>(seqh, wf1h, bff1 + (size_t)l * 4 * DD, ffh, NTOK, 4 * DD, DD);
        run_gemm_ln(ffh, wf2h, bff2 + (size_t)l * DD, seqh, seql,
                    ln2_g + l * DD, ln2_b + l * DD, NTOK, 4 * DD);
    }

    // ---- final LN on CLS token ----
    final_ln_kernel<<<(NN + 7) / 8, 256>>>(seqh, seql, norm_g, norm_b, out);
}

// round 15
// speedup vs baseline: 3.4310x; 1.2579x over previous
#include <cuda_runtime.h>
#include <cuda_fp16.h>
#include <cstdint>
#include <cstdio>

// ---------------- problem constants ----------------
#define NN      50000
#define EE      320000
#define ETOT    (EE + NN)
#define DIN     128
#define DD      256
#define NTOK    (NN * 3)
#define NHEAD   4
#define DH      64
#define NEGS    0.2f

// ---------------- fp32 scratch ----------------
__device__ float g_s  [NN];
__device__ float g_t  [NN];

// ---------------- CSR graph scratch ----------------
__device__ int g_cnt [NN];
__device__ int g_slot[ETOT];
__device__ int g_rows[NN + 1];
__device__ int g_csrc[ETOT];

// ---------------- fp16 activation buffers ----------------
__device__ __half g_hh  [(size_t)NN * DD];
__device__ __half g_xh  [(size_t)NN * DIN];
__device__ __half g_x1h [(size_t)NN * DD];
__device__ __half g_x2h [(size_t)NN * DD];
__device__ __half g_seqh[(size_t)NTOK * DD];
__device__ __half g_seql[(size_t)NTOK * DD];
__device__ __half g_qkvh[(size_t)NTOK * 3 * DD];
__device__ __half g_atth[(size_t)NTOK * DD];
__device__ __half g_ffh [(size_t)NTOK * 4 * DD];
// weight pool (fp16-rounded)
#define WOFF_W1   0
#define WOFF_W2   32768
#define WOFF_QKV  98304
#define WOFF_WO   491520
#define WOFF_F1   622592
#define WOFF_F2   1146880
#define WTOT      1671168
__device__ __half g_wbh[WTOT];

// ================= warp-mma helpers =================
__device__ __forceinline__ uint32_t smem_u32(const void* p) {
    uint32_t a;
    asm("{ .reg .u64 t; cvta.to.shared.u64 t, %1; cvt.u32.u64 %0, t; }" : "=r"(a) : "l"(p));
    return a;
}

#define LDM4(r, addr) \
    asm volatile("ldmatrix.sync.aligned.m8n8.x4.shared.b16 {%0,%1,%2,%3}, [%4];" \
        : "=r"((r)[0]), "=r"((r)[1]), "=r"((r)[2]), "=r"((r)[3]) : "r"(addr))
#define MMA16816(c, a, b) \
    asm volatile("mma.sync.aligned.m16n8k16.row.col.f32.f16.f16.f32 " \
        "{%0,%1,%2,%3}, {%4,%5,%6,%7}, {%8,%9}, {%0,%1,%2,%3};" \
        : "+f"((c)[0]), "+f"((c)[1]), "+f"((c)[2]), "+f"((c)[3]) \
        : "r"((a)[0]), "r"((a)[1]), "r"((a)[2]), "r"((a)[3]), "r"((b)[0]), "r"((b)[1]))
#define CP_ASYNC(dst, src, sz) \
    asm volatile("cp.async.cg.shared.global [%0], [%1], 16, %2;" :: "r"(dst), "l"(src), "r"(sz))
#define CP_COMMIT() asm volatile("cp.async.commit_group;" ::: "memory")

__device__ __forceinline__ void split_store(__half* hp, __half* lp, float a, float b) {
    __half h0 = __float2half(a), h1 = __float2half(b);
    __half2 hv; hv.x = h0; hv.y = h1;
    __half2 lv;
    lv.x = __float2half(a - __half2float(h0));
    lv.y = __float2half(b - __half2float(h1));
    *(__half2*)hp = hv;
    *(__half2*)lp = lv;
}

// ================= fp16 GEMM via mma.sync (generic N, strided A) =========
#define RSB     80
#define MAT_SZ  10240
#define STG_SZ  20480
#define GM_SMEM (3 * STG_SZ)

template<bool BIAS, bool RELU>
__global__ __launch_bounds__(256, 2) void gemm_mma_kernel(
    const __half* __restrict__ Ah, const __half* __restrict__ Bh,
    const float* __restrict__ bias, __half* __restrict__ Ch,
    int M, int Nn, int K, int ldA)
{
    extern __shared__ char smraw[];
    const uint32_t sb = smem_u32(smraw);
    const int tid = threadIdx.x, wid = tid >> 5, lane = tid & 31;
    const int wm = wid & 1, wn = wid >> 1;
    const int m0 = blockIdx.y * 128, n0 = blockIdx.x * 128;

    float acc[4][4][4];
    #pragma unroll
    for (int mt = 0; mt < 4; mt++)
        #pragma unroll
        for (int nt = 0; nt < 4; nt++)
            #pragma unroll
            for (int c = 0; c < 4; c++) acc[mt][nt][c] = 0.f;

    const int a_row  = (lane & 7) + ((lane >> 3) & 1) * 8;
    const int a_k    = (lane >> 4) * 8;
    const int b_row4 = (lane & 7) + ((lane >> 4) & 1) * 8;
    const int b_k4   = ((lane >> 3) & 1) * 8;

    const int T = K >> 5;

    auto load_stage = [&](int buf, int k0) {
        uint32_t base = sb + buf * STG_SZ;
        #pragma unroll
        for (int it = 0; it < 4; it++) {
            int i    = tid + it * 256;
            int mat  = i >> 9;
            int rem  = i & 511;
            int row  = rem >> 2;
            int ch   = rem & 3;
            uint32_t dst = base + mat * MAT_SZ + row * RSB + ch * 16;
            const __half* src;
            int sz = 16;
            if (mat == 0) {
                int gm = m0 + row;
                if (gm >= M) sz = 0;
                src = Ah + (size_t)gm * ldA + k0 + ch * 8;
            } else {
                src = Bh + (size_t)(n0 + row) * K + k0 + ch * 8;
            }
            CP_ASYNC(dst, src, sz);
        }
        CP_COMMIT();
    };

    auto compute = [&](int buf) {
        uint32_t base  = sb + buf * STG_SZ;
        uint32_t aB    = base + (wm * 64) * RSB;
        uint32_t bB    = base + MAT_SZ + (wn * 32) * RSB;
        #pragma unroll
        for (int ks = 0; ks < 32; ks += 16) {
            uint32_t bh[4][2];
            #pragma unroll
            for (int ntp = 0; ntp < 2; ntp++) {
                uint32_t bd = bB + (ntp * 16 + b_row4) * RSB + (ks + b_k4) * 2;
                uint32_t r4[4];
                LDM4(r4, bd);
                bh[2 * ntp][0] = r4[0]; bh[2 * ntp][1] = r4[1];
                bh[2 * ntp + 1][0] = r4[2]; bh[2 * ntp + 1][1] = r4[3];
            }
            #pragma unroll
            for (int mt = 0; mt < 4; mt++) {
                uint32_t ah4[4];
                uint32_t ad = aB + (mt * 16 + a_row) * RSB + (ks + a_k) * 2;
                LDM4(ah4, ad);
                #pragma unroll
                for (int nt = 0; nt < 4; nt++) MMA16816(acc[mt][nt], ah4, bh[nt]);
            }
        }
    };

    load_stage(0, 0);
    if (T > 1) load_stage(1, 32);
    for (int t = 0; t < T; t++) {
        if (t + 1 < T) asm volatile("cp.async.wait_group 1;" ::: "memory");
        else           asm volatile("cp.async.wait_group 0;" ::: "memory");
        __syncthreads();
        if (t + 2 < T) load_stage((t + 2) % 3, (t + 2) << 5);
        compute(t % 3);
    }

    const int r0    = lane >> 2;
    const int cpair = (lane & 3) * 2;
    #pragma unroll
    for (int mt = 0; mt < 4; mt++) {
        int gm1 = m0 + wm * 64 + mt * 16 + r0;
        int gm2 = gm1 + 8;
        #pragma unroll
        for (int nt = 0; nt < 4; nt++) {
            int gn = n0 + wn * 32 + nt * 8 + cpair;
            float b0 = 0.f, b1 = 0.f;
            if (BIAS) { float2 bb = *(const float2*)&bias[gn]; b0 = bb.x; b1 = bb.y; }
            float v0 = acc[mt][nt][0] + b0, v1 = acc[mt][nt][1] + b1;
            float v2 = acc[mt][nt][2] + b0, v3 = acc[mt][nt][3] + b1;
            if (RELU) {
                v0 = fmaxf(v0, 0.f); v1 = fmaxf(v1, 0.f);
                v2 = fmaxf(v2, 0.f); v3 = fmaxf(v3, 0.f);
            }
            if (gm1 < M) {
                __half2 hv; hv.x = __float2half(v0); hv.y = __float2half(v1);
                *(__half2*)&Ch[(size_t)gm1 * Nn + gn] = hv;
            }
            if (gm2 < M) {
                __half2 hv; hv.x = __float2half(v2); hv.y = __float2half(v3);
                *(__half2*)&Ch[(size_t)gm2 * Nn + gn] = hv;
            }
        }
    }
}

// ================= fused GEMM + residual + LayerNorm (N=256) =============
// seq_row(gm) = LN(seq_row(gm) + bias + (A*B^T)_row). seq rows strided by ldS.
#define FL_A_SZ  10240
#define FL_B_SZ  20480
#define FL_STG   (FL_A_SZ + FL_B_SZ)
#define FL_RED   (3 * FL_STG)
#define FL_SMEM  (FL_RED + 8192)

__global__ __launch_bounds__(512, 1) void gemm_ln_kernel(
    const __half* __restrict__ Ah, const __half* __restrict__ Bh,
    const float* __restrict__ bias,
    __half* __restrict__ sh, __half* __restrict__ sl,
    const float* __restrict__ lng, const float* __restrict__ lnb,
    int M, int K, int ldA, int ldS)
{
    extern __shared__ char smraw[];
    const uint32_t sb = smem_u32(smraw);
    const int tid = threadIdx.x, wid = tid >> 5, lane = tid & 31;
    const int wm = wid & 1, wn = wid >> 1;
    const int m0 = blockIdx.x * 128;

    float acc[4][4][4];
    #pragma unroll
    for (int mt = 0; mt < 4; mt++)
        #pragma unroll
        for (int nt = 0; nt < 4; nt++)
            #pragma unroll
            for (int c = 0; c < 4; c++) acc[mt][nt][c] = 0.f;

    const int a_row  = (lane & 7) + ((lane >> 3) & 1) * 8;
    const int a_k    = (lane >> 4) * 8;
    const int b_row4 = (lane & 7) + ((lane >> 4) & 1) * 8;
    const int b_k4   = ((lane >> 3) & 1) * 8;

    const int T = K >> 5;

    auto load_stage = [&](int buf, int k0) {
        uint32_t base = sb + buf * FL_STG;
        #pragma unroll
        for (int it = 0; it < 3; it++) {
            int i = tid + it * 512;
            uint32_t dst;
            const __half* src;
            int sz = 16;
            if (i < 512) {
                int row = i >> 2, ch = i & 3;
                dst = base + row * RSB + ch * 16;
                int gm = m0 + row;
                if (gm >= M) sz = 0;
                src = Ah + (size_t)gm * ldA + k0 + ch * 8;
            } else {
                int r = i - 512;
                int row = r >> 2, ch = r & 3;
                dst = base + FL_A_SZ + row * RSB + ch * 16;
                src = Bh + (size_t)row * K + k0 + ch * 8;
            }
            CP_ASYNC(dst, src, sz);
        }
        CP_COMMIT();
    };

    auto compute = [&](int buf) {
        uint32_t base  = sb + buf * FL_STG;
        uint32_t aB    = base + (wm * 64) * RSB;
        uint32_t bB    = base + FL_A_SZ + (wn * 32) * RSB;
        #pragma unroll
        for (int ks = 0; ks < 32; ks += 16) {
            uint32_t bh[4][2];
            #pragma unroll
            for (int ntp = 0; ntp < 2; ntp++) {
                uint32_t bd = bB + (ntp * 16 + b_row4) * RSB + (ks + b_k4) * 2;
                uint32_t r4[4];
                LDM4(r4, bd);
                bh[2 * ntp][0] = r4[0]; bh[2 * ntp][1] = r4[1];
                bh[2 * ntp + 1][0] = r4[2]; bh[2 * ntp + 1][1] = r4[3];
            }
            #pragma unroll
            for (int mt = 0; mt < 4; mt++) {
                uint32_t ah4[4];
                uint32_t ad = aB + (mt * 16 + a_row) * RSB + (ks + a_k) * 2;
                LDM4(ah4, ad);
                #pragma unroll
                for (int nt = 0; nt < 4; nt++) MMA16816(acc[mt][nt], ah4, bh[nt]);
            }
        }
    };

    load_stage(0, 0);
    if (T > 1) load_stage(1, 32);
    for (int t = 0; t < T; t++) {
        if (t + 1 < T) asm volatile("cp.async.wait_group 1;" ::: "memory");
        else           asm volatile("cp.async.wait_group 0;" ::: "memory");
        __syncthreads();
        if (t + 2 < T) load_stage((t + 2) % 3, (t + 2) << 5);
        compute(t % 3);
    }

    const int r0    = lane >> 2;
    const int cpair = (lane & 3) * 2;
    float* red_sum = (float*)(smraw + FL_RED);
    float* red_sq  = (float*)(smraw + FL_RED + 4096);

    #pragma unroll
    for (int mt = 0; mt < 4; mt++) {
        int row1 = wm * 64 + mt * 16 + r0;
        int gm1 = m0 + row1, gm2 = gm1 + 8;
        float s0 = 0.f, q0 = 0.f, s1 = 0.f, q1 = 0.f;
        #pragma unroll
        for (int nt = 0; nt < 4; nt++) {
            int gn = wn * 32 + nt * 8 + cpair;
            float2 bb = *(const float2*)&bias[gn];
            float ra = 0.f, rb = 0.f, rc = 0.f, rd = 0.f;
            if (gm1 < M) {
                __half2 hh1 = *(const __half2*)&sh[(size_t)gm1 * ldS + gn];
                __half2 ll1 = *(const __half2*)&sl[(size_t)gm1 * ldS + gn];
                ra = __half2float(hh1.x) + __half2float(ll1.x);
                rb = __half2float(hh1.y) + __half2float(ll1.y);
            }
            if (gm2 < M) {
                __half2 hh2 = *(const __half2*)&sh[(size_t)gm2 * ldS + gn];
                __half2 ll2 = *(const __half2*)&sl[(size_t)gm2 * ldS + gn];
                rc = __half2float(hh2.x) + __half2float(ll2.x);
                rd = __half2float(hh2.y) + __half2float(ll2.y);
            }
            float w0 = acc[mt][nt][0] + bb.x + ra;
            float w1 = acc[mt][nt][1] + bb.y + rb;
            float w2 = acc[mt][nt][2] + bb.x + rc;
            float w3 = acc[mt][nt][3] + bb.y + rd;
            acc[mt][nt][0] = w0; acc[mt][nt][1] = w1;
            acc[mt][nt][2] = w2; acc[mt][nt][3] = w3;
            s0 += w0 + w1; q0 += w0 * w0 + w1 * w1;
            s1 += w2 + w3; q1 += w2 * w2 + w3 * w3;
        }
        s0 += __shfl_xor_sync(0xFFFFFFFFu, s0, 1); s0 += __shfl_xor_sync(0xFFFFFFFFu, s0, 2);
        q0 += __shfl_xor_sync(0xFFFFFFFFu, q0, 1); q0 += __shfl_xor_sync(0xFFFFFFFFu, q0, 2);
        s1 += __shfl_xor_sync(0xFFFFFFFFu, s1, 1); s1 += __shfl_xor_sync(0xFFFFFFFFu, s1, 2);
        q1 += __shfl_xor_sync(0xFFFFFFFFu, q1, 1); q1 += __shfl_xor_sync(0xFFFFFFFFu, q1, 2);
        if ((lane & 3) == 0) {
            red_sum[row1 * 8 + wn] = s0;       red_sq[row1 * 8 + wn] = q0;
            red_sum[(row1 + 8) * 8 + wn] = s1; red_sq[(row1 + 8) * 8 + wn] = q1;
        }
    }
    __syncthreads();

    #pragma unroll
    for (int mt = 0; mt < 4; mt++) {
        int row1 = wm * 64 + mt * 16 + r0;
        int gm1 = m0 + row1, gm2 = gm1 + 8;
        float su0 = 0.f, sq0 = 0.f, su1 = 0.f, sq1 = 0.f;
        #pragma unroll
        for (int wj = 0; wj < 8; wj++) {
            su0 += red_sum[row1 * 8 + wj];       sq0 += red_sq[row1 * 8 + wj];
            su1 += red_sum[(row1 + 8) * 8 + wj]; sq1 += red_sq[(row1 + 8) * 8 + wj];
        }
        float mean0 = su0 * (1.f / DD);
        float inv0  = rsqrtf(sq0 * (1.f / DD) - mean0 * mean0 + 1e-5f);
        float mean1 = su1 * (1.f / DD);
        float inv1  = rsqrtf(sq1 * (1.f / DD) - mean1 * mean1 + 1e-5f);
        #pragma unroll
        for (int nt = 0; nt < 4; nt++) {
            int gn = wn * 32 + nt * 8 + cpair;
            float2 gg = *(const float2*)&lng[gn];
            float2 bb = *(const float2*)&lnb[gn];
            if (gm1 < M) {
                float y0 = (acc[mt][nt][0] - mean0) * inv0 * gg.x + bb.x;
                float y1 = (acc[mt][nt][1] - mean0) * inv0 * gg.y + bb.y;
                split_store(&sh[(size_t)gm1 * ldS + gn], &sl[(size_t)gm1 * ldS + gn], y0, y1);
            }
            if (gm2 < M) {
                float y2 = (acc[mt][nt][2] - mean1) * inv1 * gg.x + bb.x;
                float y3 = (acc[mt][nt][3] - mean1) * inv1 * gg.y + bb.y;
                split_store(&sh[(size_t)gm2 * ldS + gn], &sl[(size_t)gm2 * ldS + gn], y2, y3);
            }
        }
    }
}

// ================= CSR build kernels =================
__global__ void fill0i_kernel(int* __restrict__ p, int n) {
    int i = blockIdx.x * 256 + threadIdx.x;
    if (i < n) p[i] = 0;
}

__global__ void hist_kernel(const int* __restrict__ ei, int* __restrict__ cnt,
                            int* __restrict__ slot)
{
    int e = blockIdx.x * 256 + threadIdx.x;
    if (e >= ETOT) return;
    int dst = (e < EE) ? ei[EE + e] : e - EE;
    slot[e] = atomicAdd(&cnt[dst], 1);
}

__global__ void scan_kernel(const int* __restrict__ cnt, int* __restrict__ rows) {
    __shared__ int wsum[32];
    int tid = threadIdx.x;
    const int CH = (NN + 1023) / 1024;
    int beg = tid * CH;
    int ssum = 0;
    for (int i = 0; i < CH; i++) {
        int idx = beg + i;
        if (idx < NN) ssum += cnt[idx];
    }
    int lane = tid & 31, wid = tid >> 5;
    int v = ssum;
    #pragma unroll
    for (int o = 1; o < 32; o <<= 1) {
        int u = __shfl_up_sync(0xFFFFFFFFu, v, o);
        if (lane >= o) v += u;
    }
    if (lane == 31) wsum[wid] = v;
    __syncthreads();
    if (wid == 0) {
        int w = wsum[lane];
        #pragma unroll
        for (int o = 1; o < 32; o <<= 1) {
            int u = __shfl_up_sync(0xFFFFFFFFu, w, o);
            if (lane >= o) w += u;
        }
        wsum[lane] = w;
    }
    __syncthreads();
    int off = v - ssum + (wid ? wsum[wid - 1] : 0);
    for (int i = 0; i < CH; i++) {
        int idx = beg + i;
        if (idx < NN) { rows[idx] = off; off += cnt[idx]; }
    }
    if (tid == 0) rows[NN] = ETOT;
}

__global__ void scatter_kernel(const int* __restrict__ ei, const int* __restrict__ rows,
                               const int* __restrict__ slot, int* __restrict__ csrc)
{
    int e = blockIdx.x * 256 + threadIdx.x;
    if (e >= ETOT) return;
    int src, dst;
    if (e < EE) { src = ei[e]; dst = ei[EE + e]; }
    else        { src = dst = e - EE; }
    csrc[rows[dst] + slot[e]] = src;
}

// ================= GAT gather (CSR, no atomics; fp16 h) ==================
__global__ void gather_kernel(const int* __restrict__ rows, const int* __restrict__ csrc,
                              const float* __restrict__ s, const float* __restrict__ t,
                              const __half* __restrict__ hh, const float* __restrict__ b,
                              __half* __restrict__ oh)
{
    int n = blockIdx.x * 4 + (threadIdx.x >> 6);
    if (n >= NN) return;
    int sub = threadIdx.x & 63;
    float tn = __ldg(&t[n]);
    int beg = __ldg(&rows[n]), end = __ldg(&rows[n + 1]);
    float a0 = 0.f, a1 = 0.f, a2 = 0.f, a3 = 0.f, den = 0.f;
    for (int i = beg; i < end; i++) {
        int src = __ldg(&csrc[i]);
        float x = __ldg(&s[src]) + tn;
        float ex = expf(x > 0.f ? x : NEGS * x);
        den += ex;
        size_t o = (size_t)src * DD + sub * 4;
        __half2 h01 = *(const __half2*)&hh[o];
        __half2 h23 = *(const __half2*)&hh[o + 2];
        a0 += ex * __half2float(h01.x); a1 += ex * __half2float(h01.y);
        a2 += ex * __half2float(h23.x); a3 += ex * __half2float(h23.y);
    }
    float inv = 1.f / den;
    float4 bb = *(const float4*)&b[sub * 4];
    float v0 = fmaxf(a0 * inv + bb.x, 0.f);
    float v1 = fmaxf(a1 * inv + bb.y, 0.f);
    float v2 = fmaxf(a2 * inv + bb.z, 0.f);
    float v3 = fmaxf(a3 * inv + bb.w, 0.f);
    size_t o = (size_t)n * DD + sub * 4;
    __half2 p0; p0.x = __float2half(v0); p0.y = __float2half(v1);
    __half2 p1; p1.x = __float2half(v2); p1.y = __float2half(v3);
    *(__half2*)&oh[o]     = p0;
    *(__half2*)&oh[o + 2] = p1;
}

// ================= small kernels =================
__global__ void round_kernel(const float* __restrict__ s, __half* __restrict__ h, int n)
{
    int i = blockIdx.x * 256 + threadIdx.x;
    if (i < n) h[i] = __float2half(s[i]);
}

__global__ void dots_kernel(const __half* __restrict__ hh,
                            const float* __restrict__ asrc,
                            const float* __restrict__ adst,
                            float* __restrict__ s, float* __restrict__ t)
{
    int n = blockIdx.x * 8 + (threadIdx.x >> 5);
    if (n >= NN) return;
    int lane = threadIdx.x & 31;
    const __half* row = hh + (size_t)n * DD;
    float ps = 0.f, pt = 0.f;
    #pragma unroll
    for (int i = 0; i < 4; i++) {
        int d = lane * 8 + i * 2;
        __half2 hv = *(const __half2*)&row[d];
        float v0 = __half2float(hv.x), v1 = __half2float(hv.y);
        ps += v0 * asrc[d] + v1 * asrc[d + 1];
        pt += v0 * adst[d] + v1 * adst[d + 1];
    }
    #pragma unroll
    for (int o = 16; o; o >>= 1) {
        ps += __shfl_xor_sync(0xFFFFFFFFu, ps, o);
        pt += __shfl_xor_sync(0xFFFFFFFFu, pt, o);
    }
    if (lane == 0) { s[n] = ps; t[n] = pt; }
}

__global__ void build_seq_kernel(const __half* __restrict__ x1h,
                                 const __half* __restrict__ x2h,
                                 const float* __restrict__ cls,
                                 const float* __restrict__ pos,
                                 __half* __restrict__ sh,
                                 __half* __restrict__ sl)
{
    size_t i = (size_t)blockIdx.x * 256 + threadIdx.x;
    if (i >= (size_t)NTOK * DD) return;
    int d = (int)(i & 255);
    size_t tok = i >> 8;
    int which = (int)(tok % 3);
    size_t n = tok / 3;
    float v;
    if (which == 0)      v = cls[d];
    else if (which == 1) v = __half2float(x1h[n * DD + d]);
    else                 v = __half2float(x2h[n * DD + d]);
    v += pos[which * DD + d];
    __half a = __float2half(v);
    sh[i] = a;
    sl[i] = __float2half(v - __half2float(a));
}

// attention; CLSONLY computes only query token 0 and writes compact [NN, DD]
template<bool CLSONLY>
__global__ void attn_kernel(const __half* __restrict__ qh, __half* __restrict__ atth)
{
    int w = blockIdx.x * 8 + (threadIdx.x >> 5);
    if (w >= NN * NHEAD) return;
    int lane = threadIdx.x & 31;
    int n = w >> 2, hh = w & 3;
    size_t base = (size_t)n * 3 * (3 * DD) + hh * DH + lane * 2;
    float2 q[3], k[3], v[3];
    #pragma unroll
    for (int i = 0; i < 3; i++) {
        size_t o = base + (size_t)i * (3 * DD);
        __half2 a;
        if (!CLSONLY || i == 0) {
            a = *(const __half2*)(qh + o);
            q[i].x = __half2float(a.x); q[i].y = __half2float(a.y);
        }
        a = *(const __half2*)(qh + o + DD);
        k[i].x = __half2float(a.x); k[i].y = __half2float(a.y);
        a = *(const __half2*)(qh + o + 2 * DD);
        v[i].x = __half2float(a.x); v[i].y = __half2float(a.y);
    }
    const int NI = CLSONLY ? 1 : 3;
    float lg[3][3];
    #pragma unroll
    for (int i = 0; i < NI; i++)
        #pragma unroll
        for (int j = 0; j < 3; j++) {
            float p = q[i].x * k[j].x + q[i].y * k[j].y;
            #pragma unroll
            for (int o = 16; o; o >>= 1) p += __shfl_xor_sync(0xFFFFFFFFu, p, o);
            lg[i][j] = p * 0.125f;
        }
    #pragma unroll
    for (int i = 0; i < NI; i++) {
        float m  = fmaxf(lg[i][0], fmaxf(lg[i][1], lg[i][2]));
        float e0 = expf(lg[i][0] - m), e1 = expf(lg[i][1] - m), e2 = expf(lg[i][2] - m);
        float inv = 1.f / (e0 + e1 + e2);
        float ox = (e0 * v[0].x + e1 * v[1].x + e2 * v[2].x) * inv;
        float oy = (e0 * v[0].y + e1 * v[1].y + e2 * v[2].y) * inv;
        size_t o = CLSONLY ? ((size_t)n * DD + hh * DH + lane * 2)
                           : (((size_t)(n * 3 + i)) * DD + hh * DH + lane * 2);
        __half2 hv; hv.x = __float2half(ox); hv.y = __float2half(oy);
        *(__half2*)&atth[o] = hv;
    }
}

__global__ void final_ln_kernel(const __half* __restrict__ sh, const __half* __restrict__ sl,
                                const float* __restrict__ g,
                                const float* __restrict__ b,
                                float* __restrict__ out)
{
    int n = blockIdx.x * 8 + (threadIdx.x >> 5);
    if (n >= NN) return;
    int lane = threadIdx.x & 31;
    const __half* ph = sh + (size_t)n * 3 * DD;
    const __half* pl = sl + (size_t)n * 3 * DD;
    float v[8];
    float sum = 0.f, sq = 0.f;
    #pragma unroll
    for (int i = 0; i < 4; i++) {
        __half2 ah = *(const __half2*)&ph[lane * 8 + i * 2];
        __half2 al = *(const __half2*)&pl[lane * 8 + i * 2];
        float w0 = __half2float(ah.x) + __half2float(al.x);
        float w1 = __half2float(ah.y) + __half2float(al.y);
        v[i * 2 + 0] = w0; v[i * 2 + 1] = w1;
        sum += w0 + w1;
        sq  += w0 * w0 + w1 * w1;
    }
    #pragma unroll
    for (int o = 16; o; o >>= 1) {
        sum += __shfl_xor_sync(0xFFFFFFFFu, sum, o);
        sq  += __shfl_xor_sync(0xFFFFFFFFu, sq, o);
    }
    float mean = sum * (1.f / DD);
    float var  = sq * (1.f / DD) - mean * mean;
    float inv  = rsqrtf(var + 1e-5f);
    #pragma unroll
    for (int i = 0; i < 8; i++) {
        int d = lane * 8 + i;
        out[(size_t)n * DD + d] = (v[i] - mean) * inv * g[d] + b[d];
    }
}

// ================= host side =================
template<bool BIAS, bool RELU>
static void run_gemm_tc(const __half* Ah, const __half* Bh,
                        const float* bias, __half* Ch,
                        int M, int Nn, int K, int ldA)
{
    cudaFuncSetAttribute(gemm_mma_kernel<BIAS, RELU>,
                         cudaFuncAttributeMaxDynamicSharedMemorySize, GM_SMEM);
    dim3 grid(Nn / 128, (M + 127) / 128);
    gemm_mma_kernel<BIAS, RELU><<<grid, 256, GM_SMEM>>>(Ah, Bh, bias, Ch, M, Nn, K, ldA);
}

static void run_gemm_ln(const __half* Ah, const __half* Bh, const float* bias,
                        __half* sh, __half* sl, const float* lng, const float* lnb,
                        int M, int K, int ldA, int ldS)
{
    cudaFuncSetAttribute(gemm_ln_kernel,
                         cudaFuncAttributeMaxDynamicSharedMemorySize, FL_SMEM);
    gemm_ln_kernel<<<(M + 127) / 128, 512, FL_SMEM>>>(Ah, Bh, bias, sh, sl, lng, lnb,
                                                      M, K, ldA, ldS);
}

extern "C" void kernel_launch(void* const* d_in, const int* in_sizes, int n_in,
                              void* d_out, int out_size)
{
    const float* x        = (const float*)d_in[0];
    const int*   ei       = (const int*)  d_in[1];
    const float* gat1_W   = (const float*)d_in[2];
    const float* gat1_b   = (const float*)d_in[3];
    const float* gat1_as  = (const float*)d_in[4];
    const float* gat1_ad  = (const float*)d_in[5];
    const float* gat2_W   = (const float*)d_in[6];
    const float* gat2_b   = (const float*)d_in[7];
    const float* gat2_as  = (const float*)d_in[8];
    const float* gat2_ad  = (const float*)d_in[9];
    const float* cls      = (const float*)d_in[10];
    const float* pos      = (const float*)d_in[11];
    const float* Wqkv     = (const float*)d_in[12];
    const float* bqkv     = (const float*)d_in[13];
    const float* Wo       = (const float*)d_in[14];
    const float* bo       = (const float*)d_in[15];
    const float* ln1_g    = (const float*)d_in[16];
    const float* ln1_b    = (const float*)d_in[17];
    const float* ln2_g    = (const float*)d_in[18];
    const float* ln2_b    = (const float*)d_in[19];
    const float* Wff1     = (const float*)d_in[20];
    const float* bff1     = (const float*)d_in[21];
    const float* Wff2     = (const float*)d_in[22];
    const float* bff2     = (const float*)d_in[23];
    const float* norm_g   = (const float*)d_in[24];
    const float* norm_b   = (const float*)d_in[25];
    float* out = (float*)d_out;

    float *s, *t;
    cudaGetSymbolAddress((void**)&s, g_s);
    cudaGetSymbolAddress((void**)&t, g_t);

    int *cnt, *slot, *rows, *csrc;
    cudaGetSymbolAddress((void**)&cnt,  g_cnt);
    cudaGetSymbolAddress((void**)&slot, g_slot);
    cudaGetSymbolAddress((void**)&rows, g_rows);
    cudaGetSymbolAddress((void**)&csrc, g_csrc);

    __half *hh, *xh, *x1h, *x2h, *seqh, *seql, *qkvh, *atth, *ffh, *wbh;
    cudaGetSymbolAddress((void**)&hh,   g_hh);
    cudaGetSymbolAddress((void**)&xh,   g_xh);
    cudaGetSymbolAddress((void**)&x1h,  g_x1h);
    cudaGetSymbolAddress((void**)&x2h,  g_x2h);
    cudaGetSymbolAddress((void**)&seqh, g_seqh);
    cudaGetSymbolAddress((void**)&seql, g_seql);
    cudaGetSymbolAddress((void**)&qkvh, g_qkvh);
    cudaGetSymbolAddress((void**)&atth, g_atth);
    cudaGetSymbolAddress((void**)&ffh,  g_ffh);
    cudaGetSymbolAddress((void**)&wbh,  g_wbh);

    // ---- CSR build ----
    fill0i_kernel<<<(NN + 255) / 256, 256>>>(cnt, NN);
    hist_kernel<<<(ETOT + 255) / 256, 256>>>(ei, cnt, slot);
    scan_kernel<<<1, 1024>>>(cnt, rows);
    scatter_kernel<<<(ETOT + 255) / 256, 256>>>(ei, rows, slot, csrc);

    // ---- conversions ----
    round_kernel<<<(NN * DIN + 255) / 256, 256>>>(x, xh, NN * DIN);
    round_kernel<<<(DD * DIN + 255) / 256, 256>>>(gat1_W, wbh + WOFF_W1, DD * DIN);
    round_kernel<<<(DD * DD + 255) / 256, 256>>>(gat2_W, wbh + WOFF_W2, DD * DD);
    round_kernel<<<(2 * 3 * DD * DD + 255) / 256, 256>>>(Wqkv, wbh + WOFF_QKV, 2 * 3 * DD * DD);
    round_kernel<<<(2 * DD * DD + 255) / 256, 256>>>(Wo, wbh + WOFF_WO, 2 * DD * DD);
    round_kernel<<<(2 * 4 * DD * DD + 255) / 256, 256>>>(Wff1, wbh + WOFF_F1, 2 * 4 * DD * DD);
    round_kernel<<<(2 * DD * 4 * DD + 255) / 256, 256>>>(Wff2, wbh + WOFF_F2, 2 * DD * 4 * DD);

    // ---- GAT layer 1 ----
    run_gemm_tc<false, false>(xh, wbh + WOFF_W1, nullptr, hh, NN, DD, DIN, DIN);
    dots_kernel<<<(NN + 7) / 8, 256>>>(hh, gat1_as, gat1_ad, s, t);
    gather_kernel<<<(NN + 3) / 4, 256>>>(rows, csrc, s, t, hh, gat1_b, x1h);

    // ---- GAT layer 2 ----
    run_gemm_tc<false, false>(x1h, wbh + WOFF_W2, nullptr, hh, NN, DD, DD, DD);
    dots_kernel<<<(NN + 7) / 8, 256>>>(hh, gat2_as, gat2_ad, s, t);
    gather_kernel<<<(NN + 3) / 4, 256>>>(rows, csrc, s, t, hh, gat2_b, x2h);

    // ---- build sequence ----
    build_seq_kernel<<<(unsigned)(((size_t)NTOK * DD + 255) / 256), 256>>>(
        x1h, x2h, cls, pos, seqh, seql);

    // ---- transformer layer 0 (full) ----
    {
        const __half* wqh  = wbh + WOFF_QKV;
        const __half* woh  = wbh + WOFF_WO;
        const __half* wf1h = wbh + WOFF_F1;
        const __half* wf2h = wbh + WOFF_F2;
        run_gemm_tc<true, false>(seqh, wqh, bqkv, qkvh, NTOK, 3 * DD, DD, DD);
        attn_kernel<false><<<(NN * NHEAD + 7) / 8, 256>>>(qkvh, atth);
        run_gemm_ln(atth, woh, bo, seqh, seql, ln1_g, ln1_b, NTOK, DD, DD, DD);
        run_gemm_tc<true, true>(seqh, wf1h, bff1, ffh, NTOK, 4 * DD, DD, DD);
        run_gemm_ln(ffh, wf2h, bff2, seqh, seql, ln2_g, ln2_b, NTOK, 4 * DD, 4 * DD, DD);
    }

    // ---- transformer layer 1 (CLS-only after attention) ----
    {
        const __half* wqh  = wbh + WOFF_QKV + (size_t)3 * DD * DD;
        const __half* woh  = wbh + WOFF_WO  + (size_t)DD * DD;
        const __half* wf1h = wbh + WOFF_F1  + (size_t)4 * DD * DD;
        const __half* wf2h = wbh + WOFF_F2  + (size_t)DD * 4 * DD;
        run_gemm_tc<true, false>(seqh, wqh, bqkv + 3 * DD, qkvh, NTOK, 3 * DD, DD, DD);
        attn_kernel<true><<<(NN * NHEAD + 7) / 8, 256>>>(qkvh, atth);   // compact [NN, DD]
        // CLS rows of seq live at token stride 3*DD
        run_gemm_ln(atth, woh, bo + DD, seqh, seql,
                    ln1_g + DD, ln1_b + DD, NN, DD, DD, 3 * DD);
        run_gemm_tc<true, true>(seqh, wf1h, bff1 + 4 * DD, ffh, NN, 4 * DD, DD, 3 * DD);
        run_gemm_ln(ffh, wf2h, bff2 + DD, seqh, seql,
                    ln2_g + DD, ln2_b + DD, NN, 4 * DD, 4 * DD, 3 * DD);
    }

    // ---- final LN on CLS token ----
    final_ln_kernel<<<(NN + 7) / 8, 256>>>(seqh, seql, norm_g, norm_b, out);
}

// round 16
// speedup vs baseline: 3.6313x; 1.0584x over previous
#include <cuda_runtime.h>
#include <cuda_fp16.h>
#include <cstdint>
#include <cstdio>

// ---------------- problem constants ----------------
#define NN      50000
#define EE      320000
#define ETOT    (EE + NN)
#define DIN     128
#define DD      256
#define NTOK    (NN * 3)
#define NHEAD   4
#define DH      64
#define NEGS    0.2f

// ---------------- fp32 scratch ----------------
__device__ float g_s  [NN];
__device__ float g_t  [NN];

// ---------------- CSR graph scratch ----------------
__device__ int g_cnt [NN];
__device__ int g_slot[ETOT];
__device__ int g_rows[NN + 1];
__device__ int g_csrc[ETOT];

// ---------------- fp16 activation buffers ----------------
__device__ __half g_hh  [(size_t)NN * DD];      // GAT projection / L1 Q-CLS
__device__ __half g_xh  [(size_t)NN * DIN];
__device__ __half g_x1h [(size_t)NN * DD];
__device__ __half g_x2h [(size_t)NN * DD];
__device__ __half g_seqh[(size_t)NTOK * DD];
__device__ __half g_seql[(size_t)NTOK * DD];
__device__ __half g_qkvh[(size_t)NTOK * 3 * DD];  // L0 QKV / L1 KV
__device__ __half g_atth[(size_t)NTOK * DD];
__device__ __half g_ffh [(size_t)NTOK * 4 * DD];
// weight pool (fp16-rounded); offsets are cumulative
#define WOFF_W1   0
#define WOFF_W2   32768
#define WOFF_QKV  98304
#define WOFF_WO   491520
#define WOFF_F1   622592
#define WOFF_F2   1146880
#define WTOT      1671168
__device__ __half g_wbh[WTOT];

// ================= warp-mma helpers =================
__device__ __forceinline__ uint32_t smem_u32(const void* p) {
    uint32_t a;
    asm("{ .reg .u64 t; cvta.to.shared.u64 t, %1; cvt.u32.u64 %0, t; }" : "=r"(a) : "l"(p));
    return a;
}

#define LDM4(r, addr) \
    asm volatile("ldmatrix.sync.aligned.m8n8.x4.shared.b16 {%0,%1,%2,%3}, [%4];" \
        : "=r"((r)[0]), "=r"((r)[1]), "=r"((r)[2]), "=r"((r)[3]) : "r"(addr))
#define MMA16816(c, a, b) \
    asm volatile("mma.sync.aligned.m16n8k16.row.col.f32.f16.f16.f32 " \
        "{%0,%1,%2,%3}, {%4,%5,%6,%7}, {%8,%9}, {%0,%1,%2,%3};" \
        : "+f"((c)[0]), "+f"((c)[1]), "+f"((c)[2]), "+f"((c)[3]) \
        : "r"((a)[0]), "r"((a)[1]), "r"((a)[2]), "r"((a)[3]), "r"((b)[0]), "r"((b)[1]))
#define CP_ASYNC(dst, src, sz) \
    asm volatile("cp.async.cg.shared.global [%0], [%1], 16, %2;" :: "r"(dst), "l"(src), "r"(sz))
#define CP_COMMIT() asm volatile("cp.async.commit_group;" ::: "memory")

__device__ __forceinline__ void split_store(__half* hp, __half* lp, float a, float b) {
    __half h0 = __float2half(a), h1 = __float2half(b);
    __half2 hv; hv.x = h0; hv.y = h1;
    __half2 lv;
    lv.x = __float2half(a - __half2float(h0));
    lv.y = __float2half(b - __half2float(h1));
    *(__half2*)hp = hv;
    *(__half2*)lp = lv;
}

// ================= fp16 GEMM via mma.sync (generic N, strided A) =========
// Optional fused GAT-dots epilogue: atomicAdd partial h.asrc / h.adst per row.
#define RSB     80
#define MAT_SZ  10240
#define STG_SZ  20480
#define GM_SMEM (3 * STG_SZ)

template<bool BIAS, bool RELU, bool DOTS>
__global__ __launch_bounds__(256, 2) void gemm_mma_kernel(
    const __half* __restrict__ Ah, const __half* __restrict__ Bh,
    const float* __restrict__ bias, __half* __restrict__ Ch,
    const float* __restrict__ asrc, const float* __restrict__ adst,
    float* __restrict__ ds, float* __restrict__ dt,
    int M, int Nn, int K, int ldA)
{
    extern __shared__ char smraw[];
    const uint32_t sb = smem_u32(smraw);
    const int tid = threadIdx.x, wid = tid >> 5, lane = tid & 31;
    const int wm = wid & 1, wn = wid >> 1;
    const int m0 = blockIdx.y * 128, n0 = blockIdx.x * 128;

    float acc[4][4][4];
    #pragma unroll
    for (int mt = 0; mt < 4; mt++)
        #pragma unroll
        for (int nt = 0; nt < 4; nt++)
            #pragma unroll
            for (int c = 0; c < 4; c++) acc[mt][nt][c] = 0.f;

    const int a_row  = (lane & 7) + ((lane >> 3) & 1) * 8;
    const int a_k    = (lane >> 4) * 8;
    const int b_row4 = (lane & 7) + ((lane >> 4) & 1) * 8;
    const int b_k4   = ((lane >> 3) & 1) * 8;

    const int T = K >> 5;

    auto load_stage = [&](int buf, int k0) {
        uint32_t base = sb + buf * STG_SZ;
        #pragma unroll
        for (int it = 0; it < 4; it++) {
            int i    = tid + it * 256;
            int mat  = i >> 9;
            int rem  = i & 511;
            int row  = rem >> 2;
            int ch   = rem & 3;
            uint32_t dst = base + mat * MAT_SZ + row * RSB + ch * 16;
            const __half* src;
            int sz = 16;
            if (mat == 0) {
                int gm = m0 + row;
                if (gm >= M) sz = 0;
                src = Ah + (size_t)gm * ldA + k0 + ch * 8;
            } else {
                src = Bh + (size_t)(n0 + row) * K + k0 + ch * 8;
            }
            CP_ASYNC(dst, src, sz);
        }
        CP_COMMIT();
    };

    auto compute = [&](int buf) {
        uint32_t base  = sb + buf * STG_SZ;
        uint32_t aB    = base + (wm * 64) * RSB;
        uint32_t bB    = base + MAT_SZ + (wn * 32) * RSB;
        #pragma unroll
        for (int ks = 0; ks < 32; ks += 16) {
            uint32_t bh[4][2];
            #pragma unroll
            for (int ntp = 0; ntp < 2; ntp++) {
                uint32_t bd = bB + (ntp * 16 + b_row4) * RSB + (ks + b_k4) * 2;
                uint32_t r4[4];
                LDM4(r4, bd);
                bh[2 * ntp][0] = r4[0]; bh[2 * ntp][1] = r4[1];
                bh[2 * ntp + 1][0] = r4[2]; bh[2 * ntp + 1][1] = r4[3];
            }
            #pragma unroll
            for (int mt = 0; mt < 4; mt++) {
                uint32_t ah4[4];
                uint32_t ad = aB + (mt * 16 + a_row) * RSB + (ks + a_k) * 2;
                LDM4(ah4, ad);
                #pragma unroll
                for (int nt = 0; nt < 4; nt++) MMA16816(acc[mt][nt], ah4, bh[nt]);
            }
        }
    };

    load_stage(0, 0);
    if (T > 1) load_stage(1, 32);
    for (int t = 0; t < T; t++) {
        if (t + 1 < T) asm volatile("cp.async.wait_group 1;" ::: "memory");
        else           asm volatile("cp.async.wait_group 0;" ::: "memory");
        __syncthreads();
        if (t + 2 < T) load_stage((t + 2) % 3, (t + 2) << 5);
        compute(t % 3);
    }

    const int r0    = lane >> 2;
    const int cpair = (lane & 3) * 2;
    #pragma unroll
    for (int mt = 0; mt < 4; mt++) {
        int gm1 = m0 + wm * 64 + mt * 16 + r0;
        int gm2 = gm1 + 8;
        float s1 = 0.f, t1 = 0.f, s2 = 0.f, t2 = 0.f;
        #pragma unroll
        for (int nt = 0; nt < 4; nt++) {
            int gn = n0 + wn * 32 + nt * 8 + cpair;
            float b0 = 0.f, b1 = 0.f;
            if (BIAS) { float2 bb = *(const float2*)&bias[gn]; b0 = bb.x; b1 = bb.y; }
            float v0 = acc[mt][nt][0] + b0, v1 = acc[mt][nt][1] + b1;
            float v2 = acc[mt][nt][2] + b0, v3 = acc[mt][nt][3] + b1;
            if (RELU) {
                v0 = fmaxf(v0, 0.f); v1 = fmaxf(v1, 0.f);
                v2 = fmaxf(v2, 0.f); v3 = fmaxf(v3, 0.f);
            }
            if (DOTS) {
                float2 as = *(const float2*)&asrc[gn];
                float2 ad = *(const float2*)&adst[gn];
                s1 += v0 * as.x + v1 * as.y; t1 += v0 * ad.x + v1 * ad.y;
                s2 += v2 * as.x + v3 * as.y; t2 += v2 * ad.x + v3 * ad.y;
            }
            if (gm1 < M) {
                __half2 hv; hv.x = __float2half(v0); hv.y = __float2half(v1);
                *(__half2*)&Ch[(size_t)gm1 * Nn + gn] = hv;
            }
            if (gm2 < M) {
                __half2 hv; hv.x = __float2half(v2); hv.y = __float2half(v3);
                *(__half2*)&Ch[(size_t)gm2 * Nn + gn] = hv;
            }
        }
        if (DOTS) {
            s1 += __shfl_xor_sync(0xFFFFFFFFu, s1, 1); s1 += __shfl_xor_sync(0xFFFFFFFFu, s1, 2);
            t1 += __shfl_xor_sync(0xFFFFFFFFu, t1, 1); t1 += __shfl_xor_sync(0xFFFFFFFFu, t1, 2);
            s2 += __shfl_xor_sync(0xFFFFFFFFu, s2, 1); s2 += __shfl_xor_sync(0xFFFFFFFFu, s2, 2);
            t2 += __shfl_xor_sync(0xFFFFFFFFu, t2, 1); t2 += __shfl_xor_sync(0xFFFFFFFFu, t2, 2);
            if ((lane & 3) == 0) {
                if (gm1 < M) { atomicAdd(&ds[gm1], s1); atomicAdd(&dt[gm1], t1); }
                if (gm2 < M) { atomicAdd(&ds[gm2], s2); atomicAdd(&dt[gm2], t2); }
            }
        }
    }
}

// ================= fused GEMM + residual + LayerNorm (N=256) =============
#define FL_A_SZ  10240
#define FL_B_SZ  20480
#define FL_STG   (FL_A_SZ + FL_B_SZ)
#define FL_RED   (3 * FL_STG)
#define FL_SMEM  (FL_RED + 8192)

__global__ __launch_bounds__(512, 1) void gemm_ln_kernel(
    const __half* __restrict__ Ah, const __half* __restrict__ Bh,
    const float* __restrict__ bias,
    __half* __restrict__ sh, __half* __restrict__ sl,
    const float* __restrict__ lng, const float* __restrict__ lnb,
    int M, int K, int ldA, int ldS)
{
    extern __shared__ char smraw[];
    const uint32_t sb = smem_u32(smraw);
    const int tid = threadIdx.x, wid = tid >> 5, lane = tid & 31;
    const int wm = wid & 1, wn = wid >> 1;
    const int m0 = blockIdx.x * 128;

    float acc[4][4][4];
    #pragma unroll
    for (int mt = 0; mt < 4; mt++)
        #pragma unroll
        for (int nt = 0; nt < 4; nt++)
            #pragma unroll
            for (int c = 0; c < 4; c++) acc[mt][nt][c] = 0.f;

    const int a_row  = (lane & 7) + ((lane >> 3) & 1) * 8;
    const int a_k    = (lane >> 4) * 8;
    const int b_row4 = (lane & 7) + ((lane >> 4) & 1) * 8;
    const int b_k4   = ((lane >> 3) & 1) * 8;

    const int T = K >> 5;

    auto load_stage = [&](int buf, int k0) {
        uint32_t base = sb + buf * FL_STG;
        #pragma unroll
        for (int it = 0; it < 3; it++) {
            int i = tid + it * 512;
            uint32_t dst;
            const __half* src;
            int sz = 16;
            if (i < 512) {
                int row = i >> 2, ch = i & 3;
                dst = base + row * RSB + ch * 16;
                int gm = m0 + row;
                if (gm >= M) sz = 0;
                src = Ah + (size_t)gm * ldA + k0 + ch * 8;
            } else {
                int r = i - 512;
                int row = r >> 2, ch = r & 3;
                dst = base + FL_A_SZ + row * RSB + ch * 16;
                src = Bh + (size_t)row * K + k0 + ch * 8;
            }
            CP_ASYNC(dst, src, sz);
        }
        CP_COMMIT();
    };

    auto compute = [&](int buf) {
        uint32_t base  = sb + buf * FL_STG;
        uint32_t aB    = base + (wm * 64) * RSB;
        uint32_t bB    = base + FL_A_SZ + (wn * 32) * RSB;
        #pragma unroll
        for (int ks = 0; ks < 32; ks += 16) {
            uint32_t bh[4][2];
            #pragma unroll
            for (int ntp = 0; ntp < 2; ntp++) {
                uint32_t bd = bB + (ntp * 16 + b_row4) * RSB + (ks + b_k4) * 2;
                uint32_t r4[4];
                LDM4(r4, bd);
                bh[2 * ntp][0] = r4[0]; bh[2 * ntp][1] = r4[1];
                bh[2 * ntp + 1][0] = r4[2]; bh[2 * ntp + 1][1] = r4[3];
            }
            #pragma unroll
            for (int mt = 0; mt < 4; mt++) {
                uint32_t ah4[4];
                uint32_t ad = aB + (mt * 16 + a_row) * RSB + (ks + a_k) * 2;
                LDM4(ah4, ad);
                #pragma unroll
                for (int nt = 0; nt < 4; nt++) MMA16816(acc[mt][nt], ah4, bh[nt]);
            }
        }
    };

    load_stage(0, 0);
    if (T > 1) load_stage(1, 32);
    for (int t = 0; t < T; t++) {
        if (t + 1 < T) asm volatile("cp.async.wait_group 1;" ::: "memory");
        else           asm volatile("cp.async.wait_group 0;" ::: "memory");
        __syncthreads();
        if (t + 2 < T) load_stage((t + 2) % 3, (t + 2) << 5);
        compute(t % 3);
    }

    const int r0    = lane >> 2;
    const int cpair = (lane & 3) * 2;
    float* red_sum = (float*)(smraw + FL_RED);
    float* red_sq  = (float*)(smraw + FL_RED + 4096);

    #pragma unroll
    for (int mt = 0; mt < 4; mt++) {
        int row1 = wm * 64 + mt * 16 + r0;
        int gm1 = m0 + row1, gm2 = gm1 + 8;
        float s0 = 0.f, q0 = 0.f, s1 = 0.f, q1 = 0.f;
        #pragma unroll
        for (int nt = 0; nt < 4; nt++) {
            int gn = wn * 32 + nt * 8 + cpair;
            float2 bb = *(const float2*)&bias[gn];
            float ra = 0.f, rb = 0.f, rc = 0.f, rd = 0.f;
            if (gm1 < M) {
                __half2 hh1 = *(const __half2*)&sh[(size_t)gm1 * ldS + gn];
                __half2 ll1 = *(const __half2*)&sl[(size_t)gm1 * ldS + gn];
                ra = __half2float(hh1.x) + __half2float(ll1.x);
                rb = __half2float(hh1.y) + __half2float(ll1.y);
            }
            if (gm2 < M) {
                __half2 hh2 = *(const __half2*)&sh[(size_t)gm2 * ldS + gn];
                __half2 ll2 = *(const __half2*)&sl[(size_t)gm2 * ldS + gn];
                rc = __half2float(hh2.x) + __half2float(ll2.x);
                rd = __half2float(hh2.y) + __half2float(ll2.y);
            }
            float w0 = acc[mt][nt][0] + bb.x + ra;
            float w1 = acc[mt][nt][1] + bb.y + rb;
            float w2 = acc[mt][nt][2] + bb.x + rc;
            float w3 = acc[mt][nt][3] + bb.y + rd;
            acc[mt][nt][0] = w0; acc[mt][nt][1] = w1;
            acc[mt][nt][2] = w2; acc[mt][nt][3] = w3;
            s0 += w0 + w1; q0 += w0 * w0 + w1 * w1;
            s1 += w2 + w3; q1 += w2 * w2 + w3 * w3;
        }
        s0 += __shfl_xor_sync(0xFFFFFFFFu, s0, 1); s0 += __shfl_xor_sync(0xFFFFFFFFu, s0, 2);
        q0 += __shfl_xor_sync(0xFFFFFFFFu, q0, 1); q0 += __shfl_xor_sync(0xFFFFFFFFu, q0, 2);
        s1 += __shfl_xor_sync(0xFFFFFFFFu, s1, 1); s1 += __shfl_xor_sync(0xFFFFFFFFu, s1, 2);
        q1 += __shfl_xor_sync(0xFFFFFFFFu, q1, 1); q1 += __shfl_xor_sync(0xFFFFFFFFu, q1, 2);
        if ((lane & 3) == 0) {
            red_sum[row1 * 8 + wn] = s0;       red_sq[row1 * 8 + wn] = q0;
            red_sum[(row1 + 8) * 8 + wn] = s1; red_sq[(row1 + 8) * 8 + wn] = q1;
        }
    }
    __syncthreads();

    #pragma unroll
    for (int mt = 0; mt < 4; mt++) {
        int row1 = wm * 64 + mt * 16 + r0;
        int gm1 = m0 + row1, gm2 = gm1 + 8;
        float su0 = 0.f, sq0 = 0.f, su1 = 0.f, sq1 = 0.f;
        #pragma unroll
        for (int wj = 0; wj < 8; wj++) {
            su0 += red_sum[row1 * 8 + wj];       sq0 += red_sq[row1 * 8 + wj];
            su1 += red_sum[(row1 + 8) * 8 + wj]; sq1 += red_sq[(row1 + 8) * 8 + wj];
        }
        float mean0 = su0 * (1.f / DD);
        float inv0  = rsqrtf(sq0 * (1.f / DD) - mean0 * mean0 + 1e-5f);
        float mean1 = su1 * (1.f / DD);
        float inv1  = rsqrtf(sq1 * (1.f / DD) - mean1 * mean1 + 1e-5f);
        #pragma unroll
        for (int nt = 0; nt < 4; nt++) {
            int gn = wn * 32 + nt * 8 + cpair;
            float2 gg = *(const float2*)&lng[gn];
            float2 bb = *(const float2*)&lnb[gn];
            if (gm1 < M) {
                float y0 = (acc[mt][nt][0] - mean0) * inv0 * gg.x + bb.x;
                float y1 = (acc[mt][nt][1] - mean0) * inv0 * gg.y + bb.y;
                split_store(&sh[(size_t)gm1 * ldS + gn], &sl[(size_t)gm1 * ldS + gn], y0, y1);
            }
            if (gm2 < M) {
                float y2 = (acc[mt][nt][2] - mean1) * inv1 * gg.x + bb.x;
                float y3 = (acc[mt][nt][3] - mean1) * inv1 * gg.y + bb.y;
                split_store(&sh[(size_t)gm2 * ldS + gn], &sl[(size_t)gm2 * ldS + gn], y2, y3);
            }
        }
    }
}

// ================= CSR build kernels =================
__global__ void fill0i_kernel(int* __restrict__ p, int n) {
    int i = blockIdx.x * 256 + threadIdx.x;
    if (i < n) p[i] = 0;
}

__global__ void hist_kernel(const int* __restrict__ ei, int* __restrict__ cnt,
                            int* __restrict__ slot)
{
    int e = blockIdx.x * 256 + threadIdx.x;
    if (e >= ETOT) return;
    int dst = (e < EE) ? ei[EE + e] : e - EE;
    slot[e] = atomicAdd(&cnt[dst], 1);
}

__global__ void scan_kernel(const int* __restrict__ cnt, int* __restrict__ rows) {
    __shared__ int wsum[32];
    int tid = threadIdx.x;
    const int CH = (NN + 1023) / 1024;
    int beg = tid * CH;
    int ssum = 0;
    for (int i = 0; i < CH; i++) {
        int idx = beg + i;
        if (idx < NN) ssum += cnt[idx];
    }
    int lane = tid & 31, wid = tid >> 5;
    int v = ssum;
    #pragma unroll
    for (int o = 1; o < 32; o <<= 1) {
        int u = __shfl_up_sync(0xFFFFFFFFu, v, o);
        if (lane >= o) v += u;
    }
    if (lane == 31) wsum[wid] = v;
    __syncthreads();
    if (wid == 0) {
        int w = wsum[lane];
        #pragma unroll
        for (int o = 1; o < 32; o <<= 1) {
            int u = __shfl_up_sync(0xFFFFFFFFu, w, o);
            if (lane >= o) w += u;
        }
        wsum[lane] = w;
    }
    __syncthreads();
    int off = v - ssum + (wid ? wsum[wid - 1] : 0);
    for (int i = 0; i < CH; i++) {
        int idx = beg + i;
        if (idx < NN) { rows[idx] = off; off += cnt[idx]; }
    }
    if (tid == 0) rows[NN] = ETOT;
}

__global__ void scatter_kernel(const int* __restrict__ ei, const int* __restrict__ rows,
                               const int* __restrict__ slot, int* __restrict__ csrc)
{
    int e = blockIdx.x * 256 + threadIdx.x;
    if (e >= ETOT) return;
    int src, dst;
    if (e < EE) { src = ei[e]; dst = ei[EE + e]; }
    else        { src = dst = e - EE; }
    csrc[rows[dst] + slot[e]] = src;
}

// ================= GAT gather (CSR, no atomics; fp16 h) ==================
__global__ void gather_kernel(const int* __restrict__ rows, const int* __restrict__ csrc,
                              const float* __restrict__ s, const float* __restrict__ t,
                              const __half* __restrict__ hh, const float* __restrict__ b,
                              __half* __restrict__ oh)
{
    int n = blockIdx.x * 4 + (threadIdx.x >> 6);
    if (n >= NN) return;
    int sub = threadIdx.x & 63;
    float tn = __ldg(&t[n]);
    int beg = __ldg(&rows[n]), end = __ldg(&rows[n + 1]);
    float a0 = 0.f, a1 = 0.f, a2 = 0.f, a3 = 0.f, den = 0.f;
    for (int i = beg; i < end; i++) {
        int src = __ldg(&csrc[i]);
        float x = __ldg(&s[src]) + tn;
        float ex = expf(x > 0.f ? x : NEGS * x);
        den += ex;
        size_t o = (size_t)src * DD + sub * 4;
        __half2 h01 = *(const __half2*)&hh[o];
        __half2 h23 = *(const __half2*)&hh[o + 2];
        a0 += ex * __half2float(h01.x); a1 += ex * __half2float(h01.y);
        a2 += ex * __half2float(h23.x); a3 += ex * __half2float(h23.y);
    }
    float inv = 1.f / den;
    float4 bb = *(const float4*)&b[sub * 4];
    float v0 = fmaxf(a0 * inv + bb.x, 0.f);
    float v1 = fmaxf(a1 * inv + bb.y, 0.f);
    float v2 = fmaxf(a2 * inv + bb.z, 0.f);
    float v3 = fmaxf(a3 * inv + bb.w, 0.f);
    size_t o = (size_t)n * DD + sub * 4;
    __half2 p0; p0.x = __float2half(v0); p0.y = __float2half(v1);
    __half2 p1; p1.x = __float2half(v2); p1.y = __float2half(v3);
    *(__half2*)&oh[o]     = p0;
    *(__half2*)&oh[o + 2] = p1;
}

// ================= small kernels =================
__global__ void round_kernel(const float* __restrict__ s, __half* __restrict__ h, int n)
{
    int i = blockIdx.x * 256 + threadIdx.x;
    if (i < n) h[i] = __float2half(s[i]);
}

// merged weight rounding into the pool (offsets cumulative)
__global__ void round_w_kernel(const float* __restrict__ w1, const float* __restrict__ w2,
                               const float* __restrict__ wqkv, const float* __restrict__ wo,
                               const float* __restrict__ f1, const float* __restrict__ f2,
                               __half* __restrict__ pool)
{
    int i = blockIdx.x * 256 + threadIdx.x;
    if (i >= WTOT) return;
    float v;
    if (i < WOFF_W2)        v = w1[i];
    else if (i < WOFF_QKV)  v = w2[i - WOFF_W2];
    else if (i < WOFF_WO)   v = wqkv[i - WOFF_QKV];
    else if (i < WOFF_F1)   v = wo[i - WOFF_WO];
    else if (i < WOFF_F2)   v = f1[i - WOFF_F1];
    else                    v = f2[i - WOFF_F2];
    pool[i] = __float2half(v);
}

__global__ void build_seq_kernel(const __half* __restrict__ x1h,
                                 const __half* __restrict__ x2h,
                                 const float* __restrict__ cls,
                                 const float* __restrict__ pos,
                                 __half* __restrict__ sh,
                                 __half* __restrict__ sl)
{
    size_t i = (size_t)blockIdx.x * 256 + threadIdx.x;
    if (i >= (size_t)NTOK * DD) return;
    int d = (int)(i & 255);
    size_t tok = i >> 8;
    int which = (int)(tok % 3);
    size_t n = tok / 3;
    float v;
    if (which == 0)      v = cls[d];
    else if (which == 1) v = __half2float(x1h[n * DD + d]);
    else                 v = __half2float(x2h[n * DD + d]);
    v += pos[which * DD + d];
    __half a = __float2half(v);
    sh[i] = a;
    sl[i] = __float2half(v - __half2float(a));
}

// L0 attention: full QKV layout [NTOK, 3*DD]
__global__ void attn_kernel(const __half* __restrict__ qh, __half* __restrict__ atth)
{
    int w = blockIdx.x * 8 + (threadIdx.x >> 5);
    if (w >= NN * NHEAD) return;
    int lane = threadIdx.x & 31;
    int n = w >> 2, hh = w & 3;
    size_t base = (size_t)n * 3 * (3 * DD) + hh * DH + lane * 2;
    float2 q[3], k[3], v[3];
    #pragma unroll
    for (int i = 0; i < 3; i++) {
        size_t o = base + (size_t)i * (3 * DD);
        __half2 a;
        a = *(const __half2*)(qh + o);
        q[i].x = __half2float(a.x); q[i].y = __half2float(a.y);
        a = *(const __half2*)(qh + o + DD);
        k[i].x = __half2float(a.x); k[i].y = __half2float(a.y);
        a = *(const __half2*)(qh + o + 2 * DD);
        v[i].x = __half2float(a.x); v[i].y = __half2float(a.y);
    }
    float lg[3][3];
    #pragma unroll
    for (int i = 0; i < 3; i++)
        #pragma unroll
        for (int j = 0; j < 3; j++) {
            float p = q[i].x * k[j].x + q[i].y * k[j].y;
            #pragma unroll
            for (int o = 16; o; o >>= 1) p += __shfl_xor_sync(0xFFFFFFFFu, p, o);
            lg[i][j] = p * 0.125f;
        }
    #pragma unroll
    for (int i = 0; i < 3; i++) {
        float m  = fmaxf(lg[i][0], fmaxf(lg[i][1], lg[i][2]));
        float e0 = expf(lg[i][0] - m), e1 = expf(lg[i][1] - m), e2 = expf(lg[i][2] - m);
        float inv = 1.f / (e0 + e1 + e2);
        float ox = (e0 * v[0].x + e1 * v[1].x + e2 * v[2].x) * inv;
        float oy = (e0 * v[0].y + e1 * v[1].y + e2 * v[2].y) * inv;
        size_t o = ((size_t)(n * 3 + i)) * DD + hh * DH + lane * 2;
        __half2 hv; hv.x = __float2half(ox); hv.y = __float2half(oy);
        *(__half2*)&atth[o] = hv;
    }
}

// L1 attention: Q from compact [NN, DD], K/V from [NTOK, 2*DD]; out [NN, DD]
__global__ void attn_cls_kernel(const __half* __restrict__ qc, const __half* __restrict__ kv,
                                __half* __restrict__ atth)
{
    int w = blockIdx.x * 8 + (threadIdx.x >> 5);
    if (w >= NN * NHEAD) return;
    int lane = threadIdx.x & 31;
    int n = w >> 2, hh = w & 3;
    __half2 qa = *(const __half2*)&qc[(size_t)n * DD + hh * DH + lane * 2];
    float qx = __half2float(qa.x), qy = __half2float(qa.y);
    float2 k[3], v[3];
    #pragma unroll
    for (int i = 0; i < 3; i++) {
        size_t o = (size_t)(n * 3 + i) * (2 * DD) + hh * DH + lane * 2;
        __half2 a;
        a = *(const __half2*)(kv + o);
        k[i].x = __half2float(a.x); k[i].y = __half2float(a.y);
        a = *(const __half2*)(kv + o + DD);
        v[i].x = __half2float(a.x); v[i].y = __half2float(a.y);
    }
    float lg[3];
    #pragma unroll
    for (int j = 0; j < 3; j++) {
        float p = qx * k[j].x + qy * k[j].y;
        #pragma unroll
        for (int o = 16; o; o >>= 1) p += __shfl_xor_sync(0xFFFFFFFFu, p, o);
        lg[j] = p * 0.125f;
    }
    float m  = fmaxf(lg[0], fmaxf(lg[1], lg[2]));
    float e0 = expf(lg[0] - m), e1 = expf(lg[1] - m), e2 = expf(lg[2] - m);
    float inv = 1.f / (e0 + e1 + e2);
    float ox = (e0 * v[0].x + e1 * v[1].x + e2 * v[2].x) * inv;
    float oy = (e0 * v[0].y + e1 * v[1].y + e2 * v[2].y) * inv;
    __half2 hv; hv.x = __float2half(ox); hv.y = __float2half(oy);
    *(__half2*)&atth[(size_t)n * DD + hh * DH + lane * 2] = hv;
}

__global__ void final_ln_kernel(const __half* __restrict__ sh, const __half* __restrict__ sl,
                                const float* __restrict__ g,
                                const float* __restrict__ b,
                                float* __restrict__ out)
{
    int n = blockIdx.x * 8 + (threadIdx.x >> 5);
    if (n >= NN) return;
    int lane = threadIdx.x & 31;
    const __half* ph = sh + (size_t)n * 3 * DD;
    const __half* pl = sl + (size_t)n * 3 * DD;
    float v[8];
    float sum = 0.f, sq = 0.f;
    #pragma unroll
    for (int i = 0; i < 4; i++) {
        __half2 ah = *(const __half2*)&ph[lane * 8 + i * 2];
        __half2 al = *(const __half2*)&pl[lane * 8 + i * 2];
        float w0 = __half2float(ah.x) + __half2float(al.x);
        float w1 = __half2float(ah.y) + __half2float(al.y);
        v[i * 2 + 0] = w0; v[i * 2 + 1] = w1;
        sum += w0 + w1;
        sq  += w0 * w0 + w1 * w1;
    }
    #pragma unroll
    for (int o = 16; o; o >>= 1) {
        sum += __shfl_xor_sync(0xFFFFFFFFu, sum, o);
        sq  += __shfl_xor_sync(0xFFFFFFFFu, sq, o);
    }
    float mean = sum * (1.f / DD);
    float var  = sq * (1.f / DD) - mean * mean;
    float inv  = rsqrtf(var + 1e-5f);
    #pragma unroll
    for (int i = 0; i < 8; i++) {
        int d = lane * 8 + i;
        out[(size_t)n * DD + d] = (v[i] - mean) * inv * g[d] + b[d];
    }
}

// ================= host side =================
template<bool BIAS, bool RELU, bool DOTS>
static void run_gemm_tc(const __half* Ah, const __half* Bh,
                        const float* bias, __half* Ch,
                        const float* asrc, const float* adst, float* ds, float* dt,
                        int M, int Nn, int K, int ldA)
{
    cudaFuncSetAttribute(gemm_mma_kernel<BIAS, RELU, DOTS>,
                         cudaFuncAttributeMaxDynamicSharedMemorySize, GM_SMEM);
    dim3 grid(Nn / 128, (M + 127) / 128);
    gemm_mma_kernel<BIAS, RELU, DOTS><<<grid, 256, GM_SMEM>>>(
        Ah, Bh, bias, Ch, asrc, adst, ds, dt, M, Nn, K, ldA);
}

static void run_gemm_ln(const __half* Ah, const __half* Bh, const float* bias,
                        __half* sh, __half* sl, const float* lng, const float* lnb,
                        int M, int K, int ldA, int ldS)
{
    cudaFuncSetAttribute(gemm_ln_kernel,
                         cudaFuncAttributeMaxDynamicSharedMemorySize, FL_SMEM);
    gemm_ln_kernel<<<(M + 127) / 128, 512, FL_SMEM>>>(Ah, Bh, bias, sh, sl, lng, lnb,
                                                      M, K, ldA, ldS);
}

extern "C" void kernel_launch(void* const* d_in, const int* in_sizes, int n_in,
                              void* d_out, int out_size)
{
    const float* x        = (const float*)d_in[0];
    const int*   ei       = (const int*)  d_in[1];
    const float* gat1_W   = (const float*)d_in[2];
    const float* gat1_b   = (const float*)d_in[3];
    const float* gat1_as  = (const float*)d_in[4];
    const float* gat1_ad  = (const float*)d_in[5];
    const float* gat2_W   = (const float*)d_in[6];
    const float* gat2_b   = (const float*)d_in[7];
    const float* gat2_as  = (const float*)d_in[8];
    const float* gat2_ad  = (const float*)d_in[9];
    const float* cls      = (const float*)d_in[10];
    const float* pos      = (const float*)d_in[11];
    const float* Wqkv     = (const float*)d_in[12];
    const float* bqkv     = (const float*)d_in[13];
    const float* Wo       = (const float*)d_in[14];
    const float* bo       = (const float*)d_in[15];
    const float* ln1_g    = (const float*)d_in[16];
    const float* ln1_b    = (const float*)d_in[17];
    const float* ln2_g    = (const float*)d_in[18];
    const float* ln2_b    = (const float*)d_in[19];
    const float* Wff1     = (const float*)d_in[20];
    const float* bff1     = (const float*)d_in[21];
    const float* Wff2     = (const float*)d_in[22];
    const float* bff2     = (const float*)d_in[23];
    const float* norm_g   = (const float*)d_in[24];
    const float* norm_b   = (const float*)d_in[25];
    float* out = (float*)d_out;

    float *s, *t;
    cudaGetSymbolAddress((void**)&s, g_s);
    cudaGetSymbolAddress((void**)&t, g_t);

    int *cnt, *slot, *rows, *csrc;
    cudaGetSymbolAddress((void**)&cnt,  g_cnt);
    cudaGetSymbolAddress((void**)&slot, g_slot);
    cudaGetSymbolAddress((void**)&rows, g_rows);
    cudaGetSymbolAddress((void**)&csrc, g_csrc);

    __half *hh, *xh, *x1h, *x2h, *seqh, *seql, *qkvh, *atth, *ffh, *wbh;
    cudaGetSymbolAddress((void**)&hh,   g_hh);
    cudaGetSymbolAddress((void**)&xh,   g_xh);
    cudaGetSymbolAddress((void**)&x1h,  g_x1h);
    cudaGetSymbolAddress((void**)&x2h,  g_x2h);
    cudaGetSymbolAddress((void**)&seqh, g_seqh);
    cudaGetSymbolAddress((void**)&seql, g_seql);
    cudaGetSymbolAddress((void**)&qkvh, g_qkvh);
    cudaGetSymbolAddress((void**)&atth, g_atth);
    cudaGetSymbolAddress((void**)&ffh,  g_ffh);
    cudaGetSymbolAddress((void**)&wbh,  g_wbh);

    // ---- CSR build ----
    fill0i_kernel<<<(NN + 255) / 256, 256>>>(cnt, NN);
    hist_kernel<<<(ETOT + 255) / 256, 256>>>(ei, cnt, slot);
    scan_kernel<<<1, 1024>>>(cnt, rows);
    scatter_kernel<<<(ETOT + 255) / 256, 256>>>(ei, rows, slot, csrc);

    // ---- conversions ----
    round_kernel<<<(NN * DIN + 255) / 256, 256>>>(x, xh, NN * DIN);
    round_w_kernel<<<(WTOT + 255) / 256, 256>>>(gat1_W, gat2_W, Wqkv, Wo, Wff1, Wff2, wbh);

    // ---- GAT layer 1 (GEMM with fused dots) ----
    cudaMemsetAsync(s, 0, NN * sizeof(float));
    cudaMemsetAsync(t, 0, NN * sizeof(float));
    run_gemm_tc<false, false, true>(xh, wbh + WOFF_W1, nullptr, hh,
                                    gat1_as, gat1_ad, s, t, NN, DD, DIN, DIN);
    gather_kernel<<<(NN + 3) / 4, 256>>>(rows, csrc, s, t, hh, gat1_b, x1h);

    // ---- GAT layer 2 ----
    cudaMemsetAsync(s, 0, NN * sizeof(float));
    cudaMemsetAsync(t, 0, NN * sizeof(float));
    run_gemm_tc<false, false, true>(x1h, wbh + WOFF_W2, nullptr, hh,
                                    gat2_as, gat2_ad, s, t, NN, DD, DD, DD);
    gather_kernel<<<(NN + 3) / 4, 256>>>(rows, csrc, s, t, hh, gat2_b, x2h);

    // ---- build sequence ----
    build_seq_kernel<<<(unsigned)(((size_t)NTOK * DD + 255) / 256), 256>>>(
        x1h, x2h, cls, pos, seqh, seql);

    // ---- transformer layer 0 (full) ----
    {
        const __half* wqh  = wbh + WOFF_QKV;
        const __half* woh  = wbh + WOFF_WO;
        const __half* wf1h = wbh + WOFF_F1;
        const __half* wf2h = wbh + WOFF_F2;
        run_gemm_tc<true, false, false>(seqh, wqh, bqkv, qkvh,
                                        nullptr, nullptr, nullptr, nullptr,
                                        NTOK, 3 * DD, DD, DD);
        attn_kernel<<<(NN * NHEAD + 7) / 8, 256>>>(qkvh, atth);
        run_gemm_ln(atth, woh, bo, seqh, seql, ln1_g, ln1_b, NTOK, DD, DD, DD);
        run_gemm_tc<true, true, false>(seqh, wf1h, bff1, ffh,
                                       nullptr, nullptr, nullptr, nullptr,
                                       NTOK, 4 * DD, DD, DD);
        run_gemm_ln(ffh, wf2h, bff2, seqh, seql, ln2_g, ln2_b, NTOK, 4 * DD, 4 * DD, DD);
    }

    // ---- transformer layer 1 (CLS-only; KV + Q-CLS split) ----
    {
        const __half* wq1  = wbh + WOFF_QKV + (size_t)3 * DD * DD;   // layer-1 QKV base
        const __half* wkv  = wq1 + (size_t)DD * DD;                  // K,V rows
        const __half* woh  = wbh + WOFF_WO  + (size_t)DD * DD;
        const __half* wf1h = wbh + WOFF_F1  + (size_t)4 * DD * DD;
        const __half* wf2h = wbh + WOFF_F2  + (size_t)DD * 4 * DD;
        // KV for all tokens: [NTOK, 512] into qkvh
        run_gemm_tc<true, false, false>(seqh, wkv, bqkv + 3 * DD + DD, qkvh,
                                        nullptr, nullptr, nullptr, nullptr,
                                        NTOK, 2 * DD, DD, DD);
        // Q for CLS tokens only: [NN, 256] into hh (free after GAT)
        run_gemm_tc<true, false, false>(seqh, wq1, bqkv + 3 * DD, hh,
                                        nullptr, nullptr, nullptr, nullptr,
                                        NN, DD, DD, 3 * DD);
        attn_cls_kernel<<<(NN * NHEAD + 7) / 8, 256>>>(hh, qkvh, atth);  // [NN, DD]
        run_gemm_ln(atth, woh, bo + DD, seqh, seql,
                    ln1_g + DD, ln1_b + DD, NN, DD, DD, 3 * DD);
        run_gemm_tc<true, true, false>(seqh, wf1h, bff1 + 4 * DD, ffh,
                                       nullptr, nullptr, nullptr, nullptr,
                                       NN, 4 * DD, DD, 3 * DD);
        run_gemm_ln(ffh, wf2h, bff2 + DD, seqh, seql,
                    ln2_g + DD, ln2_b + DD, NN, 4 * DD, 4 * DD, 3 * DD);
    }

    // ---- final LN on CLS token ----
    final_ln_kernel<<<(NN + 7) / 8, 256>>>(seqh, seql, norm_g, norm_b, out);
}

// round 17
// speedup vs baseline: 3.8441x; 1.0586x over previous
#include <cuda_runtime.h>
#include <cuda_fp16.h>
#include <cstdint>
#include <cstdio>

// ---------------- problem constants ----------------
#define NN      50000
#define EE      320000
#define ETOT    (EE + NN)
#define DIN     128
#define DD      256
#define NTOK    (NN * 3)
#define NHEAD   4
#define DH      64
#define NEGS    0.2f

// ---------------- fp32 scratch ----------------
__device__ float g_s  [NN];
__device__ float g_t  [NN];

// ---------------- CSR graph scratch ----------------
__device__ int g_cnt [NN];
__device__ int g_slot[ETOT];
__device__ int g_rows[NN + 1];
__device__ int g_csrc[ETOT];

// ---------------- fp16 activation buffers ----------------
__device__ __half g_hh  [(size_t)NN * DD];      // GAT projection / L1 Q-CLS
__device__ __half g_xh  [(size_t)NN * DIN];
__device__ __half g_x1h [(size_t)NN * DD];
__device__ __half g_seqh[(size_t)NTOK * DD];
__device__ __half g_seql[(size_t)NTOK * DD];
__device__ __half g_qkvh[(size_t)NTOK * 3 * DD];
__device__ __half g_atth[(size_t)NTOK * DD];
__device__ __half g_ffh [(size_t)NTOK * 4 * DD];
// weight pool (fp16-rounded); offsets cumulative
#define WOFF_W1   0
#define WOFF_W2   32768
#define WOFF_QKV  98304
#define WOFF_WO   491520
#define WOFF_F1   622592
#define WOFF_F2   1146880
#define WTOT      1671168
__device__ __half g_wbh[WTOT];

// ================= warp-mma helpers =================
__device__ __forceinline__ uint32_t smem_u32(const void* p) {
    uint32_t a;
    asm("{ .reg .u64 t; cvta.to.shared.u64 t, %1; cvt.u32.u64 %0, t; }" : "=r"(a) : "l"(p));
    return a;
}

#define LDM4(r, addr) \
    asm volatile("ldmatrix.sync.aligned.m8n8.x4.shared.b16 {%0,%1,%2,%3}, [%4];" \
        : "=r"((r)[0]), "=r"((r)[1]), "=r"((r)[2]), "=r"((r)[3]) : "r"(addr))
#define MMA16816(c, a, b) \
    asm volatile("mma.sync.aligned.m16n8k16.row.col.f32.f16.f16.f32 " \
        "{%0,%1,%2,%3}, {%4,%5,%6,%7}, {%8,%9}, {%0,%1,%2,%3};" \
        : "+f"((c)[0]), "+f"((c)[1]), "+f"((c)[2]), "+f"((c)[3]) \
        : "r"((a)[0]), "r"((a)[1]), "r"((a)[2]), "r"((a)[3]), "r"((b)[0]), "r"((b)[1]))
#define CP_ASYNC(dst, src, sz) \
    asm volatile("cp.async.cg.shared.global [%0], [%1], 16, %2;" :: "r"(dst), "l"(src), "r"(sz))
#define CP_COMMIT() asm volatile("cp.async.commit_group;" ::: "memory")

__device__ __forceinline__ void split_store(__half* hp, __half* lp, float a, float b) {
    __half h0 = __float2half(a), h1 = __float2half(b);
    __half2 hv; hv.x = h0; hv.y = h1;
    __half2 lv;
    lv.x = __float2half(a - __half2float(h0));
    lv.y = __float2half(b - __half2float(h1));
    *(__half2*)hp = hv;
    *(__half2*)lp = lv;
}

// ================= fp16 GEMM via mma.sync (generic N, strided A) =========
#define RSB     80
#define MAT_SZ  10240
#define STG_SZ  20480
#define GM_SMEM (3 * STG_SZ)

template<bool BIAS, bool RELU, bool DOTS>
__global__ __launch_bounds__(256, 2) void gemm_mma_kernel(
    const __half* __restrict__ Ah, const __half* __restrict__ Bh,
    const float* __restrict__ bias, __half* __restrict__ Ch,
    const float* __restrict__ asrc, const float* __restrict__ adst,
    float* __restrict__ ds, float* __restrict__ dt,
    int M, int Nn, int K, int ldA)
{
    extern __shared__ char smraw[];
    const uint32_t sb = smem_u32(smraw);
    const int tid = threadIdx.x, wid = tid >> 5, lane = tid & 31;
    const int wm = wid & 1, wn = wid >> 1;
    const int m0 = blockIdx.y * 128, n0 = blockIdx.x * 128;

    float acc[4][4][4];
    #pragma unroll
    for (int mt = 0; mt < 4; mt++)
        #pragma unroll
        for (int nt = 0; nt < 4; nt++)
            #pragma unroll
            for (int c = 0; c < 4; c++) acc[mt][nt][c] = 0.f;

    const int a_row  = (lane & 7) + ((lane >> 3) & 1) * 8;
    const int a_k    = (lane >> 4) * 8;
    const int b_row4 = (lane & 7) + ((lane >> 4) & 1) * 8;
    const int b_k4   = ((lane >> 3) & 1) * 8;

    const int T = K >> 5;

    auto load_stage = [&](int buf, int k0) {
        uint32_t base = sb + buf * STG_SZ;
        #pragma unroll
        for (int it = 0; it < 4; it++) {
            int i    = tid + it * 256;
            int mat  = i >> 9;
            int rem  = i & 511;
            int row  = rem >> 2;
            int ch   = rem & 3;
            uint32_t dst = base + mat * MAT_SZ + row * RSB + ch * 16;
            const __half* src;
            int sz = 16;
            if (mat == 0) {
                int gm = m0 + row;
                if (gm >= M) sz = 0;
                src = Ah + (size_t)gm * ldA + k0 + ch * 8;
            } else {
                src = Bh + (size_t)(n0 + row) * K + k0 + ch * 8;
            }
            CP_ASYNC(dst, src, sz);
        }
        CP_COMMIT();
    };

    auto compute = [&](int buf) {
        uint32_t base  = sb + buf * STG_SZ;
        uint32_t aB    = base + (wm * 64) * RSB;
        uint32_t bB    = base + MAT_SZ + (wn * 32) * RSB;
        #pragma unroll
        for (int ks = 0; ks < 32; ks += 16) {
            uint32_t bh[4][2];
            #pragma unroll
            for (int ntp = 0; ntp < 2; ntp++) {
                uint32_t bd = bB + (ntp * 16 + b_row4) * RSB + (ks + b_k4) * 2;
                uint32_t r4[4];
                LDM4(r4, bd);
                bh[2 * ntp][0] = r4[0]; bh[2 * ntp][1] = r4[1];
                bh[2 * ntp + 1][0] = r4[2]; bh[2 * ntp + 1][1] = r4[3];
            }
            #pragma unroll
            for (int mt = 0; mt < 4; mt++) {
                uint32_t ah4[4];
                uint32_t ad = aB + (mt * 16 + a_row) * RSB + (ks + a_k) * 2;
                LDM4(ah4, ad);
                #pragma unroll
                for (int nt = 0; nt < 4; nt++) MMA16816(acc[mt][nt], ah4, bh[nt]);
            }
        }
    };

    load_stage(0, 0);
    if (T > 1) load_stage(1, 32);
    for (int t = 0; t < T; t++) {
        if (t + 1 < T) asm volatile("cp.async.wait_group 1;" ::: "memory");
        else           asm volatile("cp.async.wait_group 0;" ::: "memory");
        __syncthreads();
        if (t + 2 < T) load_stage((t + 2) % 3, (t + 2) << 5);
        compute(t % 3);
    }

    const int r0    = lane >> 2;
    const int cpair = (lane & 3) * 2;
    #pragma unroll
    for (int mt = 0; mt < 4; mt++) {
        int gm1 = m0 + wm * 64 + mt * 16 + r0;
        int gm2 = gm1 + 8;
        float s1 = 0.f, t1 = 0.f, s2 = 0.f, t2 = 0.f;
        #pragma unroll
        for (int nt = 0; nt < 4; nt++) {
            int gn = n0 + wn * 32 + nt * 8 + cpair;
            float b0 = 0.f, b1 = 0.f;
            if (BIAS) { float2 bb = *(const float2*)&bias[gn]; b0 = bb.x; b1 = bb.y; }
            float v0 = acc[mt][nt][0] + b0, v1 = acc[mt][nt][1] + b1;
            float v2 = acc[mt][nt][2] + b0, v3 = acc[mt][nt][3] + b1;
            if (RELU) {
                v0 = fmaxf(v0, 0.f); v1 = fmaxf(v1, 0.f);
                v2 = fmaxf(v2, 0.f); v3 = fmaxf(v3, 0.f);
            }
            if (DOTS) {
                float2 as = *(const float2*)&asrc[gn];
                float2 ad = *(const float2*)&adst[gn];
                s1 += v0 * as.x + v1 * as.y; t1 += v0 * ad.x + v1 * ad.y;
                s2 += v2 * as.x + v3 * as.y; t2 += v2 * ad.x + v3 * ad.y;
            }
            if (gm1 < M) {
                __half2 hv; hv.x = __float2half(v0); hv.y = __float2half(v1);
                *(__half2*)&Ch[(size_t)gm1 * Nn + gn] = hv;
            }
            if (gm2 < M) {
                __half2 hv; hv.x = __float2half(v2); hv.y = __float2half(v3);
                *(__half2*)&Ch[(size_t)gm2 * Nn + gn] = hv;
            }
        }
        if (DOTS) {
            s1 += __shfl_xor_sync(0xFFFFFFFFu, s1, 1); s1 += __shfl_xor_sync(0xFFFFFFFFu, s1, 2);
            t1 += __shfl_xor_sync(0xFFFFFFFFu, t1, 1); t1 += __shfl_xor_sync(0xFFFFFFFFu, t1, 2);
            s2 += __shfl_xor_sync(0xFFFFFFFFu, s2, 1); s2 += __shfl_xor_sync(0xFFFFFFFFu, s2, 2);
            t2 += __shfl_xor_sync(0xFFFFFFFFu, t2, 1); t2 += __shfl_xor_sync(0xFFFFFFFFu, t2, 2);
            if ((lane & 3) == 0) {
                if (gm1 < M) { atomicAdd(&ds[gm1], s1); atomicAdd(&dt[gm1], t1); }
                if (gm2 < M) { atomicAdd(&ds[gm2], s2); atomicAdd(&dt[gm2], t2); }
            }
        }
    }
}

// ================= fused GEMM + residual + LayerNorm (N=256) =============
// FINAL: additionally applies the final LayerNorm and writes fp32 out (no seq store).
#define FL_A_SZ  10240
#define FL_B_SZ  20480
#define FL_STG   (FL_A_SZ + FL_B_SZ)
#define FL_RED   (3 * FL_STG)
#define FL_SMEM  (FL_RED + 8192)

template<bool FINAL>
__global__ __launch_bounds__(512, 1) void gemm_ln_kernel(
    const __half* __restrict__ Ah, const __half* __restrict__ Bh,
    const float* __restrict__ bias,
    __half* __restrict__ sh, __half* __restrict__ sl,
    const float* __restrict__ lng, const float* __restrict__ lnb,
    const float* __restrict__ fg, const float* __restrict__ fb,
    float* __restrict__ fout,
    int M, int K, int ldA, int ldS)
{
    extern __shared__ char smraw[];
    const uint32_t sb = smem_u32(smraw);
    const int tid = threadIdx.x, wid = tid >> 5, lane = tid & 31;
    const int wm = wid & 1, wn = wid >> 1;
    const int m0 = blockIdx.x * 128;

    float acc[4][4][4];
    #pragma unroll
    for (int mt = 0; mt < 4; mt++)
        #pragma unroll
        for (int nt = 0; nt < 4; nt++)
            #pragma unroll
            for (int c = 0; c < 4; c++) acc[mt][nt][c] = 0.f;

    const int a_row  = (lane & 7) + ((lane >> 3) & 1) * 8;
    const int a_k    = (lane >> 4) * 8;
    const int b_row4 = (lane & 7) + ((lane >> 4) & 1) * 8;
    const int b_k4   = ((lane >> 3) & 1) * 8;

    const int T = K >> 5;

    auto load_stage = [&](int buf, int k0) {
        uint32_t base = sb + buf * FL_STG;
        #pragma unroll
        for (int it = 0; it < 3; it++) {
            int i = tid + it * 512;
            uint32_t dst;
            const __half* src;
            int sz = 16;
            if (i < 512) {
                int row = i >> 2, ch = i & 3;
                dst = base + row * RSB + ch * 16;
                int gm = m0 + row;
                if (gm >= M) sz = 0;
                src = Ah + (size_t)gm * ldA + k0 + ch * 8;
            } else {
                int r = i - 512;
                int row = r >> 2, ch = r & 3;
                dst = base + FL_A_SZ + row * RSB + ch * 16;
                src = Bh + (size_t)row * K + k0 + ch * 8;
            }
            CP_ASYNC(dst, src, sz);
        }
        CP_COMMIT();
    };

    auto compute = [&](int buf) {
        uint32_t base  = sb + buf * FL_STG;
        uint32_t aB    = base + (wm * 64) * RSB;
        uint32_t bB    = base + FL_A_SZ + (wn * 32) * RSB;
        #pragma unroll
        for (int ks = 0; ks < 32; ks += 16) {
            uint32_t bh[4][2];
            #pragma unroll
            for (int ntp = 0; ntp < 2; ntp++) {
                uint32_t bd = bB + (ntp * 16 + b_row4) * RSB + (ks + b_k4) * 2;
                uint32_t r4[4];
                LDM4(r4, bd);
                bh[2 * ntp][0] = r4[0]; bh[2 * ntp][1] = r4[1];
                bh[2 * ntp + 1][0] = r4[2]; bh[2 * ntp + 1][1] = r4[3];
            }
            #pragma unroll
            for (int mt = 0; mt < 4; mt++) {
                uint32_t ah4[4];
                uint32_t ad = aB + (mt * 16 + a_row) * RSB + (ks + a_k) * 2;
                LDM4(ah4, ad);
                #pragma unroll
                for (int nt = 0; nt < 4; nt++) MMA16816(acc[mt][nt], ah4, bh[nt]);
            }
        }
    };

    load_stage(0, 0);
    if (T > 1) load_stage(1, 32);
    for (int t = 0; t < T; t++) {
        if (t + 1 < T) asm volatile("cp.async.wait_group 1;" ::: "memory");
        else           asm volatile("cp.async.wait_group 0;" ::: "memory");
        __syncthreads();
        if (t + 2 < T) load_stage((t + 2) % 3, (t + 2) << 5);
        compute(t % 3);
    }

    const int r0    = lane >> 2;
    const int cpair = (lane & 3) * 2;
    float* red_sum = (float*)(smraw + FL_RED);
    float* red_sq  = (float*)(smraw + FL_RED + 4096);

    // ---- pass 1: w = acc + bias + residual; reduce sum/sq ----
    #pragma unroll
    for (int mt = 0; mt < 4; mt++) {
        int row1 = wm * 64 + mt * 16 + r0;
        int gm1 = m0 + row1, gm2 = gm1 + 8;
        float s0 = 0.f, q0 = 0.f, s1 = 0.f, q1 = 0.f;
        #pragma unroll
        for (int nt = 0; nt < 4; nt++) {
            int gn = wn * 32 + nt * 8 + cpair;
            float2 bb = *(const float2*)&bias[gn];
            float ra = 0.f, rb = 0.f, rc = 0.f, rd = 0.f;
            if (gm1 < M) {
                __half2 hh1 = *(const __half2*)&sh[(size_t)gm1 * ldS + gn];
                __half2 ll1 = *(const __half2*)&sl[(size_t)gm1 * ldS + gn];
                ra = __half2float(hh1.x) + __half2float(ll1.x);
                rb = __half2float(hh1.y) + __half2float(ll1.y);
            }
            if (gm2 < M) {
                __half2 hh2 = *(const __half2*)&sh[(size_t)gm2 * ldS + gn];
                __half2 ll2 = *(const __half2*)&sl[(size_t)gm2 * ldS + gn];
                rc = __half2float(hh2.x) + __half2float(ll2.x);
                rd = __half2float(hh2.y) + __half2float(ll2.y);
            }
            float w0 = acc[mt][nt][0] + bb.x + ra;
            float w1 = acc[mt][nt][1] + bb.y + rb;
            float w2 = acc[mt][nt][2] + bb.x + rc;
            float w3 = acc[mt][nt][3] + bb.y + rd;
            acc[mt][nt][0] = w0; acc[mt][nt][1] = w1;
            acc[mt][nt][2] = w2; acc[mt][nt][3] = w3;
            s0 += w0 + w1; q0 += w0 * w0 + w1 * w1;
            s1 += w2 + w3; q1 += w2 * w2 + w3 * w3;
        }
        s0 += __shfl_xor_sync(0xFFFFFFFFu, s0, 1); s0 += __shfl_xor_sync(0xFFFFFFFFu, s0, 2);
        q0 += __shfl_xor_sync(0xFFFFFFFFu, q0, 1); q0 += __shfl_xor_sync(0xFFFFFFFFu, q0, 2);
        s1 += __shfl_xor_sync(0xFFFFFFFFu, s1, 1); s1 += __shfl_xor_sync(0xFFFFFFFFu, s1, 2);
        q1 += __shfl_xor_sync(0xFFFFFFFFu, q1, 1); q1 += __shfl_xor_sync(0xFFFFFFFFu, q1, 2);
        if ((lane & 3) == 0) {
            red_sum[row1 * 8 + wn] = s0;       red_sq[row1 * 8 + wn] = q0;
            red_sum[(row1 + 8) * 8 + wn] = s1; red_sq[(row1 + 8) * 8 + wn] = q1;
        }
    }
    __syncthreads();

    // ---- pass 2: y = LN1(w); store (or feed final LN) ----
    float ys0[4], yq0[4], ys1[4], yq1[4];
    #pragma unroll
    for (int mt = 0; mt < 4; mt++) {
        int row1 = wm * 64 + mt * 16 + r0;
        int gm1 = m0 + row1, gm2 = gm1 + 8;
        float su0 = 0.f, sq0 = 0.f, su1 = 0.f, sq1 = 0.f;
        #pragma unroll
        for (int wj = 0; wj < 8; wj++) {
            su0 += red_sum[row1 * 8 + wj];       sq0 += red_sq[row1 * 8 + wj];
            su1 += red_sum[(row1 + 8) * 8 + wj]; sq1 += red_sq[(row1 + 8) * 8 + wj];
        }
        float mean0 = su0 * (1.f / DD);
        float inv0  = rsqrtf(sq0 * (1.f / DD) - mean0 * mean0 + 1e-5f);
        float mean1 = su1 * (1.f / DD);
        float inv1  = rsqrtf(sq1 * (1.f / DD) - mean1 * mean1 + 1e-5f);
        float a0 = 0.f, b0s = 0.f, a1 = 0.f, b1s = 0.f;
        #pragma unroll
        for (int nt = 0; nt < 4; nt++) {
            int gn = wn * 32 + nt * 8 + cpair;
            float2 gg = *(const float2*)&lng[gn];
            float2 bb = *(const float2*)&lnb[gn];
            float y0 = (acc[mt][nt][0] - mean0) * inv0 * gg.x + bb.x;
            float y1 = (acc[mt][nt][1] - mean0) * inv0 * gg.y + bb.y;
            float y2 = (acc[mt][nt][2] - mean1) * inv1 * gg.x + bb.x;
            float y3 = (acc[mt][nt][3] - mean1) * inv1 * gg.y + bb.y;
            if (FINAL) {
                acc[mt][nt][0] = y0; acc[mt][nt][1] = y1;
                acc[mt][nt][2] = y2; acc[mt][nt][3] = y3;
                a0 += y0 + y1; b0s += y0 * y0 + y1 * y1;
                a1 += y2 + y3; b1s += y2 * y2 + y3 * y3;
            } else {
                if (gm1 < M)
                    split_store(&sh[(size_t)gm1 * ldS + gn], &sl[(size_t)gm1 * ldS + gn], y0, y1);
                if (gm2 < M)
                    split_store(&sh[(size_t)gm2 * ldS + gn], &sl[(size_t)gm2 * ldS + gn], y2, y3);
            }
        }
        if (FINAL) { ys0[mt] = a0; yq0[mt] = b0s; ys1[mt] = a1; yq1[mt] = b1s; }
    }

    if (FINAL) {
        __syncthreads();   // all reads of red arrays done
        #pragma unroll
        for (int mt = 0; mt < 4; mt++) {
            int row1 = wm * 64 + mt * 16 + r0;
            float s0 = ys0[mt], q0 = yq0[mt], s1 = ys1[mt], q1 = yq1[mt];
            s0 += __shfl_xor_sync(0xFFFFFFFFu, s0, 1); s0 += __shfl_xor_sync(0xFFFFFFFFu, s0, 2);
            q0 += __shfl_xor_sync(0xFFFFFFFFu, q0, 1); q0 += __shfl_xor_sync(0xFFFFFFFFu, q0, 2);
            s1 += __shfl_xor_sync(0xFFFFFFFFu, s1, 1); s1 += __shfl_xor_sync(0xFFFFFFFFu, s1, 2);
            q1 += __shfl_xor_sync(0xFFFFFFFFu, q1, 1); q1 += __shfl_xor_sync(0xFFFFFFFFu, q1, 2);
            if ((lane & 3) == 0) {
                red_sum[row1 * 8 + wn] = s0;       red_sq[row1 * 8 + wn] = q0;
                red_sum[(row1 + 8) * 8 + wn] = s1; red_sq[(row1 + 8) * 8 + wn] = q1;
            }
        }
        __syncthreads();
        #pragma unroll
        for (int mt = 0; mt < 4; mt++) {
            int row1 = wm * 64 + mt * 16 + r0;
            int gm1 = m0 + row1, gm2 = gm1 + 8;
            float su0 = 0.f, sq0 = 0.f, su1 = 0.f, sq1 = 0.f;
            #pragma unroll
            for (int wj = 0; wj < 8; wj++) {
                su0 += red_sum[row1 * 8 + wj];       sq0 += red_sq[row1 * 8 + wj];
                su1 += red_sum[(row1 + 8) * 8 + wj]; sq1 += red_sq[(row1 + 8) * 8 + wj];
            }
            float mean0 = su0 * (1.f / DD);
            float inv0  = rsqrtf(sq0 * (1.f / DD) - mean0 * mean0 + 1e-5f);
            float mean1 = su1 * (1.f / DD);
            float inv1  = rsqrtf(sq1 * (1.f / DD) - mean1 * mean1 + 1e-5f);
            #pragma unroll
            for (int nt = 0; nt < 4; nt++) {
                int gn = wn * 32 + nt * 8 + cpair;
                float2 gg = *(const float2*)&fg[gn];
                float2 bb = *(const float2*)&fb[gn];
                if (gm1 < M) {
                    float z0 = (acc[mt][nt][0] - mean0) * inv0 * gg.x + bb.x;
                    float z1 = (acc[mt][nt][1] - mean0) * inv0 * gg.y + bb.y;
                    *(float2*)&fout[(size_t)gm1 * DD + gn] = make_float2(z0, z1);
                }
                if (gm2 < M) {
                    float z2 = (acc[mt][nt][2] - mean1) * inv1 * gg.x + bb.x;
                    float z3 = (acc[mt][nt][3] - mean1) * inv1 * gg.y + bb.y;
                    *(float2*)&fout[(size_t)gm2 * DD + gn] = make_float2(z2, z3);
                }
            }
        }
    }
}

// ================= CSR build kernels =================
__global__ void fill0i_kernel(int* __restrict__ p, int n) {
    int i = blockIdx.x * 256 + threadIdx.x;
    if (i < n) p[i] = 0;
}

__global__ void hist_kernel(const int* __restrict__ ei, int* __restrict__ cnt,
                            int* __restrict__ slot)
{
    int e = blockIdx.x * 256 + threadIdx.x;
    if (e >= ETOT) return;
    int dst = (e < EE) ? ei[EE + e] : e - EE;
    slot[e] = atomicAdd(&cnt[dst], 1);
}

__global__ void scan_kernel(const int* __restrict__ cnt, int* __restrict__ rows) {
    __shared__ int wsum[32];
    int tid = threadIdx.x;
    const int CH = (NN + 1023) / 1024;
    int beg = tid * CH;
    int ssum = 0;
    for (int i = 0; i < CH; i++) {
        int idx = beg + i;
        if (idx < NN) ssum += cnt[idx];
    }
    int lane = tid & 31, wid = tid >> 5;
    int v = ssum;
    #pragma unroll
    for (int o = 1; o < 32; o <<= 1) {
        int u = __shfl_up_sync(0xFFFFFFFFu, v, o);
        if (lane >= o) v += u;
    }
    if (lane == 31) wsum[wid] = v;
    __syncthreads();
    if (wid == 0) {
        int w = wsum[lane];
        #pragma unroll
        for (int o = 1; o < 32; o <<= 1) {
            int u = __shfl_up_sync(0xFFFFFFFFu, w, o);
            if (lane >= o) w += u;
        }
        wsum[lane] = w;
    }
    __syncthreads();
    int off = v - ssum + (wid ? wsum[wid - 1] : 0);
    for (int i = 0; i < CH; i++) {
        int idx = beg + i;
        if (idx < NN) { rows[idx] = off; off += cnt[idx]; }
    }
    if (tid == 0) rows[NN] = ETOT;
}

__global__ void scatter_kernel(const int* __restrict__ ei, const int* __restrict__ rows,
                               const int* __restrict__ slot, int* __restrict__ csrc)
{
    int e = blockIdx.x * 256 + threadIdx.x;
    if (e >= ETOT) return;
    int src, dst;
    if (e < EE) { src = ei[e]; dst = ei[EE + e]; }
    else        { src = dst = e - EE; }
    csrc[rows[dst] + slot[e]] = src;
}

// ================= GAT gather; optional seq-row output (pos added) =======
template<bool OUTX, bool OUTSEQ>
__global__ void gather_kernel(const int* __restrict__ rows, const int* __restrict__ csrc,
                              const float* __restrict__ s, const float* __restrict__ t,
                              const __half* __restrict__ hh, const float* __restrict__ b,
                              __half* __restrict__ oh,
                              const float* __restrict__ pos,
                              __half* __restrict__ sh, __half* __restrict__ sl, int tokOff)
{
    int n = blockIdx.x * 4 + (threadIdx.x >> 6);
    if (n >= NN) return;
    int sub = threadIdx.x & 63;
    float tn = __ldg(&t[n]);
    int beg = __ldg(&rows[n]), end = __ldg(&rows[n + 1]);
    float a0 = 0.f, a1 = 0.f, a2 = 0.f, a3 = 0.f, den = 0.f;
    for (int i = beg; i < end; i++) {
        int src = __ldg(&csrc[i]);
        float x = __ldg(&s[src]) + tn;
        float ex = expf(x > 0.f ? x : NEGS * x);
        den += ex;
        size_t o = (size_t)src * DD + sub * 4;
        __half2 h01 = *(const __half2*)&hh[o];
        __half2 h23 = *(const __half2*)&hh[o + 2];
        a0 += ex * __half2float(h01.x); a1 += ex * __half2float(h01.y);
        a2 += ex * __half2float(h23.x); a3 += ex * __half2float(h23.y);
    }
    float inv = 1.f / den;
    float4 bb = *(const float4*)&b[sub * 4];
    float v0 = fmaxf(a0 * inv + bb.x, 0.f);
    float v1 = fmaxf(a1 * inv + bb.y, 0.f);
    float v2 = fmaxf(a2 * inv + bb.z, 0.f);
    float v3 = fmaxf(a3 * inv + bb.w, 0.f);
    if (OUTX) {
        size_t o = (size_t)n * DD + sub * 4;
        __half2 p0; p0.x = __float2half(v0); p0.y = __float2half(v1);
        __half2 p1; p1.x = __float2half(v2); p1.y = __float2half(v3);
        *(__half2*)&oh[o]     = p0;
        *(__half2*)&oh[o + 2] = p1;
    }
    if (OUTSEQ) {
        float4 pv = *(const float4*)&pos[sub * 4];
        size_t o = (size_t)(n * 3 + tokOff) * DD + sub * 4;
        // fp16 x-value reconstruction matches prior rounding path:
        float w0 = __half2float(__float2half(v0)) + pv.x;
        float w1 = __half2float(__float2half(v1)) + pv.y;
        float w2 = __half2float(__float2half(v2)) + pv.z;
        float w3 = __half2float(__float2half(v3)) + pv.w;
        split_store(&sh[o],     &sl[o],     w0, w1);
        split_store(&sh[o + 2], &sl[o + 2], w2, w3);
    }
}

// ================= small kernels =================
__global__ void round_kernel(const float* __restrict__ s, __half* __restrict__ h, int n)
{
    int i = blockIdx.x * 256 + threadIdx.x;
    if (i < n) h[i] = __float2half(s[i]);
}

__global__ void round_w_kernel(const float* __restrict__ w1, const float* __restrict__ w2,
                               const float* __restrict__ wqkv, const float* __restrict__ wo,
                               const float* __restrict__ f1, const float* __restrict__ f2,
                               __half* __restrict__ pool)
{
    int i = blockIdx.x * 256 + threadIdx.x;
    if (i >= WTOT) return;
    float v;
    if (i < WOFF_W2)        v = w1[i];
    else if (i < WOFF_QKV)  v = w2[i - WOFF_W2];
    else if (i < WOFF_WO)   v = wqkv[i - WOFF_QKV];
    else if (i < WOFF_F1)   v = wo[i - WOFF_WO];
    else if (i < WOFF_F2)   v = f1[i - WOFF_F1];
    else                    v = f2[i - WOFF_F2];
    pool[i] = __float2half(v);
}

// CLS token rows of seq: cls + pos[0]
__global__ void cls_seq_kernel(const float* __restrict__ cls,
                               const float* __restrict__ pos,
                               __half* __restrict__ sh, __half* __restrict__ sl)
{
    size_t i = (size_t)blockIdx.x * 256 + threadIdx.x;
    if (i >= (size_t)NN * DD) return;
    int d = (int)(i & 255);
    size_t n = i >> 8;
    float v = cls[d] + pos[d];
    size_t o = n * 3 * DD + d;
    __half a = __float2half(v);
    sh[o] = a;
    sl[o] = __float2half(v - __half2float(a));
}

// L0 attention
__global__ void attn_kernel(const __half* __restrict__ qh, __half* __restrict__ atth)
{
    int w = blockIdx.x * 8 + (threadIdx.x >> 5);
    if (w >= NN * NHEAD) return;
    int lane = threadIdx.x & 31;
    int n = w >> 2, hh = w & 3;
    size_t base = (size_t)n * 3 * (3 * DD) + hh * DH + lane * 2;
    float2 q[3], k[3], v[3];
    #pragma unroll
    for (int i = 0; i < 3; i++) {
        size_t o = base + (size_t)i * (3 * DD);
        __half2 a;
        a = *(const __half2*)(qh + o);
        q[i].x = __half2float(a.x); q[i].y = __half2float(a.y);
        a = *(const __half2*)(qh + o + DD);
        k[i].x = __half2float(a.x); k[i].y = __half2float(a.y);
        a = *(const __half2*)(qh + o + 2 * DD);
        v[i].x = __half2float(a.x); v[i].y = __half2float(a.y);
    }
    float lg[3][3];
    #pragma unroll
    for (int i = 0; i < 3; i++)
        #pragma unroll
        for (int j = 0; j < 3; j++) {
            float p = q[i].x * k[j].x + q[i].y * k[j].y;
            #pragma unroll
            for (int o = 16; o; o >>= 1) p += __shfl_xor_sync(0xFFFFFFFFu, p, o);
            lg[i][j] = p * 0.125f;
        }
    #pragma unroll
    for (int i = 0; i < 3; i++) {
        float m  = fmaxf(lg[i][0], fmaxf(lg[i][1], lg[i][2]));
        float e0 = expf(lg[i][0] - m), e1 = expf(lg[i][1] - m), e2 = expf(lg[i][2] - m);
        float inv = 1.f / (e0 + e1 + e2);
        float ox = (e0 * v[0].x + e1 * v[1].x + e2 * v[2].x) * inv;
        float oy = (e0 * v[0].y + e1 * v[1].y + e2 * v[2].y) * inv;
        size_t o = ((size_t)(n * 3 + i)) * DD + hh * DH + lane * 2;
        __half2 hv; hv.x = __float2half(ox); hv.y = __float2half(oy);
        *(__half2*)&atth[o] = hv;
    }
}

// L1 attention: Q compact [NN, DD], K/V [NTOK, 2*DD]; out [NN, DD]
__global__ void attn_cls_kernel(const __half* __restrict__ qc, const __half* __restrict__ kv,
                                __half* __restrict__ atth)
{
    int w = blockIdx.x * 8 + (threadIdx.x >> 5);
    if (w >= NN * NHEAD) return;
    int lane = threadIdx.x & 31;
    int n = w >> 2, hh = w & 3;
    __half2 qa = *(const __half2*)&qc[(size_t)n * DD + hh * DH + lane * 2];
    float qx = __half2float(qa.x), qy = __half2float(qa.y);
    float2 k[3], v[3];
    #pragma unroll
    for (int i = 0; i < 3; i++) {
        size_t o = (size_t)(n * 3 + i) * (2 * DD) + hh * DH + lane * 2;
        __half2 a;
        a = *(const __half2*)(kv + o);
        k[i].x = __half2float(a.x); k[i].y = __half2float(a.y);
        a = *(const __half2*)(kv + o + DD);
        v[i].x = __half2float(a.x); v[i].y = __half2float(a.y);
    }
    float lg[3];
    #pragma unroll
    for (int j = 0; j < 3; j++) {
        float p = qx * k[j].x + qy * k[j].y;
        #pragma unroll
        for (int o = 16; o; o >>= 1) p += __shfl_xor_sync(0xFFFFFFFFu, p, o);
        lg[j] = p * 0.125f;
    }
    float m  = fmaxf(lg[0], fmaxf(lg[1], lg[2]));
    float e0 = expf(lg[0] - m), e1 = expf(lg[1] - m), e2 = expf(lg[2] - m);
    float inv = 1.f / (e0 + e1 + e2);
    float ox = (e0 * v[0].x + e1 * v[1].x + e2 * v[2].x) * inv;
    float oy = (e0 * v[0].y + e1 * v[1].y + e2 * v[2].y) * inv;
    __half2 hv; hv.x = __float2half(ox); hv.y = __float2half(oy);
    *(__half2*)&atth[(size_t)n * DD + hh * DH + lane * 2] = hv;
}

// ================= host side =================
template<bool BIAS, bool RELU, bool DOTS>
static void run_gemm_tc(const __half* Ah, const __half* Bh,
                        const float* bias, __half* Ch,
                        const float* asrc, const float* adst, float* ds, float* dt,
                        int M, int Nn, int K, int ldA)
{
    cudaFuncSetAttribute(gemm_mma_kernel<BIAS, RELU, DOTS>,
                         cudaFuncAttributeMaxDynamicSharedMemorySize, GM_SMEM);
    dim3 grid(Nn / 128, (M + 127) / 128);
    gemm_mma_kernel<BIAS, RELU, DOTS><<<grid, 256, GM_SMEM>>>(
        Ah, Bh, bias, Ch, asrc, adst, ds, dt, M, Nn, K, ldA);
}

template<bool FINAL>
static void run_gemm_ln(const __half* Ah, const __half* Bh, const float* bias,
                        __half* sh, __half* sl, const float* lng, const float* lnb,
                        const float* fg, const float* fb, float* fout,
                        int M, int K, int ldA, int ldS)
{
    cudaFuncSetAttribute(gemm_ln_kernel<FINAL>,
                         cudaFuncAttributeMaxDynamicSharedMemorySize, FL_SMEM);
    gemm_ln_kernel<FINAL><<<(M + 127) / 128, 512, FL_SMEM>>>(
        Ah, Bh, bias, sh, sl, lng, lnb, fg, fb, fout, M, K, ldA, ldS);
}

extern "C" void kernel_launch(void* const* d_in, const int* in_sizes, int n_in,
                              void* d_out, int out_size)
{
    const float* x        = (const float*)d_in[0];
    const int*   ei       = (const int*)  d_in[1];
    const float* gat1_W   = (const float*)d_in[2];
    const float* gat1_b   = (const float*)d_in[3];
    const float* gat1_as  = (const float*)d_in[4];
    const float* gat1_ad  = (const float*)d_in[5];
    const float* gat2_W   = (const float*)d_in[6];
    const float* gat2_b   = (const float*)d_in[7];
    const float* gat2_as  = (const float*)d_in[8];
    const float* gat2_ad  = (const float*)d_in[9];
    const float* cls      = (const float*)d_in[10];
    const float* pos      = (const float*)d_in[11];
    const float* Wqkv     = (const float*)d_in[12];
    const float* bqkv     = (const float*)d_in[13];
    const float* Wo       = (const float*)d_in[14];
    const float* bo       = (const float*)d_in[15];
    const float* ln1_g    = (const float*)d_in[16];
    const float* ln1_b    = (const float*)d_in[17];
    const float* ln2_g    = (const float*)d_in[18];
    const float* ln2_b    = (const float*)d_in[19];
    const float* Wff1     = (const float*)d_in[20];
    const float* bff1     = (const float*)d_in[21];
    const float* Wff2     = (const float*)d_in[22];
    const float* bff2     = (const float*)d_in[23];
    const float* norm_g   = (const float*)d_in[24];
    const float* norm_b   = (const float*)d_in[25];
    float* out = (float*)d_out;

    float *s, *t;
    cudaGetSymbolAddress((void**)&s, g_s);
    cudaGetSymbolAddress((void**)&t, g_t);

    int *cnt, *slot, *rows, *csrc;
    cudaGetSymbolAddress((void**)&cnt,  g_cnt);
    cudaGetSymbolAddress((void**)&slot, g_slot);
    cudaGetSymbolAddress((void**)&rows, g_rows);
    cudaGetSymbolAddress((void**)&csrc, g_csrc);

    __half *hh, *xh, *x1h, *seqh, *seql, *qkvh, *atth, *ffh, *wbh;
    cudaGetSymbolAddress((void**)&hh,   g_hh);
    cudaGetSymbolAddress((void**)&xh,   g_xh);
    cudaGetSymbolAddress((void**)&x1h,  g_x1h);
    cudaGetSymbolAddress((void**)&seqh, g_seqh);
    cudaGetSymbolAddress((void**)&seql, g_seql);
    cudaGetSymbolAddress((void**)&qkvh, g_qkvh);
    cudaGetSymbolAddress((void**)&atth, g_atth);
    cudaGetSymbolAddress((void**)&ffh,  g_ffh);
    cudaGetSymbolAddress((void**)&wbh,  g_wbh);

    // ---- CSR build ----
    fill0i_kernel<<<(NN + 255) / 256, 256>>>(cnt, NN);
    hist_kernel<<<(ETOT + 255) / 256, 256>>>(ei, cnt, slot);
    scan_kernel<<<1, 1024>>>(cnt, rows);
    scatter_kernel<<<(ETOT + 255) / 256, 256>>>(ei, rows, slot, csrc);

    // ---- conversions ----
    round_kernel<<<(NN * DIN + 255) / 256, 256>>>(x, xh, NN * DIN);
    round_w_kernel<<<(WTOT + 255) / 256, 256>>>(gat1_W, gat2_W, Wqkv, Wo, Wff1, Wff2, wbh);

    // ---- GAT layer 1 (GEMM + fused dots; gather writes x1h + seq token1) ----
    cudaMemsetAsync(s, 0, NN * sizeof(float));
    cudaMemsetAsync(t, 0, NN * sizeof(float));
    run_gemm_tc<false, false, true>(xh, wbh + WOFF_W1, nullptr, hh,
                                    gat1_as, gat1_ad, s, t, NN, DD, DIN, DIN);
    gather_kernel<true, true><<<(NN + 3) / 4, 256>>>(rows, csrc, s, t, hh, gat1_b,
                                                     x1h, pos + DD, seqh, seql, 1);

    // ---- GAT layer 2 (gather writes seq token2 only) ----
    cudaMemsetAsync(s, 0, NN * sizeof(float));
    cudaMemsetAsync(t, 0, NN * sizeof(float));
    run_gemm_tc<false, false, true>(x1h, wbh + WOFF_W2, nullptr, hh,
                                    gat2_as, gat2_ad, s, t, NN, DD, DD, DD);
    gather_kernel<false, true><<<(NN + 3) / 4, 256>>>(rows, csrc, s, t, hh, gat2_b,
                                                      nullptr, pos + 2 * DD, seqh, seql, 2);

    // ---- CLS token rows of seq ----
    cls_seq_kernel<<<(unsigned)(((size_t)NN * DD + 255) / 256), 256>>>(cls, pos, seqh, seql);

    // ---- transformer layer 0 (full) ----
    {
        const __half* wqh  = wbh + WOFF_QKV;
        const __half* woh  = wbh + WOFF_WO;
        const __half* wf1h = wbh + WOFF_F1;
        const __half* wf2h = wbh + WOFF_F2;
        run_gemm_tc<true, false, false>(seqh, wqh, bqkv, qkvh,
                                        nullptr, nullptr, nullptr, nullptr,
                                        NTOK, 3 * DD, DD, DD);
        attn_kernel<<<(NN * NHEAD + 7) / 8, 256>>>(qkvh, atth);
        run_gemm_ln<false>(atth, woh, bo, seqh, seql, ln1_g, ln1_b,
                           nullptr, nullptr, nullptr, NTOK, DD, DD, DD);
        run_gemm_tc<true, true, false>(seqh, wf1h, bff1, ffh,
                                       nullptr, nullptr, nullptr, nullptr,
                                       NTOK, 4 * DD, DD, DD);
        run_gemm_ln<false>(ffh, wf2h, bff2, seqh, seql, ln2_g, ln2_b,
                           nullptr, nullptr, nullptr, NTOK, 4 * DD, 4 * DD, DD);
    }

    // ---- transformer layer 1 (CLS-only; final LN fused into FF2) ----
    {
        const __half* wq1  = wbh + WOFF_QKV + (size_t)3 * DD * DD;
        const __half* wkv  = wq1 + (size_t)DD * DD;
        const __half* woh  = wbh + WOFF_WO  + (size_t)DD * DD;
        const __half* wf1h = wbh + WOFF_F1  + (size_t)4 * DD * DD;
        const __half* wf2h = wbh + WOFF_F2  + (size_t)DD * 4 * DD;
        run_gemm_tc<true, false, false>(seqh, wkv, bqkv + 3 * DD + DD, qkvh,
                                        nullptr, nullptr, nullptr, nullptr,
                                        NTOK, 2 * DD, DD, DD);
        run_gemm_tc<true, false, false>(seqh, wq1, bqkv + 3 * DD, hh,
                                        nullptr, nullptr, nullptr, nullptr,
                                        NN, DD, DD, 3 * DD);
        attn_cls_kernel<<<(NN * NHEAD + 7) / 8, 256>>>(hh, qkvh, atth);
        run_gemm_ln<false>(atth, woh, bo + DD, seqh, seql,
                           ln1_g + DD, ln1_b + DD, nullptr, nullptr, nullptr,
                           NN, DD, DD, 3 * DD);
        run_gemm_tc<true, true, false>(seqh, wf1h, bff1 + 4 * DD, ffh,
                                       nullptr, nullptr, nullptr, nullptr,
                                       NN, 4 * DD, DD, 3 * DD);
        run_gemm_ln<true>(ffh, wf2h, bff2 + DD, seqh, seql,
                          ln2_g + DD, ln2_b + DD, norm_g, norm_b, out,
                          NN, 4 * DD, 4 * DD, 3 * DD);
    }
}